// round 10
// baseline (speedup 1.0000x reference)
#include <cuda_runtime.h>
#include <cuda_bf16.h>
#include <math.h>
#include <stdint.h>

// Problem constants
#define Bn 8
#define Cn 384
#define NQ 4096
#define NK 1024
#define Hn 8
#define Dn 48
#define Fn 1536
#define GRN_EPS 1e-6f
#define LN_EPS 1e-5f

// GEMM tiling (bf16): 256x128 CTA tile, 64x64 warp tiles (8 warps)
#define BM 256
#define BN 128
#define KSB 32        // k elements per slab
#define KW 16         // uint32 words per row (KSB/2)
#define NSTAGE 3
#define AW (BM * KW)  // A words per stage (4096)
#define BW (BN * KW)  // B words per stage (2048)
#define GEMM_SMEM (NSTAGE * (AW + BW) * 4)  // 73728 bytes

#define CC (Cn * Cn)
#define FC (Fn * Cn)

// ---------------- scratch (device globals; no allocations) ----------------
__device__ float g_q[(size_t)Bn * NQ * Cn];
__device__ float g_k[(size_t)Bn * NK * Cn];
__device__ float g_v[(size_t)Bn * NK * Cn];
__device__ float g_working[(size_t)Bn * Cn * NQ];
__device__ float g_kv[(size_t)Bn * Hn * Dn * Dn];
__device__ float g_ksum[(size_t)Bn * Hn * Dn];
__device__ float g_gx[(size_t)Bn * Cn];  // raw sum of squares
__device__ float g_meanc[Bn];

__device__ __nv_bfloat16 b_ada[(size_t)Bn * NQ * Cn];
__device__ __nv_bfloat16 b_key[(size_t)Bn * NK * Cn];
__device__ __nv_bfloat16 b_val[(size_t)Bn * NK * Cn];
__device__ __nv_bfloat16 b_qp[(size_t)Bn * NQ * Cn];
__device__ __nv_bfloat16 b_nrm[(size_t)Bn * NQ * Cn];
__device__ __nv_bfloat16 b_h[(size_t)Bn * NQ * Fn];
__device__ __nv_bfloat16 b_wts[4 * CC + 2 * FC];
__device__ __nv_bfloat16 b_M[(size_t)Bn * Cn * Cn];

// ---------------- helpers ----------------
__device__ __forceinline__ void cp_async16(void* smem_dst, const void* gsrc) {
    uint32_t s = (uint32_t)__cvta_generic_to_shared(smem_dst);
    asm volatile("cp.async.cg.shared.global [%0], [%1], 16;" ::"r"(s), "l"(gsrc));
}
__device__ __forceinline__ void cp_commit() { asm volatile("cp.async.commit_group;"); }
__device__ __forceinline__ void cp_wait1() { asm volatile("cp.async.wait_group 1;"); }
__device__ __forceinline__ void cp_wait0() { asm volatile("cp.async.wait_group 0;"); }

__device__ __forceinline__ void mma16(float* c, uint32_t a0, uint32_t a1, uint32_t a2,
                                      uint32_t a3, uint32_t b0, uint32_t b1) {
    asm volatile(
        "mma.sync.aligned.m16n8k16.row.col.f32.bf16.bf16.f32 "
        "{%0,%1,%2,%3},{%4,%5,%6,%7},{%8,%9},{%0,%1,%2,%3};"
        : "+f"(c[0]), "+f"(c[1]), "+f"(c[2]), "+f"(c[3])
        : "r"(a0), "r"(a1), "r"(a2), "r"(a3), "r"(b0), "r"(b1));
}

__device__ __forceinline__ void ldsm4(uint32_t& r0, uint32_t& r1, uint32_t& r2, uint32_t& r3,
                                      uint32_t saddr) {
    asm volatile("ldmatrix.sync.aligned.m8n8.x4.shared.b16 {%0,%1,%2,%3}, [%4];"
                 : "=r"(r0), "=r"(r1), "=r"(r2), "=r"(r3)
                 : "r"(saddr));
}

// ---------------- merged weight convert ----------------
__global__ void conv_f2bf_all(const float4* __restrict__ wq, const float4* __restrict__ wk,
                              const float4* __restrict__ wv, const float4* __restrict__ wo,
                              const float4* __restrict__ w1, const float4* __restrict__ w2,
                              __nv_bfloat162* __restrict__ dst) {
    const int C4 = CC / 4, F4 = FC / 4;
    int total = 4 * C4 + 2 * F4;
    for (int i = blockIdx.x * 256 + threadIdx.x; i < total; i += gridDim.x * 256) {
        const float4* src;
        int off;
        if (i < 4 * C4) {
            int seg = i / C4;
            off = i - seg * C4;
            src = (seg == 0) ? wq : (seg == 1) ? wk : (seg == 2) ? wv : wo;
        } else if (i < 4 * C4 + F4) {
            src = w1;
            off = i - 4 * C4;
        } else {
            src = w2;
            off = i - 4 * C4 - F4;
        }
        float4 v = src[off];
        __nv_bfloat162 a, b;
        a.x = __float2bfloat16_rn(v.x); a.y = __float2bfloat16_rn(v.y);
        b.x = __float2bfloat16_rn(v.z); b.y = __float2bfloat16_rn(v.w);
        dst[2 * i] = a;
        dst[2 * i + 1] = b;
    }
}

// ---------------- GRN (gx = RAW sum of squares; consumers apply sqrt) ----------------
__global__ void grn_reduce_kernel(const float* __restrict__ x, float* __restrict__ gx, int N) {
    int bc = blockIdx.x;
    const float4* p = (const float4*)(x + (size_t)bc * N);
    int n4 = N >> 2;
    float s = 0.f;
    for (int i = threadIdx.x; i < n4; i += 256) {
        float4 v = p[i];
        s += v.x * v.x + v.y * v.y + v.z * v.z + v.w * v.w;
    }
    __shared__ float red[256];
    red[threadIdx.x] = s;
    __syncthreads();
    for (int st = 128; st > 0; st >>= 1) {
        if (threadIdx.x < st) red[threadIdx.x] += red[threadIdx.x + st];
        __syncthreads();
    }
    if (threadIdx.x == 0) gx[bc] = red[0];
}

__global__ void grn_mean_kernel(const float* __restrict__ gx, float* __restrict__ meanc) {
    int b = blockIdx.x;
    int t = threadIdx.x;  // 128
    float s = 0.f;
    for (int c = t; c < Cn; c += 128) s += sqrtf(gx[b * Cn + c]);
    __shared__ float red[128];
    red[t] = s;
    __syncthreads();
    for (int st = 64; st > 0; st >>= 1) {
        if (t < st) red[t] += red[t + st];
        __syncthreads();
    }
    if (t == 0) meanc[b] = red[0] * (1.f / (float)Cn) + GRN_EPS;
}

// ---------------- transpose + (optional GRN) + convert to bf16 rows ----------------
__global__ void transconv_kernel(const float* __restrict__ x, __nv_bfloat16* __restrict__ out,
                                 const float* __restrict__ gx, const float* __restrict__ meanc,
                                 const float* __restrict__ gamma, const float* __restrict__ beta,
                                 int N, int grn) {
    int b = blockIdx.z;
    int c0 = blockIdx.x * 64;
    int n0 = blockIdx.y * 32;
    __shared__ float t[64][33];
    int tid = threadIdx.x;
    int j = tid & 31, i0 = tid >> 5;
#pragma unroll
    for (int p = 0; p < 8; p++) {
        int i = i0 + p * 8;
        t[i][j] = x[((size_t)b * Cn + c0 + i) * N + n0 + j];
    }
    __syncthreads();
    int cp = tid & 31;
    int nn0 = tid >> 5;
    int c = c0 + 2 * cp;
    float sc0 = 1.f, bt0 = 0.f, sc1 = 1.f, bt1 = 0.f;
    if (grn) {
        sc0 = 1.f + (1.f + gamma[c]) * sqrtf(gx[b * Cn + c]) / meanc[b];
        bt0 = beta[c];
        sc1 = 1.f + (1.f + gamma[c + 1]) * sqrtf(gx[b * Cn + c + 1]) / meanc[b];
        bt1 = beta[c + 1];
    }
#pragma unroll
    for (int p = 0; p < 4; p++) {
        int nn = nn0 + p * 8;
        float v0 = t[2 * cp][nn] * sc0 + bt0;
        float v1 = t[2 * cp + 1][nn] * sc1 + bt1;
        __nv_bfloat162 hv;
        hv.x = __float2bfloat16_rn(v0);
        hv.y = __float2bfloat16_rn(v1);
        *(__nv_bfloat162*)(out + ((size_t)b * N + n0 + nn) * Cn + c) = hv;
    }
}

// ---------------- shared GEMM mainloop (256x128 tile, ldmatrix fragments) --------------
#define GEMM_MAINLOOP(Ab, Wp, K)                                                          \
    const uint32_t a_base = (uint32_t)__cvta_generic_to_shared(As);                       \
    const uint32_t b_base = (uint32_t)__cvta_generic_to_shared(Bs);                       \
    int lr = (lane & 7) + ((lane >> 3) & 1) * 8;                                          \
    int lca = lane >> 4;                                                                  \
    int lrb = (lane & 7) + (lane >> 4) * 8;                                               \
    int lcb = (lane >> 3) & 1;                                                            \
    int nslab = (K) / KSB;                                                                \
    LOAD_BF(0, 0);                                                                        \
    LOAD_BF(1, 1);                                                                        \
    for (int s = 0; s < nslab; s++) {                                                     \
        int stg = s % NSTAGE;                                                             \
        if (s + 1 < nslab) cp_wait1(); else cp_wait0();                                   \
        __syncthreads();                                                                  \
        if (s + 2 < nslab) LOAD_BF(s + 2, (s + 2) % NSTAGE);                              \
        uint32_t Ast = a_base + stg * AW * 4;                                             \
        uint32_t Bst = b_base + stg * BW * 4;                                             \
        _Pragma("unroll") for (int kb = 0; kb < 2; kb++) {                                \
            uint32_t af[4][4], bfr[8][2];                                                 \
            _Pragma("unroll") for (int mf = 0; mf < 4; mf++) {                            \
                int row = wm + mf * 16 + lr;                                              \
                int ch = 2 * kb + lca;                                                    \
                ldsm4(af[mf][0], af[mf][1], af[mf][2], af[mf][3],                         \
                      Ast + row * 64 + ((ch ^ ((row >> 1) & 3)) << 4));                   \
            }                                                                             \
            _Pragma("unroll") for (int p = 0; p < 4; p++) {                               \
                int row = wn + p * 16 + lrb;                                              \
                int ch = 2 * kb + lcb;                                                    \
                ldsm4(bfr[2 * p][0], bfr[2 * p][1], bfr[2 * p + 1][0], bfr[2 * p + 1][1], \
                      Bst + row * 64 + ((ch ^ ((row >> 1) & 3)) << 4));                   \
            }                                                                             \
            _Pragma("unroll") for (int mf = 0; mf < 4; mf++)                              \
                _Pragma("unroll") for (int nf = 0; nf < 8; nf++)                          \
                    mma16(acc[mf][nf], af[mf][0], af[mf][1], af[mf][2], af[mf][3],        \
                          bfr[nf][0], bfr[nf][1]);                                        \
        }                                                                                 \
    }

// 256 threads load 1024 A-chunks + 512 B-chunks of 16B per slab
#define LOAD_BF(slab, stg)                                                              \
    {                                                                                   \
        int kk0 = (slab)*KSB;                                                           \
        uint32_t* Ad = As + (size_t)(stg)*AW;                                           \
        uint32_t* Bd = Bs + (size_t)(stg)*BW;                                           \
        _Pragma("unroll") for (int p = 0; p < 4; p++) {                                 \
            int c = tid + p * 256;                                                      \
            int r = c >> 2, ch = c & 3;                                                 \
            int sw = ((ch ^ ((r >> 1) & 3)) << 2);                                      \
            cp_async16(Ad + r * KW + sw, Ab + (size_t)(m0 + r) * K + kk0 + ch * 8);     \
        }                                                                               \
        _Pragma("unroll") for (int p = 0; p < 2; p++) {                                 \
            int c = tid + p * 256;                                                      \
            int r = c >> 2, ch = c & 3;                                                 \
            int sw = ((ch ^ ((r >> 1) & 3)) << 2);                                      \
            cp_async16(Bd + r * KW + sw, Wp + (size_t)(c0 + r) * K + kk0 + ch * 8);     \
        }                                                                               \
        cp_commit();                                                                    \
    }

// ---------------- bf16 GEMM, row-major output (+optional second problem set) ----------
// blockIdx.y < ysplit: set 1 (A,W,bias -> Yf/Yh); else set 2 (A2,W2,bias2 -> Yf2), mode 0
__global__ __launch_bounds__(256, 1) void gemm_bf16_row(
    const __nv_bfloat16* __restrict__ A, const __nv_bfloat16* __restrict__ W,
    const float* __restrict__ bias, float* __restrict__ Yf, __nv_bfloat16* __restrict__ Yh,
    const __nv_bfloat16* __restrict__ A2, const __nv_bfloat16* __restrict__ W2,
    const float* __restrict__ bias2, float* __restrict__ Yf2,
    int N, int K, int Cout, int mode, int ysplit) {
    extern __shared__ uint32_t smu[];
    uint32_t* As = smu;
    uint32_t* Bs = smu + NSTAGE * AW;
    int b = blockIdx.z;
    int m0 = blockIdx.x * BM;
    int yb = blockIdx.y;
    if (yb >= ysplit) {
        A = A2; W = W2; bias = bias2; Yf = Yf2; Yh = nullptr; mode = 0;
        yb -= ysplit;
    }
    int c0 = yb * BN;
    int tid = threadIdx.x;
    int warp = tid >> 5, lane = tid & 31;
    int g = lane >> 2, lq = lane & 3;
    int wm = (warp & 3) * 64;
    int wn = (warp >> 2) * 64;
    float acc[4][8][4] = {};
    const __nv_bfloat16* Ab = A + (size_t)b * N * K;
    const __nv_bfloat16* Wp = W;

    GEMM_MAINLOOP(Ab, Wp, K)

#pragma unroll
    for (int mf = 0; mf < 4; mf++) {
#pragma unroll
        for (int nf = 0; nf < 8; nf++) {
            int co = c0 + wn + nf * 8 + lq * 2;
            float b0v = bias[co], b1v = bias[co + 1];
#pragma unroll
            for (int hr = 0; hr < 2; hr++) {
                int m = m0 + wm + mf * 16 + g + hr * 8;
                float v0 = acc[mf][nf][hr * 2 + 0] + b0v;
                float v1 = acc[mf][nf][hr * 2 + 1] + b1v;
                if (mode == 1) {
                    v0 = v0 / (1.f + expf(-v0));
                    v1 = v1 / (1.f + expf(-v1));
                    __nv_bfloat162 hv;
                    hv.x = __float2bfloat16_rn(v0);
                    hv.y = __float2bfloat16_rn(v1);
                    *(__nv_bfloat162*)(Yh + ((size_t)b * N + m) * Cout + co) = hv;
                } else {
                    *(float2*)(Yf + ((size_t)b * N + m) * Cout + co) = make_float2(v0, v1);
                }
            }
        }
    }
}

// ---------------- bf16 GEMM, channel-major fused output (batch-strided W) ----------
// mode 0: out = resid1 + val*s1
// mode 1: out = resid1 + (resid2 + val*s1)*s2
// mode 2: mode 0 + accumulate sum_m out^2 into gx[b*Cn+co] (GRN reduce fusion)
__global__ __launch_bounds__(256, 1) void gemm_bf16_cm(
    const __nv_bfloat16* __restrict__ A, const __nv_bfloat16* __restrict__ W,
    const float* __restrict__ bias,
    const float* __restrict__ resid1, const float* __restrict__ resid2,
    const float* __restrict__ scal1, const float* __restrict__ scal2,
    float* __restrict__ out, float* __restrict__ gx,
    int N, int K, int Cout, int mode, int wstride) {
    extern __shared__ uint32_t smu[];
    uint32_t* As = smu;
    uint32_t* Bs = smu + NSTAGE * AW;
    int b = blockIdx.z;
    int m0 = blockIdx.x * BM;
    int c0 = blockIdx.y * BN;
    int tid = threadIdx.x;
    int warp = tid >> 5, lane = tid & 31;
    int g = lane >> 2, lq = lane & 3;
    int wm = (warp & 3) * 64;
    int wn = (warp >> 2) * 64;
    float acc[4][8][4] = {};
    const __nv_bfloat16* Ab = A + (size_t)b * N * K;
    const __nv_bfloat16* Wp = W + (size_t)b * wstride;

    GEMM_MAINLOOP(Ab, Wp, K)

    float* sq_s = (float*)smu;  // reuse stage memory for per-co sum of squares
    if (mode == 2) {
        __syncthreads();  // all warps done with smem
        if (tid < BN) sq_s[tid] = 0.f;
        __syncthreads();
    }

#pragma unroll
    for (int nf = 0; nf < 8; nf++) {
#pragma unroll
        for (int cj = 0; cj < 2; cj++) {
            int col = wn + nf * 8 + lq * 2 + cj;
            int co = c0 + col;
            float bv = bias[co];
            float s1 = scal1[co];
            float s2 = (mode == 1) ? scal2[co] : 0.f;
            float sq = 0.f;
#pragma unroll
            for (int mf = 0; mf < 4; mf++) {
#pragma unroll
                for (int hr = 0; hr < 2; hr++) {
                    int m = m0 + wm + mf * 16 + g + hr * 8;
                    size_t idx = ((size_t)b * Cout + co) * (size_t)N + m;
                    float val = acc[mf][nf][hr * 2 + cj] + bv;
                    float o;
                    if (mode == 1)
                        o = resid1[idx] + (resid2[idx] + val * s1) * s2;
                    else
                        o = resid1[idx] + val * s1;
                    out[idx] = o;
                    sq += o * o;
                }
            }
            if (mode == 2) atomicAdd(&sq_s[col], sq);
        }
    }
    if (mode == 2) {
        __syncthreads();
        if (tid < BN) atomicAdd(&gx[(size_t)b * Cn + c0 + tid], sq_s[tid]);
    }
}

// ---------------- LayerNorm + elu+1 (in place) — for k ----------------
__global__ void ln_elu_kernel(float* __restrict__ x, const float* __restrict__ w,
                              const float* __restrict__ bvec) {
    int r = blockIdx.x;
    float* p = x + (size_t)r * Cn;
    int t = threadIdx.x;  // 128
    float v0 = p[t], v1 = p[t + 128], v2 = p[t + 256];
    float s = v0 + v1 + v2;
    float s2 = v0 * v0 + v1 * v1 + v2 * v2;
    __shared__ float red[128];
    red[t] = s;
    __syncthreads();
    for (int st = 64; st > 0; st >>= 1) {
        if (t < st) red[t] += red[t + st];
        __syncthreads();
    }
    float mu = red[0] * (1.f / (float)Cn);
    __syncthreads();
    red[t] = s2;
    __syncthreads();
    for (int st = 64; st > 0; st >>= 1) {
        if (t < st) red[t] += red[t + st];
        __syncthreads();
    }
    float var = red[0] * (1.f / (float)Cn) - mu * mu;
    float inv = rsqrtf(var + LN_EPS);
    float y;
    y = (v0 - mu) * inv * w[t] + bvec[t];
    p[t] = (y > 0.f) ? y + 1.f : expf(y);
    y = (v1 - mu) * inv * w[t + 128] + bvec[t + 128];
    p[t + 128] = (y > 0.f) ? y + 1.f : expf(y);
    y = (v2 - mu) * inv * w[t + 256] + bvec[t + 256];
    p[t + 256] = (y > 0.f) ? y + 1.f : expf(y);
}

// ---------------- q: LayerNorm + elu+1 + den fold -> bf16 q' ----------------
__global__ void ln_elu_q_den(const float* __restrict__ x, const float* __restrict__ ksum,
                             const float* __restrict__ w, const float* __restrict__ bvec,
                             __nv_bfloat16* __restrict__ qp) {
    int r = blockIdx.x;
    int b = r / NQ;
    const float* p = x + (size_t)r * Cn;
    int t = threadIdx.x;  // 128
    float v0 = p[t], v1 = p[t + 128], v2 = p[t + 256];
    float s = v0 + v1 + v2;
    float s2 = v0 * v0 + v1 * v1 + v2 * v2;
    __shared__ float red[128];
    __shared__ float yb[384];
    __shared__ float den[8];
    red[t] = s;
    __syncthreads();
    for (int st = 64; st > 0; st >>= 1) {
        if (t < st) red[t] += red[t + st];
        __syncthreads();
    }
    float mu = red[0] * (1.f / (float)Cn);
    __syncthreads();
    red[t] = s2;
    __syncthreads();
    for (int st = 64; st > 0; st >>= 1) {
        if (t < st) red[t] += red[t + st];
        __syncthreads();
    }
    float var = red[0] * (1.f / (float)Cn) - mu * mu;
    float inv = rsqrtf(var + LN_EPS);
    float y0 = (v0 - mu) * inv * w[t] + bvec[t];
    y0 = (y0 > 0.f) ? y0 + 1.f : expf(y0);
    float y1 = (v1 - mu) * inv * w[t + 128] + bvec[t + 128];
    y1 = (y1 > 0.f) ? y1 + 1.f : expf(y1);
    float y2 = (v2 - mu) * inv * w[t + 256] + bvec[t + 256];
    y2 = (y2 > 0.f) ? y2 + 1.f : expf(y2);
    yb[t] = y0; yb[t + 128] = y1; yb[t + 256] = y2;
    __syncthreads();
    if (t < 8) {
        const float* ksr = ksum + ((size_t)b * Hn + t) * Dn;
        float sd = 0.f;
#pragma unroll
        for (int j = 0; j < Dn; j++) sd += yb[t * Dn + j] * ksr[j];
        den[t] = sd + 1e-8f;
    }
    __syncthreads();
    __nv_bfloat16* o = qp + (size_t)r * Cn;
    o[t] = __float2bfloat16_rn(y0 / den[t / Dn]);
    o[t + 128] = __float2bfloat16_rn(y1 / den[(t + 128) / Dn]);
    o[t + 256] = __float2bfloat16_rn(y2 / den[(t + 256) / Dn]);
}

// ---------------- zero kv/ksum/gx ----------------
__global__ void zero_kv(float* __restrict__ kv, float* __restrict__ ksum,
                        float* __restrict__ gx) {
    int i = blockIdx.x * 256 + threadIdx.x;
    if (i < Bn * Hn * Dn * Dn) kv[i] = 0.f;
    if (i < Bn * Hn * Dn) ksum[i] = 0.f;
    if (i < Bn * Cn) gx[i] = 0.f;
}

// ---------------- kv_sum + k_sum: register outer-product + NK split --------------
__global__ void kv_v2(const float* __restrict__ k, const float* __restrict__ v,
                      float* __restrict__ kv, float* __restrict__ ksum) {
    int bh = blockIdx.x;
    int chunk = blockIdx.y;
    int b = bh >> 3, h = bh & 7;
    __shared__ float ks[32][49];
    __shared__ float vs[32][49];
    int tid = threadIdx.x;  // 256
    int di = tid >> 4, ei = tid & 15;
    int d0 = di * 3, e0 = ei * 3;
    float acc[3][3] = {};
    float ksa[3] = {};
    int nbeg = chunk * (NK / 4);
    for (int n0 = nbeg; n0 < nbeg + NK / 4; n0 += 32) {
        for (int i = tid; i < 32 * Dn; i += 256) {
            int nn = i / Dn, dd = i % Dn;
            size_t base = ((size_t)b * NK + n0 + nn) * Cn + h * Dn + dd;
            ks[nn][dd] = k[base];
            vs[nn][dd] = v[base];
        }
        __syncthreads();
#pragma unroll 4
        for (int nn = 0; nn < 32; nn++) {
            float kd0 = ks[nn][d0], kd1 = ks[nn][d0 + 1], kd2 = ks[nn][d0 + 2];
            float ve0 = vs[nn][e0], ve1 = vs[nn][e0 + 1], ve2 = vs[nn][e0 + 2];
            acc[0][0] += kd0 * ve0; acc[0][1] += kd0 * ve1; acc[0][2] += kd0 * ve2;
            acc[1][0] += kd1 * ve0; acc[1][1] += kd1 * ve1; acc[1][2] += kd1 * ve2;
            acc[2][0] += kd2 * ve0; acc[2][1] += kd2 * ve1; acc[2][2] += kd2 * ve2;
            if (ei == 0) { ksa[0] += kd0; ksa[1] += kd1; ksa[2] += kd2; }
        }
        __syncthreads();
    }
    float* kvb = kv + (size_t)bh * Dn * Dn;
#pragma unroll
    for (int i = 0; i < 3; i++)
#pragma unroll
        for (int j = 0; j < 3; j++)
            atomicAdd(&kvb[(d0 + i) * Dn + e0 + j], acc[i][j]);
    if (ei == 0)
#pragma unroll
        for (int i = 0; i < 3; i++) atomicAdd(&ksum[bh * Dn + d0 + i], ksa[i]);
}

// ---------------- make_M ----------------
__global__ void make_M(const float* __restrict__ kv, const float* __restrict__ Wo,
                       __nv_bfloat16* __restrict__ Wt) {
    int cb = blockIdx.x;
    int h = blockIdx.y;
    int b = blockIdx.z;
    __shared__ float kvs[Dn][49];
    __shared__ float wos[Dn][132];
    int tid = threadIdx.x;  // 256
    for (int i = tid; i < Dn * Dn; i += 256)
        kvs[i / Dn][i % Dn] = kv[((size_t)b * Hn + h) * Dn * Dn + i];
    for (int i = tid; i < 128 * Dn; i += 256) {
        int co = i / Dn, e = i % Dn;
        wos[e][co] = Wo[(size_t)(cb * 128 + co) * Cn + h * Dn + e];
    }
    __syncthreads();
    int cog = tid & 15, dg = tid >> 4;
    int co0 = cog * 8, d0 = dg * 3;
    float acc[8][3] = {};
#pragma unroll 4
    for (int e = 0; e < Dn; e++) {
        float kd0 = kvs[d0][e], kd1 = kvs[d0 + 1][e], kd2 = kvs[d0 + 2][e];
#pragma unroll
        for (int i = 0; i < 8; i++) {
            float wv = wos[e][co0 + i];
            acc[i][0] += wv * kd0;
            acc[i][1] += wv * kd1;
            acc[i][2] += wv * kd2;
        }
    }
#pragma unroll
    for (int i = 0; i < 8; i++)
#pragma unroll
        for (int j = 0; j < 3; j++)
            Wt[((size_t)b * Cn + cb * 128 + co0 + i) * Cn + h * Dn + d0 + j] =
                __float2bfloat16_rn(acc[i][j]);
}

// ---------------- host launch ----------------
extern "C" void kernel_launch(void* const* d_in, const int* in_sizes, int n_in,
                              void* d_out, int out_size) {
    const float* query = (const float*)d_in[0];
    const float* key = (const float*)d_in[1];
    const float* value = (const float*)d_in[2];
    const float* ada_gamma = (const float*)d_in[3];
    const float* ada_beta = (const float*)d_in[4];
    const float* Wq = (const float*)d_in[5];
    const float* bq = (const float*)d_in[6];
    const float* Wk = (const float*)d_in[7];
    const float* bk = (const float*)d_in[8];
    const float* Wv = (const float*)d_in[9];
    const float* bv = (const float*)d_in[10];
    const float* Wo = (const float*)d_in[11];
    const float* bo = (const float*)d_in[12];
    const float* lnq_w = (const float*)d_in[13];
    const float* lnq_b = (const float*)d_in[14];
    const float* lnk_w = (const float*)d_in[15];
    const float* lnk_b = (const float*)d_in[16];
    const float* attn_scalar = (const float*)d_in[17];
    const float* ffn_gamma = (const float*)d_in[18];
    const float* ffn_beta = (const float*)d_in[19];
    const float* W1 = (const float*)d_in[20];
    const float* b1 = (const float*)d_in[21];
    const float* W2 = (const float*)d_in[22];
    const float* b2 = (const float*)d_in[23];
    const float* ffn_scalar = (const float*)d_in[24];
    const float* final_scalar = (const float*)d_in[25];
    float* out = (float*)d_out;

    float *q, *k, *v, *working, *kv, *ksum, *gx, *meanc;
    __nv_bfloat16 *ada_b, *key_b, *val_b, *qp_b, *nrm_b, *h_b, *wts, *M_b;
    cudaGetSymbolAddress((void**)&q, g_q);
    cudaGetSymbolAddress((void**)&k, g_k);
    cudaGetSymbolAddress((void**)&v, g_v);
    cudaGetSymbolAddress((void**)&working, g_working);
    cudaGetSymbolAddress((void**)&kv, g_kv);
    cudaGetSymbolAddress((void**)&ksum, g_ksum);
    cudaGetSymbolAddress((void**)&gx, g_gx);
    cudaGetSymbolAddress((void**)&meanc, g_meanc);
    cudaGetSymbolAddress((void**)&ada_b, b_ada);
    cudaGetSymbolAddress((void**)&key_b, b_key);
    cudaGetSymbolAddress((void**)&val_b, b_val);
    cudaGetSymbolAddress((void**)&qp_b, b_qp);
    cudaGetSymbolAddress((void**)&nrm_b, b_nrm);
    cudaGetSymbolAddress((void**)&h_b, b_h);
    cudaGetSymbolAddress((void**)&wts, b_wts);
    cudaGetSymbolAddress((void**)&M_b, b_M);

    __nv_bfloat16* wq_b = wts;
    __nv_bfloat16* wk_b = wts + CC;
    __nv_bfloat16* wv_b = wts + 2 * CC;
    __nv_bfloat16* w1_b = wts + 4 * CC;
    __nv_bfloat16* w2_b = wts + 4 * CC + FC;

    cudaFuncSetAttribute(gemm_bf16_row, cudaFuncAttributeMaxDynamicSharedMemorySize, GEMM_SMEM);
    cudaFuncSetAttribute(gemm_bf16_cm, cudaFuncAttributeMaxDynamicSharedMemorySize, GEMM_SMEM);

    // 0) weight conversions (one launch)
    conv_f2bf_all<<<1728, 256>>>((const float4*)Wq, (const float4*)Wk, (const float4*)Wv,
                                 (const float4*)Wo, (const float4*)W1, (const float4*)W2,
                                 (__nv_bfloat162*)wts);

    // 0b) key/value transpose-convert to bf16 rows
    transconv_kernel<<<dim3(Cn / 64, NK / 32, Bn), 256>>>(key, key_b, nullptr, nullptr,
                                                          nullptr, nullptr, NK, 0);
    transconv_kernel<<<dim3(Cn / 64, NK / 32, Bn), 256>>>(value, val_b, nullptr, nullptr,
                                                          nullptr, nullptr, NK, 0);

    // 1) GRN on query -> ada (bf16 rows, fused transpose)
    grn_reduce_kernel<<<Bn * Cn, 256>>>(query, gx, NQ);
    grn_mean_kernel<<<Bn, 128>>>(gx, meanc);
    transconv_kernel<<<dim3(Cn / 64, NQ / 32, Bn), 256>>>(query, ada_b, gx, meanc,
                                                          ada_gamma, ada_beta, NQ, 1);

    // 2) Q projection; K+V projections merged into one launch (ysplit=3)
    gemm_bf16_row<<<dim3(NQ / BM, Cn / BN, Bn), 256, GEMM_SMEM>>>(
        ada_b, wq_b, bq, q, nullptr, nullptr, nullptr, nullptr, nullptr, NQ, Cn, Cn, 0, 1000);
    gemm_bf16_row<<<dim3(NK / BM, 2 * (Cn / BN), Bn), 256, GEMM_SMEM>>>(
        key_b, wk_b, bk, k, nullptr, val_b, wv_b, bv, v, NK, Cn, Cn, 0, Cn / BN);

    // 3) LN + elu+1 on k (in place, fp32)
    ln_elu_kernel<<<Bn * NK, 128>>>(k, lnk_w, lnk_b);

    // 4) zero kv/ksum/gx, then kv_sum/k_sum
    zero_kv<<<(Bn * Hn * Dn * Dn + 255) / 256, 256>>>(kv, ksum, gx);
    kv_v2<<<dim3(Bn * Hn, 4), 256>>>(k, v, kv, ksum);

    // 5a) q: LN + elu+1 + fold den -> bf16 q'
    ln_elu_q_den<<<Bn * NQ, 128>>>(q, ksum, lnq_w, lnq_b, qp_b);

    // 5b) fold kv into Wo: per-batch effective weight M
    make_M<<<dim3(Cn / 128, Hn, Bn), 256>>>(kv, Wo, M_b);

    // 6) (attention + Wo) as ONE GEMM; fused GRN sum-of-squares into gx (mode 2)
    gemm_bf16_cm<<<dim3(NQ / BM, Cn / BN, Bn), 256, GEMM_SMEM>>>(
        qp_b, M_b, bo, query, nullptr, attn_scalar, nullptr, working, gx,
        NQ, Cn, Cn, 2, Cn * Cn);

    // 7) GRN mean + transconv on working (reduce already fused into step 6)
    grn_mean_kernel<<<Bn, 128>>>(gx, meanc);
    transconv_kernel<<<dim3(Cn / 64, NQ / 32, Bn), 256>>>(working, nrm_b, gx, meanc,
                                                          ffn_gamma, ffn_beta, NQ, 1);

    // 8) FFN1 (+silu) -> h (bf16 rows)
    gemm_bf16_row<<<dim3(NQ / BM, Fn / BN, Bn), 256, GEMM_SMEM>>>(
        nrm_b, w1_b, b1, nullptr, h_b, nullptr, nullptr, nullptr, nullptr, NQ, Cn, Fn, 1, 1000);

    // 9) FFN2 + ffn residual + final residual -> out (fp32, channel-major)
    gemm_bf16_cm<<<dim3(NQ / BM, Cn / BN, Bn), 256, GEMM_SMEM>>>(
        h_b, w2_b, b2, query, working, ffn_scalar, final_scalar, out, nullptr,
        NQ, Fn, Cn, 1, 0);
}

// round 11
// speedup vs baseline: 1.2092x; 1.2092x over previous
#include <cuda_runtime.h>
#include <cuda_bf16.h>
#include <math.h>
#include <stdint.h>

// Problem constants
#define Bn 8
#define Cn 384
#define NQ 4096
#define NK 1024
#define Hn 8
#define Dn 48
#define Fn 1536
#define GRN_EPS 1e-6f
#define LN_EPS 1e-5f

// GEMM tiling (bf16): 128x128 CTA tile, 64x32 warp tiles (validated R9 config)
#define BM 128
#define BN 128
#define KSB 32        // k elements per slab
#define KW 16         // uint32 words per row (KSB/2)
#define NSTAGE 3
#define GW (BM * KW)  // words per stage per operand (2048)
#define GEMM_SMEM (NSTAGE * 2 * GW * 4)  // 49152 bytes

#define CC (Cn * Cn)
#define FC (Fn * Cn)

// ---------------- scratch (device globals; no allocations) ----------------
__device__ float g_q[(size_t)Bn * NQ * Cn];
__device__ float g_k[(size_t)Bn * NK * Cn];
__device__ float g_v[(size_t)Bn * NK * Cn];
__device__ float g_working[(size_t)Bn * Cn * NQ];
__device__ float g_kv[(size_t)Bn * Hn * Dn * Dn];
__device__ float g_ksum[(size_t)Bn * Hn * Dn];
__device__ float g_gx[(size_t)Bn * Cn];  // raw sum of squares
__device__ float g_meanc[Bn];

__device__ __nv_bfloat16 b_ada[(size_t)Bn * NQ * Cn];
__device__ __nv_bfloat16 b_key[(size_t)Bn * NK * Cn];
__device__ __nv_bfloat16 b_val[(size_t)Bn * NK * Cn];
__device__ __nv_bfloat16 b_qp[(size_t)Bn * NQ * Cn];
__device__ __nv_bfloat16 b_nrm[(size_t)Bn * NQ * Cn];
__device__ __nv_bfloat16 b_h[(size_t)Bn * NQ * Fn];
__device__ __nv_bfloat16 b_wts[4 * CC + 2 * FC];
__device__ __nv_bfloat16 b_M[(size_t)Bn * Cn * Cn];

// ---------------- helpers ----------------
__device__ __forceinline__ void cp_async16(void* smem_dst, const void* gsrc) {
    uint32_t s = (uint32_t)__cvta_generic_to_shared(smem_dst);
    asm volatile("cp.async.cg.shared.global [%0], [%1], 16;" ::"r"(s), "l"(gsrc));
}
__device__ __forceinline__ void cp_commit() { asm volatile("cp.async.commit_group;"); }
__device__ __forceinline__ void cp_wait1() { asm volatile("cp.async.wait_group 1;"); }
__device__ __forceinline__ void cp_wait0() { asm volatile("cp.async.wait_group 0;"); }

__device__ __forceinline__ void mma16(float* c, uint32_t a0, uint32_t a1, uint32_t a2,
                                      uint32_t a3, uint32_t b0, uint32_t b1) {
    asm volatile(
        "mma.sync.aligned.m16n8k16.row.col.f32.bf16.bf16.f32 "
        "{%0,%1,%2,%3},{%4,%5,%6,%7},{%8,%9},{%0,%1,%2,%3};"
        : "+f"(c[0]), "+f"(c[1]), "+f"(c[2]), "+f"(c[3])
        : "r"(a0), "r"(a1), "r"(a2), "r"(a3), "r"(b0), "r"(b1));
}

__device__ __forceinline__ void ldsm4(uint32_t& r0, uint32_t& r1, uint32_t& r2, uint32_t& r3,
                                      uint32_t saddr) {
    asm volatile("ldmatrix.sync.aligned.m8n8.x4.shared.b16 {%0,%1,%2,%3}, [%4];"
                 : "=r"(r0), "=r"(r1), "=r"(r2), "=r"(r3)
                 : "r"(saddr));
}

// ---------------- merged weight convert ----------------
__global__ void conv_f2bf_all(const float4* __restrict__ wq, const float4* __restrict__ wk,
                              const float4* __restrict__ wv, const float4* __restrict__ wo,
                              const float4* __restrict__ w1, const float4* __restrict__ w2,
                              __nv_bfloat162* __restrict__ dst) {
    const int C4 = CC / 4, F4 = FC / 4;
    int total = 4 * C4 + 2 * F4;
    for (int i = blockIdx.x * 256 + threadIdx.x; i < total; i += gridDim.x * 256) {
        const float4* src;
        int off;
        if (i < 4 * C4) {
            int seg = i / C4;
            off = i - seg * C4;
            src = (seg == 0) ? wq : (seg == 1) ? wk : (seg == 2) ? wv : wo;
        } else if (i < 4 * C4 + F4) {
            src = w1;
            off = i - 4 * C4;
        } else {
            src = w2;
            off = i - 4 * C4 - F4;
        }
        float4 v = src[off];
        __nv_bfloat162 a, b;
        a.x = __float2bfloat16_rn(v.x); a.y = __float2bfloat16_rn(v.y);
        b.x = __float2bfloat16_rn(v.z); b.y = __float2bfloat16_rn(v.w);
        dst[2 * i] = a;
        dst[2 * i + 1] = b;
    }
}

// ---------------- GRN (gx = RAW sum of squares; consumers apply sqrt) ----------------
__global__ void grn_reduce_kernel(const float* __restrict__ x, float* __restrict__ gx, int N) {
    int bc = blockIdx.x;
    const float4* p = (const float4*)(x + (size_t)bc * N);
    int n4 = N >> 2;
    float s = 0.f;
    for (int i = threadIdx.x; i < n4; i += 256) {
        float4 v = p[i];
        s += v.x * v.x + v.y * v.y + v.z * v.z + v.w * v.w;
    }
    __shared__ float red[256];
    red[threadIdx.x] = s;
    __syncthreads();
    for (int st = 128; st > 0; st >>= 1) {
        if (threadIdx.x < st) red[threadIdx.x] += red[threadIdx.x + st];
        __syncthreads();
    }
    if (threadIdx.x == 0) gx[bc] = red[0];
}

__global__ void grn_mean_kernel(const float* __restrict__ gx, float* __restrict__ meanc) {
    int b = blockIdx.x;
    int t = threadIdx.x;  // 128
    float s = 0.f;
    for (int c = t; c < Cn; c += 128) s += sqrtf(gx[b * Cn + c]);
    __shared__ float red[128];
    red[t] = s;
    __syncthreads();
    for (int st = 64; st > 0; st >>= 1) {
        if (t < st) red[t] += red[t + st];
        __syncthreads();
    }
    if (t == 0) meanc[b] = red[0] * (1.f / (float)Cn) + GRN_EPS;
}

// ---------------- transpose + (optional GRN) + convert to bf16 rows ----------------
__global__ void transconv_kernel(const float* __restrict__ x, __nv_bfloat16* __restrict__ out,
                                 const float* __restrict__ gx, const float* __restrict__ meanc,
                                 const float* __restrict__ gamma, const float* __restrict__ beta,
                                 int N, int grn) {
    int b = blockIdx.z;
    int c0 = blockIdx.x * 64;
    int n0 = blockIdx.y * 32;
    __shared__ float t[64][33];
    int tid = threadIdx.x;
    int j = tid & 31, i0 = tid >> 5;
#pragma unroll
    for (int p = 0; p < 8; p++) {
        int i = i0 + p * 8;
        t[i][j] = x[((size_t)b * Cn + c0 + i) * N + n0 + j];
    }
    __syncthreads();
    int cp = tid & 31;
    int nn0 = tid >> 5;
    int c = c0 + 2 * cp;
    float sc0 = 1.f, bt0 = 0.f, sc1 = 1.f, bt1 = 0.f;
    if (grn) {
        sc0 = 1.f + (1.f + gamma[c]) * sqrtf(gx[b * Cn + c]) / meanc[b];
        bt0 = beta[c];
        sc1 = 1.f + (1.f + gamma[c + 1]) * sqrtf(gx[b * Cn + c + 1]) / meanc[b];
        bt1 = beta[c + 1];
    }
#pragma unroll
    for (int p = 0; p < 4; p++) {
        int nn = nn0 + p * 8;
        float v0 = t[2 * cp][nn] * sc0 + bt0;
        float v1 = t[2 * cp + 1][nn] * sc1 + bt1;
        __nv_bfloat162 hv;
        hv.x = __float2bfloat16_rn(v0);
        hv.y = __float2bfloat16_rn(v1);
        *(__nv_bfloat162*)(out + ((size_t)b * N + n0 + nn) * Cn + c) = hv;
    }
}

// ---------------- shared GEMM mainloop (128x128 tile, ldmatrix fragments) --------------
#define GEMM_MAINLOOP(Ab, Wp, K)                                                          \
    const uint32_t a_base = (uint32_t)__cvta_generic_to_shared(As);                       \
    const uint32_t b_base = (uint32_t)__cvta_generic_to_shared(Bs);                       \
    int lr = (lane & 7) + ((lane >> 3) & 1) * 8;                                          \
    int lca = lane >> 4;                                                                  \
    int lrb = (lane & 7) + (lane >> 4) * 8;                                               \
    int lcb = (lane >> 3) & 1;                                                            \
    int nslab = (K) / KSB;                                                                \
    LOAD_BF(0, 0);                                                                        \
    LOAD_BF(1, 1);                                                                        \
    for (int s = 0; s < nslab; s++) {                                                     \
        int stg = s % NSTAGE;                                                             \
        if (s + 1 < nslab) cp_wait1(); else cp_wait0();                                   \
        __syncthreads();                                                                  \
        if (s + 2 < nslab) LOAD_BF(s + 2, (s + 2) % NSTAGE);                              \
        uint32_t Ast = a_base + stg * GW * 4;                                             \
        uint32_t Bst = b_base + stg * GW * 4;                                             \
        _Pragma("unroll") for (int kb = 0; kb < 2; kb++) {                                \
            uint32_t af[4][4], bfr[4][2];                                                 \
            _Pragma("unroll") for (int mf = 0; mf < 4; mf++) {                            \
                int row = wm + mf * 16 + lr;                                              \
                int ch = 2 * kb + lca;                                                    \
                ldsm4(af[mf][0], af[mf][1], af[mf][2], af[mf][3],                         \
                      Ast + row * 64 + ((ch ^ ((row >> 1) & 3)) << 4));                   \
            }                                                                             \
            _Pragma("unroll") for (int p = 0; p < 2; p++) {                               \
                int row = wn + p * 16 + lrb;                                              \
                int ch = 2 * kb + lcb;                                                    \
                ldsm4(bfr[2 * p][0], bfr[2 * p][1], bfr[2 * p + 1][0], bfr[2 * p + 1][1], \
                      Bst + row * 64 + ((ch ^ ((row >> 1) & 3)) << 4));                   \
            }                                                                             \
            _Pragma("unroll") for (int mf = 0; mf < 4; mf++)                              \
                _Pragma("unroll") for (int nf = 0; nf < 4; nf++)                          \
                    mma16(acc[mf][nf], af[mf][0], af[mf][1], af[mf][2], af[mf][3],        \
                          bfr[nf][0], bfr[nf][1]);                                        \
        }                                                                                 \
    }

#define LOAD_BF(slab, stg)                                                              \
    {                                                                                   \
        int kk0 = (slab)*KSB;                                                           \
        uint32_t* Ad = As + (size_t)(stg)*GW;                                           \
        uint32_t* Bd = Bs + (size_t)(stg)*GW;                                           \
        _Pragma("unroll") for (int p = 0; p < 2; p++) {                                 \
            int c = tid + p * 256;                                                      \
            int r = c >> 2, ch = c & 3;                                                 \
            int sw = ((ch ^ ((r >> 1) & 3)) << 2);                                      \
            cp_async16(Ad + r * KW + sw, Ab + (size_t)(m0 + r) * K + kk0 + ch * 8);     \
            cp_async16(Bd + r * KW + sw, Wp + (size_t)(c0 + r) * K + kk0 + ch * 8);     \
        }                                                                               \
        cp_commit();                                                                    \
    }

// ---------------- bf16 GEMM, row-major output (+optional second problem set) ----------
// blockIdx.y < ysplit: set 1 (A,W,bias -> Yf/Yh, mode); else set 2 (A2,W2,bias2 -> Yf2), mode 0
__global__ __launch_bounds__(256) void gemm_bf16_row(
    const __nv_bfloat16* __restrict__ A, const __nv_bfloat16* __restrict__ W,
    const float* __restrict__ bias, float* __restrict__ Yf, __nv_bfloat16* __restrict__ Yh,
    const __nv_bfloat16* __restrict__ A2, const __nv_bfloat16* __restrict__ W2,
    const float* __restrict__ bias2, float* __restrict__ Yf2,
    int N, int K, int Cout, int mode, int ysplit) {
    extern __shared__ uint32_t smu[];
    uint32_t* As = smu;
    uint32_t* Bs = smu + NSTAGE * GW;
    int b = blockIdx.z;
    int m0 = blockIdx.x * BM;
    int yb = blockIdx.y;
    if (yb >= ysplit) {
        A = A2; W = W2; bias = bias2; Yf = Yf2; Yh = nullptr; mode = 0;
        yb -= ysplit;
    }
    int c0 = yb * BN;
    int tid = threadIdx.x;
    int warp = tid >> 5, lane = tid & 31;
    int g = lane >> 2, lq = lane & 3;
    int wm = (warp >> 2) * 64;
    int wn = (warp & 3) * 32;
    float acc[4][4][4] = {};
    const __nv_bfloat16* Ab = A + (size_t)b * N * K;
    const __nv_bfloat16* Wp = W;

    GEMM_MAINLOOP(Ab, Wp, K)

#pragma unroll
    for (int mf = 0; mf < 4; mf++) {
#pragma unroll
        for (int nf = 0; nf < 4; nf++) {
            int co = c0 + wn + nf * 8 + lq * 2;
            float b0v = bias[co], b1v = bias[co + 1];
#pragma unroll
            for (int hr = 0; hr < 2; hr++) {
                int m = m0 + wm + mf * 16 + g + hr * 8;
                float v0 = acc[mf][nf][hr * 2 + 0] + b0v;
                float v1 = acc[mf][nf][hr * 2 + 1] + b1v;
                if (mode == 1) {
                    v0 = v0 / (1.f + expf(-v0));
                    v1 = v1 / (1.f + expf(-v1));
                    __nv_bfloat162 hv;
                    hv.x = __float2bfloat16_rn(v0);
                    hv.y = __float2bfloat16_rn(v1);
                    *(__nv_bfloat162*)(Yh + ((size_t)b * N + m) * Cout + co) = hv;
                } else {
                    *(float2*)(Yf + ((size_t)b * N + m) * Cout + co) = make_float2(v0, v1);
                }
            }
        }
    }
}

// ---------------- bf16 GEMM, channel-major fused output (batch-strided W) ----------
// mode 0: out = resid1 + val*s1
// mode 1: out = resid1 + (resid2 + val*s1)*s2
// mode 2: mode 0 + accumulate sum_m out^2 into gx[b*Cn+co] (GRN reduce fusion)
__global__ __launch_bounds__(256) void gemm_bf16_cm(
    const __nv_bfloat16* __restrict__ A, const __nv_bfloat16* __restrict__ W,
    const float* __restrict__ bias,
    const float* __restrict__ resid1, const float* __restrict__ resid2,
    const float* __restrict__ scal1, const float* __restrict__ scal2,
    float* __restrict__ out, float* __restrict__ gx,
    int N, int K, int Cout, int mode, int wstride) {
    extern __shared__ uint32_t smu[];
    uint32_t* As = smu;
    uint32_t* Bs = smu + NSTAGE * GW;
    int b = blockIdx.z;
    int m0 = blockIdx.x * BM;
    int c0 = blockIdx.y * BN;
    int tid = threadIdx.x;
    int warp = tid >> 5, lane = tid & 31;
    int g = lane >> 2, lq = lane & 3;
    int wm = (warp >> 2) * 64;
    int wn = (warp & 3) * 32;
    float acc[4][4][4] = {};
    const __nv_bfloat16* Ab = A + (size_t)b * N * K;
    const __nv_bfloat16* Wp = W + (size_t)b * wstride;

    GEMM_MAINLOOP(Ab, Wp, K)

    float* sq_s = (float*)smu;  // reuse stage memory for per-co sum of squares
    if (mode == 2) {
        __syncthreads();  // all warps done with smem reads
        if (tid < BN) sq_s[tid] = 0.f;
        __syncthreads();
    }

#pragma unroll
    for (int nf = 0; nf < 4; nf++) {
#pragma unroll
        for (int cj = 0; cj < 2; cj++) {
            int col = wn + nf * 8 + lq * 2 + cj;
            int co = c0 + col;
            float bv = bias[co];
            float s1 = scal1[co];
            float s2 = (mode == 1) ? scal2[co] : 0.f;
            float sq = 0.f;
#pragma unroll
            for (int mf = 0; mf < 4; mf++) {
#pragma unroll
                for (int hr = 0; hr < 2; hr++) {
                    int m = m0 + wm + mf * 16 + g + hr * 8;
                    size_t idx = ((size_t)b * Cout + co) * (size_t)N + m;
                    float val = acc[mf][nf][hr * 2 + cj] + bv;
                    float o;
                    if (mode == 1)
                        o = resid1[idx] + (resid2[idx] + val * s1) * s2;
                    else
                        o = resid1[idx] + val * s1;
                    out[idx] = o;
                    sq += o * o;
                }
            }
            if (mode == 2) atomicAdd(&sq_s[col], sq);
        }
    }
    if (mode == 2) {
        __syncthreads();
        if (tid < BN) atomicAdd(&gx[(size_t)b * Cn + c0 + tid], sq_s[tid]);
    }
}

// ---------------- LayerNorm + elu+1 (in place) — for k ----------------
__global__ void ln_elu_kernel(float* __restrict__ x, const float* __restrict__ w,
                              const float* __restrict__ bvec) {
    int r = blockIdx.x;
    float* p = x + (size_t)r * Cn;
    int t = threadIdx.x;  // 128
    float v0 = p[t], v1 = p[t + 128], v2 = p[t + 256];
    float s = v0 + v1 + v2;
    float s2 = v0 * v0 + v1 * v1 + v2 * v2;
    __shared__ float red[128];
    red[t] = s;
    __syncthreads();
    for (int st = 64; st > 0; st >>= 1) {
        if (t < st) red[t] += red[t + st];
        __syncthreads();
    }
    float mu = red[0] * (1.f / (float)Cn);
    __syncthreads();
    red[t] = s2;
    __syncthreads();
    for (int st = 64; st > 0; st >>= 1) {
        if (t < st) red[t] += red[t + st];
        __syncthreads();
    }
    float var = red[0] * (1.f / (float)Cn) - mu * mu;
    float inv = rsqrtf(var + LN_EPS);
    float y;
    y = (v0 - mu) * inv * w[t] + bvec[t];
    p[t] = (y > 0.f) ? y + 1.f : expf(y);
    y = (v1 - mu) * inv * w[t + 128] + bvec[t + 128];
    p[t + 128] = (y > 0.f) ? y + 1.f : expf(y);
    y = (v2 - mu) * inv * w[t + 256] + bvec[t + 256];
    p[t + 256] = (y > 0.f) ? y + 1.f : expf(y);
}

// ---------------- q: LayerNorm + elu+1 + den fold -> bf16 q' ----------------
__global__ void ln_elu_q_den(const float* __restrict__ x, const float* __restrict__ ksum,
                             const float* __restrict__ w, const float* __restrict__ bvec,
                             __nv_bfloat16* __restrict__ qp) {
    int r = blockIdx.x;
    int b = r / NQ;
    const float* p = x + (size_t)r * Cn;
    int t = threadIdx.x;  // 128
    float v0 = p[t], v1 = p[t + 128], v2 = p[t + 256];
    float s = v0 + v1 + v2;
    float s2 = v0 * v0 + v1 * v1 + v2 * v2;
    __shared__ float red[128];
    __shared__ float yb[384];
    __shared__ float den[8];
    red[t] = s;
    __syncthreads();
    for (int st = 64; st > 0; st >>= 1) {
        if (t < st) red[t] += red[t + st];
        __syncthreads();
    }
    float mu = red[0] * (1.f / (float)Cn);
    __syncthreads();
    red[t] = s2;
    __syncthreads();
    for (int st = 64; st > 0; st >>= 1) {
        if (t < st) red[t] += red[t + st];
        __syncthreads();
    }
    float var = red[0] * (1.f / (float)Cn) - mu * mu;
    float inv = rsqrtf(var + LN_EPS);
    float y0 = (v0 - mu) * inv * w[t] + bvec[t];
    y0 = (y0 > 0.f) ? y0 + 1.f : expf(y0);
    float y1 = (v1 - mu) * inv * w[t + 128] + bvec[t + 128];
    y1 = (y1 > 0.f) ? y1 + 1.f : expf(y1);
    float y2 = (v2 - mu) * inv * w[t + 256] + bvec[t + 256];
    y2 = (y2 > 0.f) ? y2 + 1.f : expf(y2);
    yb[t] = y0; yb[t + 128] = y1; yb[t + 256] = y2;
    __syncthreads();
    if (t < 8) {
        const float* ksr = ksum + ((size_t)b * Hn + t) * Dn;
        float sd = 0.f;
#pragma unroll
        for (int j = 0; j < Dn; j++) sd += yb[t * Dn + j] * ksr[j];
        den[t] = sd + 1e-8f;
    }
    __syncthreads();
    __nv_bfloat16* o = qp + (size_t)r * Cn;
    o[t] = __float2bfloat16_rn(y0 / den[t / Dn]);
    o[t + 128] = __float2bfloat16_rn(y1 / den[(t + 128) / Dn]);
    o[t + 256] = __float2bfloat16_rn(y2 / den[(t + 256) / Dn]);
}

// ---------------- zero kv/ksum/gx ----------------
__global__ void zero_kv(float* __restrict__ kv, float* __restrict__ ksum,
                        float* __restrict__ gx) {
    int i = blockIdx.x * 256 + threadIdx.x;
    if (i < Bn * Hn * Dn * Dn) kv[i] = 0.f;
    if (i < Bn * Hn * Dn) ksum[i] = 0.f;
    if (i < Bn * Cn) gx[i] = 0.f;
}

// ---------------- kv_sum + k_sum: register outer-product + NK split --------------
__global__ void kv_v2(const float* __restrict__ k, const float* __restrict__ v,
                      float* __restrict__ kv, float* __restrict__ ksum) {
    int bh = blockIdx.x;
    int chunk = blockIdx.y;
    int b = bh >> 3, h = bh & 7;
    __shared__ float ks[32][49];
    __shared__ float vs[32][49];
    int tid = threadIdx.x;  // 256
    int di = tid >> 4, ei = tid & 15;
    int d0 = di * 3, e0 = ei * 3;
    float acc[3][3] = {};
    float ksa[3] = {};
    int nbeg = chunk * (NK / 4);
    for (int n0 = nbeg; n0 < nbeg + NK / 4; n0 += 32) {
        for (int i = tid; i < 32 * Dn; i += 256) {
            int nn = i / Dn, dd = i % Dn;
            size_t base = ((size_t)b * NK + n0 + nn) * Cn + h * Dn + dd;
            ks[nn][dd] = k[base];
            vs[nn][dd] = v[base];
        }
        __syncthreads();
#pragma unroll 4
        for (int nn = 0; nn < 32; nn++) {
            float kd0 = ks[nn][d0], kd1 = ks[nn][d0 + 1], kd2 = ks[nn][d0 + 2];
            float ve0 = vs[nn][e0], ve1 = vs[nn][e0 + 1], ve2 = vs[nn][e0 + 2];
            acc[0][0] += kd0 * ve0; acc[0][1] += kd0 * ve1; acc[0][2] += kd0 * ve2;
            acc[1][0] += kd1 * ve0; acc[1][1] += kd1 * ve1; acc[1][2] += kd1 * ve2;
            acc[2][0] += kd2 * ve0; acc[2][1] += kd2 * ve1; acc[2][2] += kd2 * ve2;
            if (ei == 0) { ksa[0] += kd0; ksa[1] += kd1; ksa[2] += kd2; }
        }
        __syncthreads();
    }
    float* kvb = kv + (size_t)bh * Dn * Dn;
#pragma unroll
    for (int i = 0; i < 3; i++)
#pragma unroll
        for (int j = 0; j < 3; j++)
            atomicAdd(&kvb[(d0 + i) * Dn + e0 + j], acc[i][j]);
    if (ei == 0)
#pragma unroll
        for (int i = 0; i < 3; i++) atomicAdd(&ksum[bh * Dn + d0 + i], ksa[i]);
}

// ---------------- make_M ----------------
__global__ void make_M(const float* __restrict__ kv, const float* __restrict__ Wo,
                       __nv_bfloat16* __restrict__ Wt) {
    int cb = blockIdx.x;
    int h = blockIdx.y;
    int b = blockIdx.z;
    __shared__ float kvs[Dn][49];
    __shared__ float wos[Dn][132];
    int tid = threadIdx.x;  // 256
    for (int i = tid; i < Dn * Dn; i += 256)
        kvs[i / Dn][i % Dn] = kv[((size_t)b * Hn + h) * Dn * Dn + i];
    for (int i = tid; i < 128 * Dn; i += 256) {
        int co = i / Dn, e = i % Dn;
        wos[e][co] = Wo[(size_t)(cb * 128 + co) * Cn + h * Dn + e];
    }
    __syncthreads();
    int cog = tid & 15, dg = tid >> 4;
    int co0 = cog * 8, d0 = dg * 3;
    float acc[8][3] = {};
#pragma unroll 4
    for (int e = 0; e < Dn; e++) {
        float kd0 = kvs[d0][e], kd1 = kvs[d0 + 1][e], kd2 = kvs[d0 + 2][e];
#pragma unroll
        for (int i = 0; i < 8; i++) {
            float wv = wos[e][co0 + i];
            acc[i][0] += wv * kd0;
            acc[i][1] += wv * kd1;
            acc[i][2] += wv * kd2;
        }
    }
#pragma unroll
    for (int i = 0; i < 8; i++)
#pragma unroll
        for (int j = 0; j < 3; j++)
            Wt[((size_t)b * Cn + cb * 128 + co0 + i) * Cn + h * Dn + d0 + j] =
                __float2bfloat16_rn(acc[i][j]);
}

// ---------------- host launch ----------------
extern "C" void kernel_launch(void* const* d_in, const int* in_sizes, int n_in,
                              void* d_out, int out_size) {
    const float* query = (const float*)d_in[0];
    const float* key = (const float*)d_in[1];
    const float* value = (const float*)d_in[2];
    const float* ada_gamma = (const float*)d_in[3];
    const float* ada_beta = (const float*)d_in[4];
    const float* Wq = (const float*)d_in[5];
    const float* bq = (const float*)d_in[6];
    const float* Wk = (const float*)d_in[7];
    const float* bk = (const float*)d_in[8];
    const float* Wv = (const float*)d_in[9];
    const float* bv = (const float*)d_in[10];
    const float* Wo = (const float*)d_in[11];
    const float* bo = (const float*)d_in[12];
    const float* lnq_w = (const float*)d_in[13];
    const float* lnq_b = (const float*)d_in[14];
    const float* lnk_w = (const float*)d_in[15];
    const float* lnk_b = (const float*)d_in[16];
    const float* attn_scalar = (const float*)d_in[17];
    const float* ffn_gamma = (const float*)d_in[18];
    const float* ffn_beta = (const float*)d_in[19];
    const float* W1 = (const float*)d_in[20];
    const float* b1 = (const float*)d_in[21];
    const float* W2 = (const float*)d_in[22];
    const float* b2 = (const float*)d_in[23];
    const float* ffn_scalar = (const float*)d_in[24];
    const float* final_scalar = (const float*)d_in[25];
    float* out = (float*)d_out;

    float *q, *k, *v, *working, *kv, *ksum, *gx, *meanc;
    __nv_bfloat16 *ada_b, *key_b, *val_b, *qp_b, *nrm_b, *h_b, *wts, *M_b;
    cudaGetSymbolAddress((void**)&q, g_q);
    cudaGetSymbolAddress((void**)&k, g_k);
    cudaGetSymbolAddress((void**)&v, g_v);
    cudaGetSymbolAddress((void**)&working, g_working);
    cudaGetSymbolAddress((void**)&kv, g_kv);
    cudaGetSymbolAddress((void**)&ksum, g_ksum);
    cudaGetSymbolAddress((void**)&gx, g_gx);
    cudaGetSymbolAddress((void**)&meanc, g_meanc);
    cudaGetSymbolAddress((void**)&ada_b, b_ada);
    cudaGetSymbolAddress((void**)&key_b, b_key);
    cudaGetSymbolAddress((void**)&val_b, b_val);
    cudaGetSymbolAddress((void**)&qp_b, b_qp);
    cudaGetSymbolAddress((void**)&nrm_b, b_nrm);
    cudaGetSymbolAddress((void**)&h_b, b_h);
    cudaGetSymbolAddress((void**)&wts, b_wts);
    cudaGetSymbolAddress((void**)&M_b, b_M);

    __nv_bfloat16* wq_b = wts;
    __nv_bfloat16* wk_b = wts + CC;
    __nv_bfloat16* wv_b = wts + 2 * CC;
    __nv_bfloat16* w1_b = wts + 4 * CC;
    __nv_bfloat16* w2_b = wts + 4 * CC + FC;

    cudaFuncSetAttribute(gemm_bf16_row, cudaFuncAttributeMaxDynamicSharedMemorySize, GEMM_SMEM);
    cudaFuncSetAttribute(gemm_bf16_cm, cudaFuncAttributeMaxDynamicSharedMemorySize, GEMM_SMEM);

    // 0) weight conversions (one launch)
    conv_f2bf_all<<<1728, 256>>>((const float4*)Wq, (const float4*)Wk, (const float4*)Wv,
                                 (const float4*)Wo, (const float4*)W1, (const float4*)W2,
                                 (__nv_bfloat162*)wts);

    // 0b) key/value transpose-convert to bf16 rows
    transconv_kernel<<<dim3(Cn / 64, NK / 32, Bn), 256>>>(key, key_b, nullptr, nullptr,
                                                          nullptr, nullptr, NK, 0);
    transconv_kernel<<<dim3(Cn / 64, NK / 32, Bn), 256>>>(value, val_b, nullptr, nullptr,
                                                          nullptr, nullptr, NK, 0);

    // 1) GRN on query -> ada (bf16 rows, fused transpose)
    grn_reduce_kernel<<<Bn * Cn, 256>>>(query, gx, NQ);
    grn_mean_kernel<<<Bn, 128>>>(gx, meanc);
    transconv_kernel<<<dim3(Cn / 64, NQ / 32, Bn), 256>>>(query, ada_b, gx, meanc,
                                                          ada_gamma, ada_beta, NQ, 1);

    // 2) Q projection; K+V projections merged into one launch (ysplit = Cn/BN = 3)
    gemm_bf16_row<<<dim3(NQ / BM, Cn / BN, Bn), 256, GEMM_SMEM>>>(
        ada_b, wq_b, bq, q, nullptr, nullptr, nullptr, nullptr, nullptr, NQ, Cn, Cn, 0, 1000);
    gemm_bf16_row<<<dim3(NK / BM, 2 * (Cn / BN), Bn), 256, GEMM_SMEM>>>(
        key_b, wk_b, bk, k, nullptr, val_b, wv_b, bv, v, NK, Cn, Cn, 0, Cn / BN);

    // 3) LN + elu+1 on k (in place, fp32)
    ln_elu_kernel<<<Bn * NK, 128>>>(k, lnk_w, lnk_b);

    // 4) zero kv/ksum/gx, then kv_sum/k_sum
    zero_kv<<<(Bn * Hn * Dn * Dn + 255) / 256, 256>>>(kv, ksum, gx);
    kv_v2<<<dim3(Bn * Hn, 4), 256>>>(k, v, kv, ksum);

    // 5a) q: LN + elu+1 + fold den -> bf16 q'
    ln_elu_q_den<<<Bn * NQ, 128>>>(q, ksum, lnq_w, lnq_b, qp_b);

    // 5b) fold kv into Wo: per-batch effective weight M
    make_M<<<dim3(Cn / 128, Hn, Bn), 256>>>(kv, Wo, M_b);

    // 6) (attention + Wo) as ONE GEMM; fused GRN sum-of-squares into gx (mode 2)
    gemm_bf16_cm<<<dim3(NQ / BM, Cn / BN, Bn), 256, GEMM_SMEM>>>(
        qp_b, M_b, bo, query, nullptr, attn_scalar, nullptr, working, gx,
        NQ, Cn, Cn, 2, Cn * Cn);

    // 7) GRN mean + transconv on working (reduce fused into step 6)
    grn_mean_kernel<<<Bn, 128>>>(gx, meanc);
    transconv_kernel<<<dim3(Cn / 64, NQ / 32, Bn), 256>>>(working, nrm_b, gx, meanc,
                                                          ffn_gamma, ffn_beta, NQ, 1);

    // 8) FFN1 (+silu) -> h (bf16 rows)
    gemm_bf16_row<<<dim3(NQ / BM, Fn / BN, Bn), 256, GEMM_SMEM>>>(
        nrm_b, w1_b, b1, nullptr, h_b, nullptr, nullptr, nullptr, nullptr, NQ, Cn, Fn, 1, 1000);

    // 9) FFN2 + ffn residual + final residual -> out (fp32, channel-major)
    gemm_bf16_cm<<<dim3(NQ / BM, Cn / BN, Bn), 256, GEMM_SMEM>>>(
        h_b, w2_b, b2, query, working, ffn_scalar, final_scalar, out, nullptr,
        NQ, Fn, Cn, 1, 0);
}

// round 12
// speedup vs baseline: 1.2348x; 1.0212x over previous
#include <cuda_runtime.h>
#include <cuda_bf16.h>
#include <math.h>
#include <stdint.h>

// Problem constants
#define Bn 8
#define Cn 384
#define NQ 4096
#define NK 1024
#define Hn 8
#define Dn 48
#define Fn 1536
#define GRN_EPS 1e-6f
#define LN_EPS 1e-5f

// GEMM tiling (bf16): 128x128 CTA tile, 64x32 warp tiles (validated R9 config)
#define BM 128
#define BN 128
#define KSB 32        // k elements per slab
#define KW 16         // uint32 words per row (KSB/2)
#define NSTAGE 3
#define GW (BM * KW)  // words per stage per operand (2048)
#define GEMM_SMEM (NSTAGE * 2 * GW * 4)  // 49152 bytes

#define CC (Cn * Cn)
#define FC (Fn * Cn)

// ---------------- scratch (device globals; no allocations) ----------------
__device__ float g_k[(size_t)Bn * NK * Cn];
__device__ float g_v[(size_t)Bn * NK * Cn];
__device__ float g_working[(size_t)Bn * Cn * NQ];
__device__ float g_kv[(size_t)Bn * Hn * Dn * Dn];
__device__ float g_ksum[(size_t)Bn * Hn * Dn];
__device__ float g_gx[(size_t)Bn * Cn];
__device__ float g_meanc[Bn];

__device__ __nv_bfloat16 b_ada[(size_t)Bn * NQ * Cn];
__device__ __nv_bfloat16 b_key[(size_t)Bn * NK * Cn];
__device__ __nv_bfloat16 b_val[(size_t)Bn * NK * Cn];
__device__ __nv_bfloat16 b_qh[(size_t)Bn * NQ * Cn];   // raw q (bf16, pre-LN)
__device__ __nv_bfloat16 b_qp[(size_t)Bn * NQ * Cn];   // q' = (elu(LN(q))+1)/den
__device__ __nv_bfloat16 b_nrm[(size_t)Bn * NQ * Cn];
__device__ __nv_bfloat16 b_h[(size_t)Bn * NQ * Fn];
__device__ __nv_bfloat16 b_wts[4 * CC + 2 * FC];
__device__ __nv_bfloat16 b_M[(size_t)Bn * Cn * Cn];

// ---------------- helpers ----------------
__device__ __forceinline__ void cp_async16(void* smem_dst, const void* gsrc) {
    uint32_t s = (uint32_t)__cvta_generic_to_shared(smem_dst);
    asm volatile("cp.async.cg.shared.global [%0], [%1], 16;" ::"r"(s), "l"(gsrc));
}
__device__ __forceinline__ void cp_commit() { asm volatile("cp.async.commit_group;"); }
__device__ __forceinline__ void cp_wait1() { asm volatile("cp.async.wait_group 1;"); }
__device__ __forceinline__ void cp_wait0() { asm volatile("cp.async.wait_group 0;"); }

__device__ __forceinline__ void mma16(float* c, uint32_t a0, uint32_t a1, uint32_t a2,
                                      uint32_t a3, uint32_t b0, uint32_t b1) {
    asm volatile(
        "mma.sync.aligned.m16n8k16.row.col.f32.bf16.bf16.f32 "
        "{%0,%1,%2,%3},{%4,%5,%6,%7},{%8,%9},{%0,%1,%2,%3};"
        : "+f"(c[0]), "+f"(c[1]), "+f"(c[2]), "+f"(c[3])
        : "r"(a0), "r"(a1), "r"(a2), "r"(a3), "r"(b0), "r"(b1));
}

__device__ __forceinline__ void ldsm4(uint32_t& r0, uint32_t& r1, uint32_t& r2, uint32_t& r3,
                                      uint32_t saddr) {
    asm volatile("ldmatrix.sync.aligned.m8n8.x4.shared.b16 {%0,%1,%2,%3}, [%4];"
                 : "=r"(r0), "=r"(r1), "=r"(r2), "=r"(r3)
                 : "r"(saddr));
}

// ---------------- merged weight convert ----------------
__global__ void conv_f2bf_all(const float4* __restrict__ wq, const float4* __restrict__ wk,
                              const float4* __restrict__ wv, const float4* __restrict__ wo,
                              const float4* __restrict__ w1, const float4* __restrict__ w2,
                              __nv_bfloat162* __restrict__ dst) {
    const int C4 = CC / 4, F4 = FC / 4;
    int total = 4 * C4 + 2 * F4;
    for (int i = blockIdx.x * 256 + threadIdx.x; i < total; i += gridDim.x * 256) {
        const float4* src;
        int off;
        if (i < 4 * C4) {
            int seg = i / C4;
            off = i - seg * C4;
            src = (seg == 0) ? wq : (seg == 1) ? wk : (seg == 2) ? wv : wo;
        } else if (i < 4 * C4 + F4) {
            src = w1;
            off = i - 4 * C4;
        } else {
            src = w2;
            off = i - 4 * C4 - F4;
        }
        float4 v = src[off];
        __nv_bfloat162 a, b;
        a.x = __float2bfloat16_rn(v.x); a.y = __float2bfloat16_rn(v.y);
        b.x = __float2bfloat16_rn(v.z); b.y = __float2bfloat16_rn(v.w);
        dst[2 * i] = a;
        dst[2 * i + 1] = b;
    }
}

// ---------------- GRN ----------------
__global__ void grn_reduce_kernel(const float* __restrict__ x, float* __restrict__ gx, int N) {
    int bc = blockIdx.x;
    const float4* p = (const float4*)(x + (size_t)bc * N);
    int n4 = N >> 2;
    float s = 0.f;
    for (int i = threadIdx.x; i < n4; i += 256) {
        float4 v = p[i];
        s += v.x * v.x + v.y * v.y + v.z * v.z + v.w * v.w;
    }
    __shared__ float red[256];
    red[threadIdx.x] = s;
    __syncthreads();
    for (int st = 128; st > 0; st >>= 1) {
        if (threadIdx.x < st) red[threadIdx.x] += red[threadIdx.x + st];
        __syncthreads();
    }
    if (threadIdx.x == 0) gx[bc] = sqrtf(red[0]);
}

__global__ void grn_mean_kernel(const float* __restrict__ gx, float* __restrict__ meanc) {
    int b = blockIdx.x;
    int t = threadIdx.x;  // 128
    float s = 0.f;
    for (int c = t; c < Cn; c += 128) s += gx[b * Cn + c];
    __shared__ float red[128];
    red[t] = s;
    __syncthreads();
    for (int st = 64; st > 0; st >>= 1) {
        if (t < st) red[t] += red[t + st];
        __syncthreads();
    }
    if (t == 0) meanc[b] = red[0] * (1.f / (float)Cn) + GRN_EPS;
}

// ---------------- transpose + (optional GRN) + convert to bf16 rows ----------------
__global__ void transconv_kernel(const float* __restrict__ x, __nv_bfloat16* __restrict__ out,
                                 const float* __restrict__ gx, const float* __restrict__ meanc,
                                 const float* __restrict__ gamma, const float* __restrict__ beta,
                                 int N, int grn) {
    int b = blockIdx.z;
    int c0 = blockIdx.x * 64;
    int n0 = blockIdx.y * 32;
    __shared__ float t[64][33];
    int tid = threadIdx.x;
    int j = tid & 31, i0 = tid >> 5;
#pragma unroll
    for (int p = 0; p < 8; p++) {
        int i = i0 + p * 8;
        t[i][j] = x[((size_t)b * Cn + c0 + i) * N + n0 + j];
    }
    __syncthreads();
    int cp = tid & 31;
    int nn0 = tid >> 5;
    int c = c0 + 2 * cp;
    float sc0 = 1.f, bt0 = 0.f, sc1 = 1.f, bt1 = 0.f;
    if (grn) {
        sc0 = 1.f + (1.f + gamma[c]) * gx[b * Cn + c] / meanc[b];
        bt0 = beta[c];
        sc1 = 1.f + (1.f + gamma[c + 1]) * gx[b * Cn + c + 1] / meanc[b];
        bt1 = beta[c + 1];
    }
#pragma unroll
    for (int p = 0; p < 4; p++) {
        int nn = nn0 + p * 8;
        float v0 = t[2 * cp][nn] * sc0 + bt0;
        float v1 = t[2 * cp + 1][nn] * sc1 + bt1;
        __nv_bfloat162 hv;
        hv.x = __float2bfloat16_rn(v0);
        hv.y = __float2bfloat16_rn(v1);
        *(__nv_bfloat162*)(out + ((size_t)b * N + n0 + nn) * Cn + c) = hv;
    }
}

// ---------------- shared GEMM mainloop (128x128 tile, ldmatrix fragments) --------------
#define GEMM_MAINLOOP(Ab, Wp, K)                                                          \
    const uint32_t a_base = (uint32_t)__cvta_generic_to_shared(As);                       \
    const uint32_t b_base = (uint32_t)__cvta_generic_to_shared(Bs);                       \
    int lr = (lane & 7) + ((lane >> 3) & 1) * 8;                                          \
    int lca = lane >> 4;                                                                  \
    int lrb = (lane & 7) + (lane >> 4) * 8;                                               \
    int lcb = (lane >> 3) & 1;                                                            \
    int nslab = (K) / KSB;                                                                \
    LOAD_BF(0, 0);                                                                        \
    LOAD_BF(1, 1);                                                                        \
    for (int s = 0; s < nslab; s++) {                                                     \
        int stg = s % NSTAGE;                                                             \
        if (s + 1 < nslab) cp_wait1(); else cp_wait0();                                   \
        __syncthreads();                                                                  \
        if (s + 2 < nslab) LOAD_BF(s + 2, (s + 2) % NSTAGE);                              \
        uint32_t Ast = a_base + stg * GW * 4;                                             \
        uint32_t Bst = b_base + stg * GW * 4;                                             \
        _Pragma("unroll") for (int kb = 0; kb < 2; kb++) {                                \
            uint32_t af[4][4], bfr[4][2];                                                 \
            _Pragma("unroll") for (int mf = 0; mf < 4; mf++) {                            \
                int row = wm + mf * 16 + lr;                                              \
                int ch = 2 * kb + lca;                                                    \
                ldsm4(af[mf][0], af[mf][1], af[mf][2], af[mf][3],                         \
                      Ast + row * 64 + ((ch ^ ((row >> 1) & 3)) << 4));                   \
            }                                                                             \
            _Pragma("unroll") for (int p = 0; p < 2; p++) {                               \
                int row = wn + p * 16 + lrb;                                              \
                int ch = 2 * kb + lcb;                                                    \
                ldsm4(bfr[2 * p][0], bfr[2 * p][1], bfr[2 * p + 1][0], bfr[2 * p + 1][1], \
                      Bst + row * 64 + ((ch ^ ((row >> 1) & 3)) << 4));                   \
            }                                                                             \
            _Pragma("unroll") for (int mf = 0; mf < 4; mf++)                              \
                _Pragma("unroll") for (int nf = 0; nf < 4; nf++)                          \
                    mma16(acc[mf][nf], af[mf][0], af[mf][1], af[mf][2], af[mf][3],        \
                          bfr[nf][0], bfr[nf][1]);                                        \
        }                                                                                 \
    }

#define LOAD_BF(slab, stg)                                                              \
    {                                                                                   \
        int kk0 = (slab)*KSB;                                                           \
        uint32_t* Ad = As + (size_t)(stg)*GW;                                           \
        uint32_t* Bd = Bs + (size_t)(stg)*GW;                                           \
        _Pragma("unroll") for (int p = 0; p < 2; p++) {                                 \
            int c = tid + p * 256;                                                      \
            int r = c >> 2, ch = c & 3;                                                 \
            int sw = ((ch ^ ((r >> 1) & 3)) << 2);                                      \
            cp_async16(Ad + r * KW + sw, Ab + (size_t)(m0 + r) * K + kk0 + ch * 8);     \
            cp_async16(Bd + r * KW + sw, Wp + (size_t)(c0 + r) * K + kk0 + ch * 8);     \
        }                                                                               \
        cp_commit();                                                                    \
    }

// ---------------- bf16 GEMM, row-major output (+optional second problem set) ----------
// modes: 0 = fp32 out, 1 = silu+bf16 out, 2 = plain bf16 out
// blockIdx.y < ysplit: set 1; else set 2 (A2,W2,bias2 -> Yf2, mode 0)
__global__ __launch_bounds__(256) void gemm_bf16_row(
    const __nv_bfloat16* __restrict__ A, const __nv_bfloat16* __restrict__ W,
    const float* __restrict__ bias, float* __restrict__ Yf, __nv_bfloat16* __restrict__ Yh,
    const __nv_bfloat16* __restrict__ A2, const __nv_bfloat16* __restrict__ W2,
    const float* __restrict__ bias2, float* __restrict__ Yf2,
    int N, int K, int Cout, int mode, int ysplit) {
    extern __shared__ uint32_t smu[];
    uint32_t* As = smu;
    uint32_t* Bs = smu + NSTAGE * GW;
    int b = blockIdx.z;
    int m0 = blockIdx.x * BM;
    int yb = blockIdx.y;
    if (yb >= ysplit) {
        A = A2; W = W2; bias = bias2; Yf = Yf2; Yh = nullptr; mode = 0;
        yb -= ysplit;
    }
    int c0 = yb * BN;
    int tid = threadIdx.x;
    int warp = tid >> 5, lane = tid & 31;
    int g = lane >> 2, lq = lane & 3;
    int wm = (warp >> 2) * 64;
    int wn = (warp & 3) * 32;
    float acc[4][4][4] = {};
    const __nv_bfloat16* Ab = A + (size_t)b * N * K;
    const __nv_bfloat16* Wp = W;

    GEMM_MAINLOOP(Ab, Wp, K)

#pragma unroll
    for (int mf = 0; mf < 4; mf++) {
#pragma unroll
        for (int nf = 0; nf < 4; nf++) {
            int co = c0 + wn + nf * 8 + lq * 2;
            float b0v = bias[co], b1v = bias[co + 1];
#pragma unroll
            for (int hr = 0; hr < 2; hr++) {
                int m = m0 + wm + mf * 16 + g + hr * 8;
                float v0 = acc[mf][nf][hr * 2 + 0] + b0v;
                float v1 = acc[mf][nf][hr * 2 + 1] + b1v;
                if (mode == 0) {
                    *(float2*)(Yf + ((size_t)b * N + m) * Cout + co) = make_float2(v0, v1);
                } else {
                    if (mode == 1) {
                        v0 = v0 / (1.f + expf(-v0));
                        v1 = v1 / (1.f + expf(-v1));
                    }
                    __nv_bfloat162 hv;
                    hv.x = __float2bfloat16_rn(v0);
                    hv.y = __float2bfloat16_rn(v1);
                    *(__nv_bfloat162*)(Yh + ((size_t)b * N + m) * Cout + co) = hv;
                }
            }
        }
    }
}

// ---------------- bf16 GEMM, channel-major fused output (batch-strided W) ----------
// mode 0: out = resid1 + val*s1
// mode 1: out = resid1 + (resid2 + val*s1)*s2
__global__ __launch_bounds__(256) void gemm_bf16_cm(
    const __nv_bfloat16* __restrict__ A, const __nv_bfloat16* __restrict__ W,
    const float* __restrict__ bias,
    const float* __restrict__ resid1, const float* __restrict__ resid2,
    const float* __restrict__ scal1, const float* __restrict__ scal2,
    float* __restrict__ out, int N, int K, int Cout, int mode, int wstride) {
    extern __shared__ uint32_t smu[];
    uint32_t* As = smu;
    uint32_t* Bs = smu + NSTAGE * GW;
    int b = blockIdx.z;
    int m0 = blockIdx.x * BM;
    int c0 = blockIdx.y * BN;
    int tid = threadIdx.x;
    int warp = tid >> 5, lane = tid & 31;
    int g = lane >> 2, lq = lane & 3;
    int wm = (warp >> 2) * 64;
    int wn = (warp & 3) * 32;
    float acc[4][4][4] = {};
    const __nv_bfloat16* Ab = A + (size_t)b * N * K;
    const __nv_bfloat16* Wp = W + (size_t)b * wstride;

    GEMM_MAINLOOP(Ab, Wp, K)

#pragma unroll
    for (int nf = 0; nf < 4; nf++) {
#pragma unroll
        for (int cj = 0; cj < 2; cj++) {
            int co = c0 + wn + nf * 8 + lq * 2 + cj;
            float bv = bias[co];
            float s1 = scal1[co];
            float s2 = (mode == 1) ? scal2[co] : 0.f;
#pragma unroll
            for (int mf = 0; mf < 4; mf++) {
#pragma unroll
                for (int hr = 0; hr < 2; hr++) {
                    int m = m0 + wm + mf * 16 + g + hr * 8;
                    size_t idx = ((size_t)b * Cout + co) * (size_t)N + m;
                    float val = acc[mf][nf][hr * 2 + cj] + bv;
                    if (mode == 0)
                        out[idx] = resid1[idx] + val * s1;
                    else
                        out[idx] = resid1[idx] + (resid2[idx] + val * s1) * s2;
                }
            }
        }
    }
}

// ---------------- LayerNorm + elu+1 (in place) — for k ----------------
__global__ void ln_elu_kernel(float* __restrict__ x, const float* __restrict__ w,
                              const float* __restrict__ bvec) {
    int r = blockIdx.x;
    float* p = x + (size_t)r * Cn;
    int t = threadIdx.x;  // 128
    float v0 = p[t], v1 = p[t + 128], v2 = p[t + 256];
    float s = v0 + v1 + v2;
    float s2 = v0 * v0 + v1 * v1 + v2 * v2;
    __shared__ float red[128];
    red[t] = s;
    __syncthreads();
    for (int st = 64; st > 0; st >>= 1) {
        if (t < st) red[t] += red[t + st];
        __syncthreads();
    }
    float mu = red[0] * (1.f / (float)Cn);
    __syncthreads();
    red[t] = s2;
    __syncthreads();
    for (int st = 64; st > 0; st >>= 1) {
        if (t < st) red[t] += red[t + st];
        __syncthreads();
    }
    float var = red[0] * (1.f / (float)Cn) - mu * mu;
    float inv = rsqrtf(var + LN_EPS);
    float y;
    y = (v0 - mu) * inv * w[t] + bvec[t];
    p[t] = (y > 0.f) ? y + 1.f : expf(y);
    y = (v1 - mu) * inv * w[t + 128] + bvec[t + 128];
    p[t + 128] = (y > 0.f) ? y + 1.f : expf(y);
    y = (v2 - mu) * inv * w[t + 256] + bvec[t + 256];
    p[t + 256] = (y > 0.f) ? y + 1.f : expf(y);
}

// ---------------- q: LayerNorm + elu+1 + den fold -> bf16 q' (reads bf16 q) ----------
__global__ void ln_elu_q_den(const __nv_bfloat16* __restrict__ x,
                             const float* __restrict__ ksum,
                             const float* __restrict__ w, const float* __restrict__ bvec,
                             __nv_bfloat16* __restrict__ qp) {
    int r = blockIdx.x;
    int b = r / NQ;
    const __nv_bfloat16* p = x + (size_t)r * Cn;
    int t = threadIdx.x;  // 128
    float v0 = __bfloat162float(p[t]);
    float v1 = __bfloat162float(p[t + 128]);
    float v2 = __bfloat162float(p[t + 256]);
    float s = v0 + v1 + v2;
    float s2 = v0 * v0 + v1 * v1 + v2 * v2;
    __shared__ float red[128];
    __shared__ float yb[384];
    __shared__ float den[8];
    red[t] = s;
    __syncthreads();
    for (int st = 64; st > 0; st >>= 1) {
        if (t < st) red[t] += red[t + st];
        __syncthreads();
    }
    float mu = red[0] * (1.f / (float)Cn);
    __syncthreads();
    red[t] = s2;
    __syncthreads();
    for (int st = 64; st > 0; st >>= 1) {
        if (t < st) red[t] += red[t + st];
        __syncthreads();
    }
    float var = red[0] * (1.f / (float)Cn) - mu * mu;
    float inv = rsqrtf(var + LN_EPS);
    float y0 = (v0 - mu) * inv * w[t] + bvec[t];
    y0 = (y0 > 0.f) ? y0 + 1.f : expf(y0);
    float y1 = (v1 - mu) * inv * w[t + 128] + bvec[t + 128];
    y1 = (y1 > 0.f) ? y1 + 1.f : expf(y1);
    float y2 = (v2 - mu) * inv * w[t + 256] + bvec[t + 256];
    y2 = (y2 > 0.f) ? y2 + 1.f : expf(y2);
    yb[t] = y0; yb[t + 128] = y1; yb[t + 256] = y2;
    __syncthreads();
    if (t < 8) {
        const float* ksr = ksum + ((size_t)b * Hn + t) * Dn;
        float sd = 0.f;
#pragma unroll
        for (int j = 0; j < Dn; j++) sd += yb[t * Dn + j] * ksr[j];
        den[t] = sd + 1e-8f;
    }
    __syncthreads();
    __nv_bfloat16* o = qp + (size_t)r * Cn;
    o[t] = __float2bfloat16_rn(y0 / den[t / Dn]);
    o[t + 128] = __float2bfloat16_rn(y1 / den[(t + 128) / Dn]);
    o[t + 256] = __float2bfloat16_rn(y2 / den[(t + 256) / Dn]);
}

// ---------------- zero kv/ksum ----------------
__global__ void zero_kv(float* __restrict__ kv, float* __restrict__ ksum) {
    int i = blockIdx.x * 256 + threadIdx.x;
    if (i < Bn * Hn * Dn * Dn) kv[i] = 0.f;
    if (i < Bn * Hn * Dn) ksum[i] = 0.f;
}

// ---------------- kv_sum + k_sum: register outer-product + NK split --------------
__global__ void kv_v2(const float* __restrict__ k, const float* __restrict__ v,
                      float* __restrict__ kv, float* __restrict__ ksum) {
    int bh = blockIdx.x;
    int chunk = blockIdx.y;
    int b = bh >> 3, h = bh & 7;
    __shared__ float ks[32][49];
    __shared__ float vs[32][49];
    int tid = threadIdx.x;  // 256
    int di = tid >> 4, ei = tid & 15;
    int d0 = di * 3, e0 = ei * 3;
    float acc[3][3] = {};
    float ksa[3] = {};
    int nbeg = chunk * (NK / 4);
    for (int n0 = nbeg; n0 < nbeg + NK / 4; n0 += 32) {
        for (int i = tid; i < 32 * Dn; i += 256) {
            int nn = i / Dn, dd = i % Dn;
            size_t base = ((size_t)b * NK + n0 + nn) * Cn + h * Dn + dd;
            ks[nn][dd] = k[base];
            vs[nn][dd] = v[base];
        }
        __syncthreads();
#pragma unroll 4
        for (int nn = 0; nn < 32; nn++) {
            float kd0 = ks[nn][d0], kd1 = ks[nn][d0 + 1], kd2 = ks[nn][d0 + 2];
            float ve0 = vs[nn][e0], ve1 = vs[nn][e0 + 1], ve2 = vs[nn][e0 + 2];
            acc[0][0] += kd0 * ve0; acc[0][1] += kd0 * ve1; acc[0][2] += kd0 * ve2;
            acc[1][0] += kd1 * ve0; acc[1][1] += kd1 * ve1; acc[1][2] += kd1 * ve2;
            acc[2][0] += kd2 * ve0; acc[2][1] += kd2 * ve1; acc[2][2] += kd2 * ve2;
            if (ei == 0) { ksa[0] += kd0; ksa[1] += kd1; ksa[2] += kd2; }
        }
        __syncthreads();
    }
    float* kvb = kv + (size_t)bh * Dn * Dn;
#pragma unroll
    for (int i = 0; i < 3; i++)
#pragma unroll
        for (int j = 0; j < 3; j++)
            atomicAdd(&kvb[(d0 + i) * Dn + e0 + j], acc[i][j]);
    if (ei == 0)
#pragma unroll
        for (int i = 0; i < 3; i++) atomicAdd(&ksum[bh * Dn + d0 + i], ksa[i]);
}

// ---------------- make_M ----------------
__global__ void make_M(const float* __restrict__ kv, const float* __restrict__ Wo,
                       __nv_bfloat16* __restrict__ Wt) {
    int cb = blockIdx.x;
    int h = blockIdx.y;
    int b = blockIdx.z;
    __shared__ float kvs[Dn][49];
    __shared__ float wos[Dn][132];
    int tid = threadIdx.x;  // 256
    for (int i = tid; i < Dn * Dn; i += 256)
        kvs[i / Dn][i % Dn] = kv[((size_t)b * Hn + h) * Dn * Dn + i];
    for (int i = tid; i < 128 * Dn; i += 256) {
        int co = i / Dn, e = i % Dn;
        wos[e][co] = Wo[(size_t)(cb * 128 + co) * Cn + h * Dn + e];
    }
    __syncthreads();
    int cog = tid & 15, dg = tid >> 4;
    int co0 = cog * 8, d0 = dg * 3;
    float acc[8][3] = {};
#pragma unroll 4
    for (int e = 0; e < Dn; e++) {
        float kd0 = kvs[d0][e], kd1 = kvs[d0 + 1][e], kd2 = kvs[d0 + 2][e];
#pragma unroll
        for (int i = 0; i < 8; i++) {
            float wv = wos[e][co0 + i];
            acc[i][0] += wv * kd0;
            acc[i][1] += wv * kd1;
            acc[i][2] += wv * kd2;
        }
    }
#pragma unroll
    for (int i = 0; i < 8; i++)
#pragma unroll
        for (int j = 0; j < 3; j++)
            Wt[((size_t)b * Cn + cb * 128 + co0 + i) * Cn + h * Dn + d0 + j] =
                __float2bfloat16_rn(acc[i][j]);
}

// ---------------- host launch ----------------
extern "C" void kernel_launch(void* const* d_in, const int* in_sizes, int n_in,
                              void* d_out, int out_size) {
    const float* query = (const float*)d_in[0];
    const float* key = (const float*)d_in[1];
    const float* value = (const float*)d_in[2];
    const float* ada_gamma = (const float*)d_in[3];
    const float* ada_beta = (const float*)d_in[4];
    const float* Wq = (const float*)d_in[5];
    const float* bq = (const float*)d_in[6];
    const float* Wk = (const float*)d_in[7];
    const float* bk = (const float*)d_in[8];
    const float* Wv = (const float*)d_in[9];
    const float* bv = (const float*)d_in[10];
    const float* Wo = (const float*)d_in[11];
    const float* bo = (const float*)d_in[12];
    const float* lnq_w = (const float*)d_in[13];
    const float* lnq_b = (const float*)d_in[14];
    const float* lnk_w = (const float*)d_in[15];
    const float* lnk_b = (const float*)d_in[16];
    const float* attn_scalar = (const float*)d_in[17];
    const float* ffn_gamma = (const float*)d_in[18];
    const float* ffn_beta = (const float*)d_in[19];
    const float* W1 = (const float*)d_in[20];
    const float* b1 = (const float*)d_in[21];
    const float* W2 = (const float*)d_in[22];
    const float* b2 = (const float*)d_in[23];
    const float* ffn_scalar = (const float*)d_in[24];
    const float* final_scalar = (const float*)d_in[25];
    float* out = (float*)d_out;

    float *k, *v, *working, *kv, *ksum, *gx, *meanc;
    __nv_bfloat16 *ada_b, *key_b, *val_b, *qh_b, *qp_b, *nrm_b, *h_b, *wts, *M_b;
    cudaGetSymbolAddress((void**)&k, g_k);
    cudaGetSymbolAddress((void**)&v, g_v);
    cudaGetSymbolAddress((void**)&working, g_working);
    cudaGetSymbolAddress((void**)&kv, g_kv);
    cudaGetSymbolAddress((void**)&ksum, g_ksum);
    cudaGetSymbolAddress((void**)&gx, g_gx);
    cudaGetSymbolAddress((void**)&meanc, g_meanc);
    cudaGetSymbolAddress((void**)&ada_b, b_ada);
    cudaGetSymbolAddress((void**)&key_b, b_key);
    cudaGetSymbolAddress((void**)&val_b, b_val);
    cudaGetSymbolAddress((void**)&qh_b, b_qh);
    cudaGetSymbolAddress((void**)&qp_b, b_qp);
    cudaGetSymbolAddress((void**)&nrm_b, b_nrm);
    cudaGetSymbolAddress((void**)&h_b, b_h);
    cudaGetSymbolAddress((void**)&wts, b_wts);
    cudaGetSymbolAddress((void**)&M_b, b_M);

    __nv_bfloat16* wq_b = wts;
    __nv_bfloat16* wk_b = wts + CC;
    __nv_bfloat16* wv_b = wts + 2 * CC;
    __nv_bfloat16* w1_b = wts + 4 * CC;
    __nv_bfloat16* w2_b = wts + 4 * CC + FC;

    cudaFuncSetAttribute(gemm_bf16_row, cudaFuncAttributeMaxDynamicSharedMemorySize, GEMM_SMEM);
    cudaFuncSetAttribute(gemm_bf16_cm, cudaFuncAttributeMaxDynamicSharedMemorySize, GEMM_SMEM);

    // 0) weight conversions (one launch)
    conv_f2bf_all<<<1728, 256>>>((const float4*)Wq, (const float4*)Wk, (const float4*)Wv,
                                 (const float4*)Wo, (const float4*)W1, (const float4*)W2,
                                 (__nv_bfloat162*)wts);

    // 0b) key/value transpose-convert to bf16 rows
    transconv_kernel<<<dim3(Cn / 64, NK / 32, Bn), 256>>>(key, key_b, nullptr, nullptr,
                                                          nullptr, nullptr, NK, 0);
    transconv_kernel<<<dim3(Cn / 64, NK / 32, Bn), 256>>>(value, val_b, nullptr, nullptr,
                                                          nullptr, nullptr, NK, 0);

    // 1) GRN on query -> ada (bf16 rows, fused transpose)
    grn_reduce_kernel<<<Bn * Cn, 256>>>(query, gx, NQ);
    grn_mean_kernel<<<Bn, 128>>>(gx, meanc);
    transconv_kernel<<<dim3(Cn / 64, NQ / 32, Bn), 256>>>(query, ada_b, gx, meanc,
                                                          ada_gamma, ada_beta, NQ, 1);

    // 2) Q projection (bf16 out); K+V projections merged into one launch
    gemm_bf16_row<<<dim3(NQ / BM, Cn / BN, Bn), 256, GEMM_SMEM>>>(
        ada_b, wq_b, bq, nullptr, qh_b, nullptr, nullptr, nullptr, nullptr,
        NQ, Cn, Cn, 2, 1000);
    gemm_bf16_row<<<dim3(NK / BM, 2 * (Cn / BN), Bn), 256, GEMM_SMEM>>>(
        key_b, wk_b, bk, k, nullptr, val_b, wv_b, bv, v, NK, Cn, Cn, 0, Cn / BN);

    // 3) LN + elu+1 on k (in place, fp32)
    ln_elu_kernel<<<Bn * NK, 128>>>(k, lnk_w, lnk_b);

    // 4) zero kv/ksum, then kv_sum/k_sum
    zero_kv<<<(Bn * Hn * Dn * Dn + 255) / 256, 256>>>(kv, ksum);
    kv_v2<<<dim3(Bn * Hn, 4), 256>>>(k, v, kv, ksum);

    // 5a) q: LN + elu+1 + fold den -> bf16 q' (reads bf16 q)
    ln_elu_q_den<<<Bn * NQ, 128>>>(qh_b, ksum, lnq_w, lnq_b, qp_b);

    // 5b) fold kv into Wo: per-batch effective weight M
    make_M<<<dim3(Cn / 128, Hn, Bn), 256>>>(kv, Wo, M_b);

    // 6) (attention + Wo) as ONE GEMM
    gemm_bf16_cm<<<dim3(NQ / BM, Cn / BN, Bn), 256, GEMM_SMEM>>>(
        qp_b, M_b, bo, query, nullptr, attn_scalar, nullptr, working,
        NQ, Cn, Cn, 0, Cn * Cn);

    // 7) GRN on working -> normed (bf16 rows, fused transpose)
    grn_reduce_kernel<<<Bn * Cn, 256>>>(working, gx, NQ);
    grn_mean_kernel<<<Bn, 128>>>(gx, meanc);
    transconv_kernel<<<dim3(Cn / 64, NQ / 32, Bn), 256>>>(working, nrm_b, gx, meanc,
                                                          ffn_gamma, ffn_beta, NQ, 1);

    // 8) FFN1 (+silu) -> h (bf16 rows)
    gemm_bf16_row<<<dim3(NQ / BM, Fn / BN, Bn), 256, GEMM_SMEM>>>(
        nrm_b, w1_b, b1, nullptr, h_b, nullptr, nullptr, nullptr, nullptr, NQ, Cn, Fn, 1, 1000);

    // 9) FFN2 + ffn residual + final residual -> out (fp32, channel-major)
    gemm_bf16_cm<<<dim3(NQ / BM, Cn / BN, Bn), 256, GEMM_SMEM>>>(
        h_b, w2_b, b2, query, working, ffn_scalar, final_scalar, out,
        NQ, Fn, Cn, 1, 0);
}

// round 14
// speedup vs baseline: 1.3944x; 1.1292x over previous
#include <cuda_runtime.h>
#include <cuda_bf16.h>
#include <math.h>
#include <stdint.h>

// Problem constants
#define Bn 8
#define Cn 384
#define NQ 4096
#define NK 1024
#define Hn 8
#define Dn 48
#define Fn 1536
#define GRN_EPS 1e-6f
#define LN_EPS 1e-5f

// GEMM tiling (bf16): 128x128 CTA tile, 64x32 warp tiles (validated config)
#define BM 128
#define BN 128
#define KSB 32
#define KW 16
#define NSTAGE 3
#define GW (BM * KW)
#define GEMM_SMEM (NSTAGE * 2 * GW * 4)  // 49152 bytes

#define CC (Cn * Cn)
#define FC (Fn * Cn)

// ---------------- scratch (device globals; no allocations) ----------------
__device__ float g_k[(size_t)Bn * NK * Cn];
__device__ float g_v[(size_t)Bn * NK * Cn];
__device__ float g_working[(size_t)Bn * Cn * NQ];
__device__ float g_kv[(size_t)Bn * Hn * Dn * Dn];
__device__ float g_ksum[(size_t)Bn * Hn * Dn];
__device__ float g_gx[(size_t)Bn * Cn];
__device__ float g_meanc[Bn];

__device__ __nv_bfloat16 b_ada[(size_t)Bn * NQ * Cn];
__device__ __nv_bfloat16 b_key[(size_t)Bn * NK * Cn];
__device__ __nv_bfloat16 b_val[(size_t)Bn * NK * Cn];
__device__ __nv_bfloat16 b_qh[(size_t)Bn * NQ * Cn];
__device__ __nv_bfloat16 b_qp[(size_t)Bn * NQ * Cn];
__device__ __nv_bfloat16 b_nrm[(size_t)Bn * NQ * Cn];
__device__ __nv_bfloat16 b_h[(size_t)Bn * NQ * Fn];
__device__ __nv_bfloat16 b_wts[4 * CC + 2 * FC];
__device__ __nv_bfloat16 b_M[(size_t)Bn * Cn * Cn];

// ---------------- helpers ----------------
__device__ __forceinline__ void cp_async16(void* smem_dst, const void* gsrc) {
    uint32_t s = (uint32_t)__cvta_generic_to_shared(smem_dst);
    asm volatile("cp.async.cg.shared.global [%0], [%1], 16;" ::"r"(s), "l"(gsrc));
}
__device__ __forceinline__ void cp_commit() { asm volatile("cp.async.commit_group;"); }
__device__ __forceinline__ void cp_wait1() { asm volatile("cp.async.wait_group 1;"); }
__device__ __forceinline__ void cp_wait0() { asm volatile("cp.async.wait_group 0;"); }

__device__ __forceinline__ void mma16(float* c, uint32_t a0, uint32_t a1, uint32_t a2,
                                      uint32_t a3, uint32_t b0, uint32_t b1) {
    asm volatile(
        "mma.sync.aligned.m16n8k16.row.col.f32.bf16.bf16.f32 "
        "{%0,%1,%2,%3},{%4,%5,%6,%7},{%8,%9},{%0,%1,%2,%3};"
        : "+f"(c[0]), "+f"(c[1]), "+f"(c[2]), "+f"(c[3])
        : "r"(a0), "r"(a1), "r"(a2), "r"(a3), "r"(b0), "r"(b1));
}

__device__ __forceinline__ void ldsm4(uint32_t& r0, uint32_t& r1, uint32_t& r2, uint32_t& r3,
                                      uint32_t saddr) {
    asm volatile("ldmatrix.sync.aligned.m8n8.x4.shared.b16 {%0,%1,%2,%3}, [%4];"
                 : "=r"(r0), "=r"(r1), "=r"(r2), "=r"(r3)
                 : "r"(saddr));
}

// ---------------- merged weight convert ----------------
__global__ void conv_f2bf_all(const float4* __restrict__ wq, const float4* __restrict__ wk,
                              const float4* __restrict__ wv, const float4* __restrict__ wo,
                              const float4* __restrict__ w1, const float4* __restrict__ w2,
                              __nv_bfloat162* __restrict__ dst) {
    const int C4 = CC / 4, F4 = FC / 4;
    int total = 4 * C4 + 2 * F4;
    for (int i = blockIdx.x * 256 + threadIdx.x; i < total; i += gridDim.x * 256) {
        const float4* src;
        int off;
        if (i < 4 * C4) {
            int seg = i / C4;
            off = i - seg * C4;
            src = (seg == 0) ? wq : (seg == 1) ? wk : (seg == 2) ? wv : wo;
        } else if (i < 4 * C4 + F4) {
            src = w1;
            off = i - 4 * C4;
        } else {
            src = w2;
            off = i - 4 * C4 - F4;
        }
        float4 v = src[off];
        __nv_bfloat162 a, b;
        a.x = __float2bfloat16_rn(v.x); a.y = __float2bfloat16_rn(v.y);
        b.x = __float2bfloat16_rn(v.z); b.y = __float2bfloat16_rn(v.w);
        dst[2 * i] = a;
        dst[2 * i + 1] = b;
    }
}

// ---------------- GRN reduce (N=NQ fixed): unrolled loads + warp reduction ----------
__global__ void grn_reduce_kernel(const float* __restrict__ x, float* __restrict__ gx) {
    int bc = blockIdx.x;
    const float4* p = (const float4*)(x + (size_t)bc * NQ);
    int t = threadIdx.x;  // 256; 1024 float4 total
    float4 a = p[t], b = p[t + 256], c = p[t + 512], d = p[t + 768];
    float s = a.x * a.x + a.y * a.y + a.z * a.z + a.w * a.w;
    s += b.x * b.x + b.y * b.y + b.z * b.z + b.w * b.w;
    s += c.x * c.x + c.y * c.y + c.z * c.z + c.w * c.w;
    s += d.x * d.x + d.y * d.y + d.z * d.z + d.w * d.w;
#pragma unroll
    for (int o = 16; o; o >>= 1) s += __shfl_down_sync(0xffffffffu, s, o);
    __shared__ float r[8];
    if ((t & 31) == 0) r[t >> 5] = s;
    __syncthreads();
    if (t == 0) {
        float S = r[0] + r[1] + r[2] + r[3] + r[4] + r[5] + r[6] + r[7];
        gx[bc] = sqrtf(S);
    }
}

__global__ void grn_mean_kernel(const float* __restrict__ gx, float* __restrict__ meanc) {
    int b = blockIdx.x;
    int t = threadIdx.x;  // 128
    float s = 0.f;
    for (int c = t; c < Cn; c += 128) s += gx[b * Cn + c];
#pragma unroll
    for (int o = 16; o; o >>= 1) s += __shfl_down_sync(0xffffffffu, s, o);
    __shared__ float r[4];
    if ((t & 31) == 0) r[t >> 5] = s;
    __syncthreads();
    if (t == 0) meanc[b] = (r[0] + r[1] + r[2] + r[3]) * (1.f / (float)Cn) + GRN_EPS;
}

// ---------------- transpose + (optional GRN) + convert to bf16 rows ----------------
__global__ void transconv_kernel(const float* __restrict__ x, __nv_bfloat16* __restrict__ out,
                                 const float* __restrict__ gx, const float* __restrict__ meanc,
                                 const float* __restrict__ gamma, const float* __restrict__ beta,
                                 int N, int grn) {
    int b = blockIdx.z;
    int c0 = blockIdx.x * 64;
    int n0 = blockIdx.y * 32;
    __shared__ float t[64][33];
    int tid = threadIdx.x;
    int j = tid & 31, i0 = tid >> 5;
#pragma unroll
    for (int p = 0; p < 8; p++) {
        int i = i0 + p * 8;
        t[i][j] = x[((size_t)b * Cn + c0 + i) * N + n0 + j];
    }
    __syncthreads();
    int cp = tid & 31;
    int nn0 = tid >> 5;
    int c = c0 + 2 * cp;
    float sc0 = 1.f, bt0 = 0.f, sc1 = 1.f, bt1 = 0.f;
    if (grn) {
        sc0 = 1.f + (1.f + gamma[c]) * gx[b * Cn + c] / meanc[b];
        bt0 = beta[c];
        sc1 = 1.f + (1.f + gamma[c + 1]) * gx[b * Cn + c + 1] / meanc[b];
        bt1 = beta[c + 1];
    }
#pragma unroll
    for (int p = 0; p < 4; p++) {
        int nn = nn0 + p * 8;
        float v0 = t[2 * cp][nn] * sc0 + bt0;
        float v1 = t[2 * cp + 1][nn] * sc1 + bt1;
        __nv_bfloat162 hv;
        hv.x = __float2bfloat16_rn(v0);
        hv.y = __float2bfloat16_rn(v1);
        *(__nv_bfloat162*)(out + ((size_t)b * N + n0 + nn) * Cn + c) = hv;
    }
}

// merged key+value transpose-convert (no GRN), one launch
__global__ void transconv_kv(const float* __restrict__ xk, __nv_bfloat16* __restrict__ ok,
                             const float* __restrict__ xv, __nv_bfloat16* __restrict__ ov) {
    int z = blockIdx.z;
    const float* x = (z < Bn) ? xk : xv;
    __nv_bfloat16* out = (z < Bn) ? ok : ov;
    int b = (z < Bn) ? z : z - Bn;
    int c0 = blockIdx.x * 64;
    int n0 = blockIdx.y * 32;
    __shared__ float t[64][33];
    int tid = threadIdx.x;
    int j = tid & 31, i0 = tid >> 5;
#pragma unroll
    for (int p = 0; p < 8; p++) {
        int i = i0 + p * 8;
        t[i][j] = x[((size_t)b * Cn + c0 + i) * NK + n0 + j];
    }
    __syncthreads();
    int cp = tid & 31;
    int nn0 = tid >> 5;
    int c = c0 + 2 * cp;
#pragma unroll
    for (int p = 0; p < 4; p++) {
        int nn = nn0 + p * 8;
        __nv_bfloat162 hv;
        hv.x = __float2bfloat16_rn(t[2 * cp][nn]);
        hv.y = __float2bfloat16_rn(t[2 * cp + 1][nn]);
        *(__nv_bfloat162*)(out + ((size_t)b * NK + n0 + nn) * Cn + c) = hv;
    }
}

// ---------------- shared GEMM mainloop (128x128 tile, ldmatrix fragments) --------------
#define GEMM_MAINLOOP(Ab, Wp, K)                                                          \
    const uint32_t a_base = (uint32_t)__cvta_generic_to_shared(As);                       \
    const uint32_t b_base = (uint32_t)__cvta_generic_to_shared(Bs);                       \
    int lr = (lane & 7) + ((lane >> 3) & 1) * 8;                                          \
    int lca = lane >> 4;                                                                  \
    int lrb = (lane & 7) + (lane >> 4) * 8;                                               \
    int lcb = (lane >> 3) & 1;                                                            \
    int nslab = (K) / KSB;                                                                \
    LOAD_BF(0, 0, Ab, Wp, K);                                                             \
    LOAD_BF(1, 1, Ab, Wp, K);                                                             \
    for (int s = 0; s < nslab; s++) {                                                     \
        int stg = s % NSTAGE;                                                             \
        if (s + 1 < nslab) cp_wait1(); else cp_wait0();                                   \
        __syncthreads();                                                                  \
        if (s + 2 < nslab) LOAD_BF(s + 2, (s + 2) % NSTAGE, Ab, Wp, K);                   \
        uint32_t Ast = a_base + stg * GW * 4;                                             \
        uint32_t Bst = b_base + stg * GW * 4;                                             \
        _Pragma("unroll") for (int kb = 0; kb < 2; kb++) {                                \
            uint32_t af[4][4], bfr[4][2];                                                 \
            _Pragma("unroll") for (int mf = 0; mf < 4; mf++) {                            \
                int row = wm + mf * 16 + lr;                                              \
                int ch = 2 * kb + lca;                                                    \
                ldsm4(af[mf][0], af[mf][1], af[mf][2], af[mf][3],                         \
                      Ast + row * 64 + ((ch ^ ((row >> 1) & 3)) << 4));                   \
            }                                                                             \
            _Pragma("unroll") for (int p = 0; p < 2; p++) {                               \
                int row = wn + p * 16 + lrb;                                              \
                int ch = 2 * kb + lcb;                                                    \
                ldsm4(bfr[2 * p][0], bfr[2 * p][1], bfr[2 * p + 1][0], bfr[2 * p + 1][1], \
                      Bst + row * 64 + ((ch ^ ((row >> 1) & 3)) << 4));                   \
            }                                                                             \
            _Pragma("unroll") for (int mf = 0; mf < 4; mf++)                              \
                _Pragma("unroll") for (int nf = 0; nf < 4; nf++)                          \
                    mma16(acc[mf][nf], af[mf][0], af[mf][1], af[mf][2], af[mf][3],        \
                          bfr[nf][0], bfr[nf][1]);                                        \
        }                                                                                 \
    }

#define LOAD_BF(slab, stg, Abp, Wpp, Kk)                                                \
    {                                                                                   \
        int kk0 = (slab)*KSB;                                                           \
        uint32_t* Ad = As + (size_t)(stg)*GW;                                           \
        uint32_t* Bd = Bs + (size_t)(stg)*GW;                                           \
        _Pragma("unroll") for (int p = 0; p < 2; p++) {                                 \
            int c = tid + p * 256;                                                      \
            int r = c >> 2, ch = c & 3;                                                 \
            int sw = ((ch ^ ((r >> 1) & 3)) << 2);                                      \
            cp_async16(Ad + r * KW + sw, (Abp) + (size_t)(m0 + r) * (Kk) + kk0 + ch * 8); \
            cp_async16(Bd + r * KW + sw, (Wpp) + (size_t)(c0 + r) * (Kk) + kk0 + ch * 8); \
        }                                                                               \
        cp_commit();                                                                    \
    }

// ---------------- Q/K/V projections in ONE launch ----------------
// yb<3: Q-set (bf16 out, N=NQ); 3..5: K-set (fp32, N=NK); 6..8: V-set (fp32, N=NK)
__global__ __launch_bounds__(256) void gemm_qkv(
    const __nv_bfloat16* __restrict__ Aq, const __nv_bfloat16* __restrict__ Wq_,
    const float* __restrict__ bq_, __nv_bfloat16* __restrict__ qh,
    const __nv_bfloat16* __restrict__ Ak, const __nv_bfloat16* __restrict__ Wk_,
    const float* __restrict__ bk_, float* __restrict__ kf,
    const __nv_bfloat16* __restrict__ Av, const __nv_bfloat16* __restrict__ Wv_,
    const float* __restrict__ bv_, float* __restrict__ vf) {
    extern __shared__ uint32_t smu[];
    uint32_t* As = smu;
    uint32_t* Bs = smu + NSTAGE * GW;
    int b = blockIdx.z;
    int m0 = blockIdx.x * BM;
    int yb = blockIdx.y;
    const __nv_bfloat16 *A, *W;
    const float* bias;
    float* Yf = nullptr;
    __nv_bfloat16* Yh = nullptr;
    int N;
    if (yb < 3) {
        A = Aq; W = Wq_; bias = bq_; Yh = qh; N = NQ;
    } else if (yb < 6) {
        A = Ak; W = Wk_; bias = bk_; Yf = kf; N = NK; yb -= 3;
    } else {
        A = Av; W = Wv_; bias = bv_; Yf = vf; N = NK; yb -= 6;
    }
    if (m0 >= N) return;
    int c0 = yb * BN;
    int tid = threadIdx.x;
    int warp = tid >> 5, lane = tid & 31;
    int g = lane >> 2, lq = lane & 3;
    int wm = (warp >> 2) * 64;
    int wn = (warp & 3) * 32;
    float acc[4][4][4] = {};
    const __nv_bfloat16* Ab = A + (size_t)b * N * Cn;
    const __nv_bfloat16* Wp = W;
    const int K = Cn;

    GEMM_MAINLOOP(Ab, Wp, K)

#pragma unroll
    for (int mf = 0; mf < 4; mf++) {
#pragma unroll
        for (int nf = 0; nf < 4; nf++) {
            int co = c0 + wn + nf * 8 + lq * 2;
            float b0v = bias[co], b1v = bias[co + 1];
#pragma unroll
            for (int hr = 0; hr < 2; hr++) {
                int m = m0 + wm + mf * 16 + g + hr * 8;
                float v0 = acc[mf][nf][hr * 2 + 0] + b0v;
                float v1 = acc[mf][nf][hr * 2 + 1] + b1v;
                if (Yh) {
                    __nv_bfloat162 hv;
                    hv.x = __float2bfloat16_rn(v0);
                    hv.y = __float2bfloat16_rn(v1);
                    *(__nv_bfloat162*)(Yh + ((size_t)b * N + m) * Cn + co) = hv;
                } else {
                    *(float2*)(Yf + ((size_t)b * N + m) * Cn + co) = make_float2(v0, v1);
                }
            }
        }
    }
}

// ---------------- bf16 GEMM, row-major output (FFN1: silu + bf16) ----------------
__global__ __launch_bounds__(256) void gemm_bf16_row(
    const __nv_bfloat16* __restrict__ A, const __nv_bfloat16* __restrict__ W,
    const float* __restrict__ bias, __nv_bfloat16* __restrict__ Yh,
    int N, int K, int Cout) {
    extern __shared__ uint32_t smu[];
    uint32_t* As = smu;
    uint32_t* Bs = smu + NSTAGE * GW;
    int b = blockIdx.z;
    int m0 = blockIdx.x * BM;
    int c0 = blockIdx.y * BN;
    int tid = threadIdx.x;
    int warp = tid >> 5, lane = tid & 31;
    int g = lane >> 2, lq = lane & 3;
    int wm = (warp >> 2) * 64;
    int wn = (warp & 3) * 32;
    float acc[4][4][4] = {};
    const __nv_bfloat16* Ab = A + (size_t)b * N * K;
    const __nv_bfloat16* Wp = W;

    GEMM_MAINLOOP(Ab, Wp, K)

#pragma unroll
    for (int mf = 0; mf < 4; mf++) {
#pragma unroll
        for (int nf = 0; nf < 4; nf++) {
            int co = c0 + wn + nf * 8 + lq * 2;
            float b0v = bias[co], b1v = bias[co + 1];
#pragma unroll
            for (int hr = 0; hr < 2; hr++) {
                int m = m0 + wm + mf * 16 + g + hr * 8;
                float v0 = acc[mf][nf][hr * 2 + 0] + b0v;
                float v1 = acc[mf][nf][hr * 2 + 1] + b1v;
                v0 = v0 / (1.f + expf(-v0));
                v1 = v1 / (1.f + expf(-v1));
                __nv_bfloat162 hv;
                hv.x = __float2bfloat16_rn(v0);
                hv.y = __float2bfloat16_rn(v1);
                *(__nv_bfloat162*)(Yh + ((size_t)b * N + m) * Cout + co) = hv;
            }
        }
    }
}

// ---------------- bf16 GEMM, channel-major fused output (batch-strided W) ----------
// mode 0: out = resid1 + val*s1
// mode 1: out = resid1 + (resid2 + val*s1)*s2
__global__ __launch_bounds__(256) void gemm_bf16_cm(
    const __nv_bfloat16* __restrict__ A, const __nv_bfloat16* __restrict__ W,
    const float* __restrict__ bias,
    const float* __restrict__ resid1, const float* __restrict__ resid2,
    const float* __restrict__ scal1, const float* __restrict__ scal2,
    float* __restrict__ out, int N, int K, int Cout, int mode, int wstride) {
    extern __shared__ uint32_t smu[];
    uint32_t* As = smu;
    uint32_t* Bs = smu + NSTAGE * GW;
    int b = blockIdx.z;
    int m0 = blockIdx.x * BM;
    int c0 = blockIdx.y * BN;
    int tid = threadIdx.x;
    int warp = tid >> 5, lane = tid & 31;
    int g = lane >> 2, lq = lane & 3;
    int wm = (warp >> 2) * 64;
    int wn = (warp & 3) * 32;
    float acc[4][4][4] = {};
    const __nv_bfloat16* Ab = A + (size_t)b * N * K;
    const __nv_bfloat16* Wp = W + (size_t)b * wstride;

    GEMM_MAINLOOP(Ab, Wp, K)

#pragma unroll
    for (int nf = 0; nf < 4; nf++) {
#pragma unroll
        for (int cj = 0; cj < 2; cj++) {
            int co = c0 + wn + nf * 8 + lq * 2 + cj;
            float bv = bias[co];
            float s1 = scal1[co];
            float s2 = (mode == 1) ? scal2[co] : 0.f;
#pragma unroll
            for (int mf = 0; mf < 4; mf++) {
#pragma unroll
                for (int hr = 0; hr < 2; hr++) {
                    int m = m0 + wm + mf * 16 + g + hr * 8;
                    size_t idx = ((size_t)b * Cout + co) * (size_t)N + m;
                    float val = acc[mf][nf][hr * 2 + cj] + bv;
                    if (mode == 0)
                        out[idx] = resid1[idx] + val * s1;
                    else
                        out[idx] = resid1[idx] + (resid2[idx] + val * s1) * s2;
                }
            }
        }
    }
}

// ---------------- LayerNorm + elu+1 (in place) — for k; warp-shuffle reduction ------
__global__ void ln_elu_kernel(float* __restrict__ x, const float* __restrict__ w,
                              const float* __restrict__ bvec) {
    int r = blockIdx.x;
    float* p = x + (size_t)r * Cn;
    int t = threadIdx.x;  // 128
    float v0 = p[t], v1 = p[t + 128], v2 = p[t + 256];
    float s = v0 + v1 + v2;
    float s2 = v0 * v0 + v1 * v1 + v2 * v2;
#pragma unroll
    for (int o = 16; o; o >>= 1) {
        s += __shfl_down_sync(0xffffffffu, s, o);
        s2 += __shfl_down_sync(0xffffffffu, s2, o);
    }
    __shared__ float r1[4], r2[4];
    if ((t & 31) == 0) { r1[t >> 5] = s; r2[t >> 5] = s2; }
    __syncthreads();
    float S = r1[0] + r1[1] + r1[2] + r1[3];
    float S2 = r2[0] + r2[1] + r2[2] + r2[3];
    float mu = S * (1.f / (float)Cn);
    float var = S2 * (1.f / (float)Cn) - mu * mu;
    float inv = rsqrtf(var + LN_EPS);
    float y;
    y = (v0 - mu) * inv * w[t] + bvec[t];
    p[t] = (y > 0.f) ? y + 1.f : expf(y);
    y = (v1 - mu) * inv * w[t + 128] + bvec[t + 128];
    p[t + 128] = (y > 0.f) ? y + 1.f : expf(y);
    y = (v2 - mu) * inv * w[t + 256] + bvec[t + 256];
    p[t + 256] = (y > 0.f) ? y + 1.f : expf(y);
}

// ---------------- q: LN + elu+1 + den fold -> bf16 q' (warp-shuffle) ----------------
__global__ void ln_elu_q_den(const __nv_bfloat16* __restrict__ x,
                             const float* __restrict__ ksum,
                             const float* __restrict__ w, const float* __restrict__ bvec,
                             __nv_bfloat16* __restrict__ qp) {
    int r = blockIdx.x;
    int b = r / NQ;
    const __nv_bfloat16* p = x + (size_t)r * Cn;
    int t = threadIdx.x;  // 128
    float v0 = __bfloat162float(p[t]);
    float v1 = __bfloat162float(p[t + 128]);
    float v2 = __bfloat162float(p[t + 256]);
    float s = v0 + v1 + v2;
    float s2 = v0 * v0 + v1 * v1 + v2 * v2;
#pragma unroll
    for (int o = 16; o; o >>= 1) {
        s += __shfl_down_sync(0xffffffffu, s, o);
        s2 += __shfl_down_sync(0xffffffffu, s2, o);
    }
    __shared__ float r1[4], r2[4];
    __shared__ float prod[Cn];
    __shared__ float den[8];
    if ((t & 31) == 0) { r1[t >> 5] = s; r2[t >> 5] = s2; }
    __syncthreads();
    float S = r1[0] + r1[1] + r1[2] + r1[3];
    float S2 = r2[0] + r2[1] + r2[2] + r2[3];
    float mu = S * (1.f / (float)Cn);
    float var = S2 * (1.f / (float)Cn) - mu * mu;
    float inv = rsqrtf(var + LN_EPS);
    float y0 = (v0 - mu) * inv * w[t] + bvec[t];
    y0 = (y0 > 0.f) ? y0 + 1.f : expf(y0);
    float y1 = (v1 - mu) * inv * w[t + 128] + bvec[t + 128];
    y1 = (y1 > 0.f) ? y1 + 1.f : expf(y1);
    float y2 = (v2 - mu) * inv * w[t + 256] + bvec[t + 256];
    y2 = (y2 > 0.f) ? y2 + 1.f : expf(y2);
    const float* ks = ksum + (size_t)b * Cn;  // [h][d] contiguous == per-channel
    prod[t] = y0 * ks[t];
    prod[t + 128] = y1 * ks[t + 128];
    prod[t + 256] = y2 * ks[t + 256];
    __syncthreads();
    // head h reduced by 16 lanes: each sums 3 channels, then shfl width-16
    int h = t >> 4, i = t & 15;
    float pd = prod[h * Dn + i * 3] + prod[h * Dn + i * 3 + 1] + prod[h * Dn + i * 3 + 2];
#pragma unroll
    for (int o = 8; o; o >>= 1) pd += __shfl_down_sync(0xffffffffu, pd, o, 16);
    if (i == 0) den[h] = pd + 1e-8f;
    __syncthreads();
    __nv_bfloat16* o = qp + (size_t)r * Cn;
    o[t] = __float2bfloat16_rn(y0 / den[t / Dn]);
    o[t + 128] = __float2bfloat16_rn(y1 / den[(t + 128) / Dn]);
    o[t + 256] = __float2bfloat16_rn(y2 / den[(t + 256) / Dn]);
}

// ---------------- zero kv/ksum ----------------
__global__ void zero_kv(float* __restrict__ kv, float* __restrict__ ksum) {
    int i = blockIdx.x * 256 + threadIdx.x;
    if (i < Bn * Hn * Dn * Dn) kv[i] = 0.f;
    if (i < Bn * Hn * Dn) ksum[i] = 0.f;
}

// ---------------- kv_sum + k_sum ----------------
__global__ void kv_v2(const float* __restrict__ k, const float* __restrict__ v,
                      float* __restrict__ kv, float* __restrict__ ksum) {
    int bh = blockIdx.x;
    int chunk = blockIdx.y;
    int b = bh >> 3, h = bh & 7;
    __shared__ float ks[32][49];
    __shared__ float vs[32][49];
    int tid = threadIdx.x;  // 256
    int di = tid >> 4, ei = tid & 15;
    int d0 = di * 3, e0 = ei * 3;
    float acc[3][3] = {};
    float ksa[3] = {};
    int nbeg = chunk * (NK / 4);
    for (int n0 = nbeg; n0 < nbeg + NK / 4; n0 += 32) {
        for (int i = tid; i < 32 * Dn; i += 256) {
            int nn = i / Dn, dd = i % Dn;
            size_t base = ((size_t)b * NK + n0 + nn) * Cn + h * Dn + dd;
            ks[nn][dd] = k[base];
            vs[nn][dd] = v[base];
        }
        __syncthreads();
#pragma unroll 4
        for (int nn = 0; nn < 32; nn++) {
            float kd0 = ks[nn][d0], kd1 = ks[nn][d0 + 1], kd2 = ks[nn][d0 + 2];
            float ve0 = vs[nn][e0], ve1 = vs[nn][e0 + 1], ve2 = vs[nn][e0 + 2];
            acc[0][0] += kd0 * ve0; acc[0][1] += kd0 * ve1; acc[0][2] += kd0 * ve2;
            acc[1][0] += kd1 * ve0; acc[1][1] += kd1 * ve1; acc[1][2] += kd1 * ve2;
            acc[2][0] += kd2 * ve0; acc[2][1] += kd2 * ve1; acc[2][2] += kd2 * ve2;
            if (ei == 0) { ksa[0] += kd0; ksa[1] += kd1; ksa[2] += kd2; }
        }
        __syncthreads();
    }
    float* kvb = kv + (size_t)bh * Dn * Dn;
#pragma unroll
    for (int i = 0; i < 3; i++)
#pragma unroll
        for (int j = 0; j < 3; j++)
            atomicAdd(&kvb[(d0 + i) * Dn + e0 + j], acc[i][j]);
    if (ei == 0)
#pragma unroll
        for (int i = 0; i < 3; i++) atomicAdd(&ksum[bh * Dn + d0 + i], ksa[i]);
}

// ---------------- make_M ----------------
__global__ void make_M(const float* __restrict__ kv, const float* __restrict__ Wo,
                       __nv_bfloat16* __restrict__ Wt) {
    int cb = blockIdx.x;
    int h = blockIdx.y;
    int b = blockIdx.z;
    __shared__ float kvs[Dn][49];
    __shared__ float wos[Dn][132];
    int tid = threadIdx.x;  // 256
    for (int i = tid; i < Dn * Dn; i += 256)
        kvs[i / Dn][i % Dn] = kv[((size_t)b * Hn + h) * Dn * Dn + i];
    for (int i = tid; i < 128 * Dn; i += 256) {
        int co = i / Dn, e = i % Dn;
        wos[e][co] = Wo[(size_t)(cb * 128 + co) * Cn + h * Dn + e];
    }
    __syncthreads();
    int cog = tid & 15, dg = tid >> 4;
    int co0 = cog * 8, d0 = dg * 3;
    float acc[8][3] = {};
#pragma unroll 4
    for (int e = 0; e < Dn; e++) {
        float kd0 = kvs[d0][e], kd1 = kvs[d0 + 1][e], kd2 = kvs[d0 + 2][e];
#pragma unroll
        for (int i = 0; i < 8; i++) {
            float wv = wos[e][co0 + i];
            acc[i][0] += wv * kd0;
            acc[i][1] += wv * kd1;
            acc[i][2] += wv * kd2;
        }
    }
#pragma unroll
    for (int i = 0; i < 8; i++)
#pragma unroll
        for (int j = 0; j < 3; j++)
            Wt[((size_t)b * Cn + cb * 128 + co0 + i) * Cn + h * Dn + d0 + j] =
                __float2bfloat16_rn(acc[i][j]);
}

// ---------------- host launch ----------------
extern "C" void kernel_launch(void* const* d_in, const int* in_sizes, int n_in,
                              void* d_out, int out_size) {
    const float* query = (const float*)d_in[0];
    const float* key = (const float*)d_in[1];
    const float* value = (const float*)d_in[2];
    const float* ada_gamma = (const float*)d_in[3];
    const float* ada_beta = (const float*)d_in[4];
    const float* Wq = (const float*)d_in[5];
    const float* bq = (const float*)d_in[6];
    const float* Wk = (const float*)d_in[7];
    const float* bk = (const float*)d_in[8];
    const float* Wv = (const float*)d_in[9];
    const float* bv = (const float*)d_in[10];
    const float* Wo = (const float*)d_in[11];
    const float* bo = (const float*)d_in[12];
    const float* lnq_w = (const float*)d_in[13];
    const float* lnq_b = (const float*)d_in[14];
    const float* lnk_w = (const float*)d_in[15];
    const float* lnk_b = (const float*)d_in[16];
    const float* attn_scalar = (const float*)d_in[17];
    const float* ffn_gamma = (const float*)d_in[18];
    const float* ffn_beta = (const float*)d_in[19];
    const float* W1 = (const float*)d_in[20];
    const float* b1 = (const float*)d_in[21];
    const float* W2 = (const float*)d_in[22];
    const float* b2 = (const float*)d_in[23];
    const float* ffn_scalar = (const float*)d_in[24];
    const float* final_scalar = (const float*)d_in[25];
    float* out = (float*)d_out;

    float *k, *v, *working, *kv, *ksum, *gx, *meanc;
    __nv_bfloat16 *ada_b, *key_b, *val_b, *qh_b, *qp_b, *nrm_b, *h_b, *wts, *M_b;
    cudaGetSymbolAddress((void**)&k, g_k);
    cudaGetSymbolAddress((void**)&v, g_v);
    cudaGetSymbolAddress((void**)&working, g_working);
    cudaGetSymbolAddress((void**)&kv, g_kv);
    cudaGetSymbolAddress((void**)&ksum, g_ksum);
    cudaGetSymbolAddress((void**)&gx, g_gx);
    cudaGetSymbolAddress((void**)&meanc, g_meanc);
    cudaGetSymbolAddress((void**)&ada_b, b_ada);
    cudaGetSymbolAddress((void**)&key_b, b_key);
    cudaGetSymbolAddress((void**)&val_b, b_val);
    cudaGetSymbolAddress((void**)&qh_b, b_qh);
    cudaGetSymbolAddress((void**)&qp_b, b_qp);
    cudaGetSymbolAddress((void**)&nrm_b, b_nrm);
    cudaGetSymbolAddress((void**)&h_b, b_h);
    cudaGetSymbolAddress((void**)&wts, b_wts);
    cudaGetSymbolAddress((void**)&M_b, b_M);

    __nv_bfloat16* wq_b = wts;
    __nv_bfloat16* wk_b = wts + CC;
    __nv_bfloat16* wv_b = wts + 2 * CC;
    __nv_bfloat16* w1_b = wts + 4 * CC;
    __nv_bfloat16* w2_b = wts + 4 * CC + FC;

    cudaFuncSetAttribute(gemm_qkv, cudaFuncAttributeMaxDynamicSharedMemorySize, GEMM_SMEM);
    cudaFuncSetAttribute(gemm_bf16_row, cudaFuncAttributeMaxDynamicSharedMemorySize, GEMM_SMEM);
    cudaFuncSetAttribute(gemm_bf16_cm, cudaFuncAttributeMaxDynamicSharedMemorySize, GEMM_SMEM);

    // 0) weight conversions (one launch)
    conv_f2bf_all<<<1728, 256>>>((const float4*)Wq, (const float4*)Wk, (const float4*)Wv,
                                 (const float4*)Wo, (const float4*)W1, (const float4*)W2,
                                 (__nv_bfloat162*)wts);

    // 0b) key+value transpose-convert, one launch
    transconv_kv<<<dim3(Cn / 64, NK / 32, 2 * Bn), 256>>>(key, key_b, value, val_b);

    // 1) GRN on query -> ada (bf16 rows, fused transpose)
    grn_reduce_kernel<<<Bn * Cn, 256>>>(query, gx);
    grn_mean_kernel<<<Bn, 128>>>(gx, meanc);
    transconv_kernel<<<dim3(Cn / 64, NQ / 32, Bn), 256>>>(query, ada_b, gx, meanc,
                                                          ada_gamma, ada_beta, NQ, 1);

    // 2) Q + K + V projections in ONE launch
    gemm_qkv<<<dim3(NQ / BM, 9, Bn), 256, GEMM_SMEM>>>(ada_b, wq_b, bq, qh_b,
                                                       key_b, wk_b, bk, k,
                                                       val_b, wv_b, bv, v);

    // 3) LN + elu+1 on k (in place, fp32)
    ln_elu_kernel<<<Bn * NK, 128>>>(k, lnk_w, lnk_b);

    // 4) zero kv/ksum, then kv_sum/k_sum
    zero_kv<<<(Bn * Hn * Dn * Dn + 255) / 256, 256>>>(kv, ksum);
    kv_v2<<<dim3(Bn * Hn, 4), 256>>>(k, v, kv, ksum);

    // 5a) q: LN + elu+1 + fold den -> bf16 q'
    ln_elu_q_den<<<Bn * NQ, 128>>>(qh_b, ksum, lnq_w, lnq_b, qp_b);

    // 5b) fold kv into Wo: per-batch effective weight M
    make_M<<<dim3(Cn / 128, Hn, Bn), 256>>>(kv, Wo, M_b);

    // 6) (attention + Wo) as ONE GEMM
    gemm_bf16_cm<<<dim3(NQ / BM, Cn / BN, Bn), 256, GEMM_SMEM>>>(
        qp_b, M_b, bo, query, nullptr, attn_scalar, nullptr, working,
        NQ, Cn, Cn, 0, Cn * Cn);

    // 7) GRN on working -> normed (bf16 rows, fused transpose)
    grn_reduce_kernel<<<Bn * Cn, 256>>>(working, gx);
    grn_mean_kernel<<<Bn, 128>>>(gx, meanc);
    transconv_kernel<<<dim3(Cn / 64, NQ / 32, Bn), 256>>>(working, nrm_b, gx, meanc,
                                                          ffn_gamma, ffn_beta, NQ, 1);

    // 8) FFN1 (+silu) -> h (bf16 rows)
    gemm_bf16_row<<<dim3(NQ / BM, Fn / BN, Bn), 256, GEMM_SMEM>>>(nrm_b, w1_b, b1, h_b,
                                                                  NQ, Cn, Fn);

    // 9) FFN2 + ffn residual + final residual -> out (fp32, channel-major)
    gemm_bf16_cm<<<dim3(NQ / BM, Cn / BN, Bn), 256, GEMM_SMEM>>>(
        h_b, w2_b, b2, query, working, ffn_scalar, final_scalar, out,
        NQ, Fn, Cn, 1, 0);
}

// round 15
// speedup vs baseline: 1.4097x; 1.0110x over previous
#include <cuda_runtime.h>
#include <cuda_bf16.h>
#include <math.h>
#include <stdint.h>

// Problem constants
#define Bn 8
#define Cn 384
#define NQ 4096
#define NK 1024
#define Hn 8
#define Dn 48
#define Fn 1536
#define GRN_EPS 1e-6f
#define LN_EPS 1e-5f

// GEMM tiling (bf16): 128x128 CTA tile, 64x32 warp tiles (validated config)
#define BM 128
#define BN 128
#define KSB 32
#define KW 16
#define NSTAGE 3
#define GW (BM * KW)
#define GEMM_SMEM (NSTAGE * 2 * GW * 4)  // 49152 bytes

#define CC (Cn * Cn)
#define FC (Fn * Cn)

// ---------------- scratch (device globals; no allocations) ----------------
__device__ float g_k[(size_t)Bn * NK * Cn];
__device__ float g_v[(size_t)Bn * NK * Cn];
__device__ float g_working[(size_t)Bn * Cn * NQ];
__device__ float g_kv[(size_t)Bn * Hn * Dn * Dn];
__device__ float g_ksum[(size_t)Bn * Hn * Dn];
__device__ float g_gx[(size_t)Bn * Cn];
__device__ float g_msum[2 * Bn];  // per-pass, per-batch sum of gx

__device__ __nv_bfloat16 b_ada[(size_t)Bn * NQ * Cn];
__device__ __nv_bfloat16 b_key[(size_t)Bn * NK * Cn];
__device__ __nv_bfloat16 b_val[(size_t)Bn * NK * Cn];
__device__ __nv_bfloat16 b_qh[(size_t)Bn * NQ * Cn];
__device__ __nv_bfloat16 b_qp[(size_t)Bn * NQ * Cn];
__device__ __nv_bfloat16 b_nrm[(size_t)Bn * NQ * Cn];
__device__ __nv_bfloat16 b_h[(size_t)Bn * NQ * Fn];
__device__ __nv_bfloat16 b_wts[4 * CC + 2 * FC];
__device__ __nv_bfloat16 b_M[(size_t)Bn * Cn * Cn];

// ---------------- helpers ----------------
__device__ __forceinline__ void cp_async16(void* smem_dst, const void* gsrc) {
    uint32_t s = (uint32_t)__cvta_generic_to_shared(smem_dst);
    asm volatile("cp.async.cg.shared.global [%0], [%1], 16;" ::"r"(s), "l"(gsrc));
}
__device__ __forceinline__ void cp_commit() { asm volatile("cp.async.commit_group;"); }
__device__ __forceinline__ void cp_wait1() { asm volatile("cp.async.wait_group 1;"); }
__device__ __forceinline__ void cp_wait0() { asm volatile("cp.async.wait_group 0;"); }

__device__ __forceinline__ void mma16(float* c, uint32_t a0, uint32_t a1, uint32_t a2,
                                      uint32_t a3, uint32_t b0, uint32_t b1) {
    asm volatile(
        "mma.sync.aligned.m16n8k16.row.col.f32.bf16.bf16.f32 "
        "{%0,%1,%2,%3},{%4,%5,%6,%7},{%8,%9},{%0,%1,%2,%3};"
        : "+f"(c[0]), "+f"(c[1]), "+f"(c[2]), "+f"(c[3])
        : "r"(a0), "r"(a1), "r"(a2), "r"(a3), "r"(b0), "r"(b1));
}

__device__ __forceinline__ void ldsm4(uint32_t& r0, uint32_t& r1, uint32_t& r2, uint32_t& r3,
                                      uint32_t saddr) {
    asm volatile("ldmatrix.sync.aligned.m8n8.x4.shared.b16 {%0,%1,%2,%3}, [%4];"
                 : "=r"(r0), "=r"(r1), "=r"(r2), "=r"(r3)
                 : "r"(saddr));
}

// ---------------- merged weight convert (+ zero msum) ----------------
__global__ void conv_f2bf_all(const float4* __restrict__ wq, const float4* __restrict__ wk,
                              const float4* __restrict__ wv, const float4* __restrict__ wo,
                              const float4* __restrict__ w1, const float4* __restrict__ w2,
                              __nv_bfloat162* __restrict__ dst, float* __restrict__ msum) {
    if (blockIdx.x == 0 && threadIdx.x < 2 * Bn) msum[threadIdx.x] = 0.f;
    const int C4 = CC / 4, F4 = FC / 4;
    int total = 4 * C4 + 2 * F4;
    for (int i = blockIdx.x * 256 + threadIdx.x; i < total; i += gridDim.x * 256) {
        const float4* src;
        int off;
        if (i < 4 * C4) {
            int seg = i / C4;
            off = i - seg * C4;
            src = (seg == 0) ? wq : (seg == 1) ? wk : (seg == 2) ? wv : wo;
        } else if (i < 4 * C4 + F4) {
            src = w1;
            off = i - 4 * C4;
        } else {
            src = w2;
            off = i - 4 * C4 - F4;
        }
        float4 v = src[off];
        __nv_bfloat162 a, b;
        a.x = __float2bfloat16_rn(v.x); a.y = __float2bfloat16_rn(v.y);
        b.x = __float2bfloat16_rn(v.z); b.y = __float2bfloat16_rn(v.w);
        dst[2 * i] = a;
        dst[2 * i + 1] = b;
    }
}

// ---------------- GRN reduce: gx[bc]=sqrt(sum x^2); atomic msum[b] += sqrt --------
__global__ void grn_reduce_kernel(const float* __restrict__ x, float* __restrict__ gx,
                                  float* __restrict__ msum) {
    int bc = blockIdx.x;
    const float4* p = (const float4*)(x + (size_t)bc * NQ);
    int t = threadIdx.x;  // 256; 1024 float4 total
    float4 a = p[t], b = p[t + 256], c = p[t + 512], d = p[t + 768];
    float s = a.x * a.x + a.y * a.y + a.z * a.z + a.w * a.w;
    s += b.x * b.x + b.y * b.y + b.z * b.z + b.w * b.w;
    s += c.x * c.x + c.y * c.y + c.z * c.z + c.w * c.w;
    s += d.x * d.x + d.y * d.y + d.z * d.z + d.w * d.w;
#pragma unroll
    for (int o = 16; o; o >>= 1) s += __shfl_down_sync(0xffffffffu, s, o);
    __shared__ float r[8];
    if ((t & 31) == 0) r[t >> 5] = s;
    __syncthreads();
    if (t == 0) {
        float S = sqrtf(r[0] + r[1] + r[2] + r[3] + r[4] + r[5] + r[6] + r[7]);
        gx[bc] = S;
        atomicAdd(&msum[bc / Cn], S);
    }
}

// ---------------- transpose + (optional GRN) + convert to bf16 rows ----------------
__global__ void transconv_kernel(const float* __restrict__ x, __nv_bfloat16* __restrict__ out,
                                 const float* __restrict__ gx, const float* __restrict__ msum,
                                 const float* __restrict__ gamma, const float* __restrict__ beta,
                                 int N, int grn) {
    int b = blockIdx.z;
    int c0 = blockIdx.x * 64;
    int n0 = blockIdx.y * 32;
    __shared__ float t[64][33];
    int tid = threadIdx.x;
    int j = tid & 31, i0 = tid >> 5;
#pragma unroll
    for (int p = 0; p < 8; p++) {
        int i = i0 + p * 8;
        t[i][j] = x[((size_t)b * Cn + c0 + i) * N + n0 + j];
    }
    __syncthreads();
    int cp = tid & 31;
    int nn0 = tid >> 5;
    int c = c0 + 2 * cp;
    float sc0 = 1.f, bt0 = 0.f, sc1 = 1.f, bt1 = 0.f;
    if (grn) {
        float meanc = msum[b] * (1.f / (float)Cn) + GRN_EPS;
        sc0 = 1.f + (1.f + gamma[c]) * gx[b * Cn + c] / meanc;
        bt0 = beta[c];
        sc1 = 1.f + (1.f + gamma[c + 1]) * gx[b * Cn + c + 1] / meanc;
        bt1 = beta[c + 1];
    }
#pragma unroll
    for (int p = 0; p < 4; p++) {
        int nn = nn0 + p * 8;
        float v0 = t[2 * cp][nn] * sc0 + bt0;
        float v1 = t[2 * cp + 1][nn] * sc1 + bt1;
        __nv_bfloat162 hv;
        hv.x = __float2bfloat16_rn(v0);
        hv.y = __float2bfloat16_rn(v1);
        *(__nv_bfloat162*)(out + ((size_t)b * N + n0 + nn) * Cn + c) = hv;
    }
}

// merged key+value transpose-convert (no GRN), one launch
__global__ void transconv_kv(const float* __restrict__ xk, __nv_bfloat16* __restrict__ ok,
                             const float* __restrict__ xv, __nv_bfloat16* __restrict__ ov) {
    int z = blockIdx.z;
    const float* x = (z < Bn) ? xk : xv;
    __nv_bfloat16* out = (z < Bn) ? ok : ov;
    int b = (z < Bn) ? z : z - Bn;
    int c0 = blockIdx.x * 64;
    int n0 = blockIdx.y * 32;
    __shared__ float t[64][33];
    int tid = threadIdx.x;
    int j = tid & 31, i0 = tid >> 5;
#pragma unroll
    for (int p = 0; p < 8; p++) {
        int i = i0 + p * 8;
        t[i][j] = x[((size_t)b * Cn + c0 + i) * NK + n0 + j];
    }
    __syncthreads();
    int cp = tid & 31;
    int nn0 = tid >> 5;
    int c = c0 + 2 * cp;
#pragma unroll
    for (int p = 0; p < 4; p++) {
        int nn = nn0 + p * 8;
        __nv_bfloat162 hv;
        hv.x = __float2bfloat16_rn(t[2 * cp][nn]);
        hv.y = __float2bfloat16_rn(t[2 * cp + 1][nn]);
        *(__nv_bfloat162*)(out + ((size_t)b * NK + n0 + nn) * Cn + c) = hv;
    }
}

// ---------------- shared GEMM mainloop (128x128 tile, ldmatrix fragments) --------------
#define GEMM_MAINLOOP(Ab, Wp, K)                                                          \
    const uint32_t a_base = (uint32_t)__cvta_generic_to_shared(As);                       \
    const uint32_t b_base = (uint32_t)__cvta_generic_to_shared(Bs);                       \
    int lr = (lane & 7) + ((lane >> 3) & 1) * 8;                                          \
    int lca = lane >> 4;                                                                  \
    int lrb = (lane & 7) + (lane >> 4) * 8;                                               \
    int lcb = (lane >> 3) & 1;                                                            \
    int nslab = (K) / KSB;                                                                \
    LOAD_BF(0, 0, Ab, Wp, K);                                                             \
    LOAD_BF(1, 1, Ab, Wp, K);                                                             \
    for (int s = 0; s < nslab; s++) {                                                     \
        int stg = s % NSTAGE;                                                             \
        if (s + 1 < nslab) cp_wait1(); else cp_wait0();                                   \
        __syncthreads();                                                                  \
        if (s + 2 < nslab) LOAD_BF(s + 2, (s + 2) % NSTAGE, Ab, Wp, K);                   \
        uint32_t Ast = a_base + stg * GW * 4;                                             \
        uint32_t Bst = b_base + stg * GW * 4;                                             \
        _Pragma("unroll") for (int kb = 0; kb < 2; kb++) {                                \
            uint32_t af[4][4], bfr[4][2];                                                 \
            _Pragma("unroll") for (int mf = 0; mf < 4; mf++) {                            \
                int row = wm + mf * 16 + lr;                                              \
                int ch = 2 * kb + lca;                                                    \
                ldsm4(af[mf][0], af[mf][1], af[mf][2], af[mf][3],                         \
                      Ast + row * 64 + ((ch ^ ((row >> 1) & 3)) << 4));                   \
            }                                                                             \
            _Pragma("unroll") for (int p = 0; p < 2; p++) {                               \
                int row = wn + p * 16 + lrb;                                              \
                int ch = 2 * kb + lcb;                                                    \
                ldsm4(bfr[2 * p][0], bfr[2 * p][1], bfr[2 * p + 1][0], bfr[2 * p + 1][1], \
                      Bst + row * 64 + ((ch ^ ((row >> 1) & 3)) << 4));                   \
            }                                                                             \
            _Pragma("unroll") for (int mf = 0; mf < 4; mf++)                              \
                _Pragma("unroll") for (int nf = 0; nf < 4; nf++)                          \
                    mma16(acc[mf][nf], af[mf][0], af[mf][1], af[mf][2], af[mf][3],        \
                          bfr[nf][0], bfr[nf][1]);                                        \
        }                                                                                 \
    }

#define LOAD_BF(slab, stg, Abp, Wpp, Kk)                                                \
    {                                                                                   \
        int kk0 = (slab)*KSB;                                                           \
        uint32_t* Ad = As + (size_t)(stg)*GW;                                           \
        uint32_t* Bd = Bs + (size_t)(stg)*GW;                                           \
        _Pragma("unroll") for (int p = 0; p < 2; p++) {                                 \
            int c = tid + p * 256;                                                      \
            int r = c >> 2, ch = c & 3;                                                 \
            int sw = ((ch ^ ((r >> 1) & 3)) << 2);                                      \
            cp_async16(Ad + r * KW + sw, (Abp) + (size_t)(m0 + r) * (Kk) + kk0 + ch * 8); \
            cp_async16(Bd + r * KW + sw, (Wpp) + (size_t)(c0 + r) * (Kk) + kk0 + ch * 8); \
        }                                                                               \
        cp_commit();                                                                    \
    }

// ---------------- Q/K/V projections in ONE launch ----------------
// yb<3: Q-set (bf16 out, N=NQ); 3..5: K-set (fp32, N=NK); 6..8: V-set (fp32, N=NK)
__global__ __launch_bounds__(256) void gemm_qkv(
    const __nv_bfloat16* __restrict__ Aq, const __nv_bfloat16* __restrict__ Wq_,
    const float* __restrict__ bq_, __nv_bfloat16* __restrict__ qh,
    const __nv_bfloat16* __restrict__ Ak, const __nv_bfloat16* __restrict__ Wk_,
    const float* __restrict__ bk_, float* __restrict__ kf,
    const __nv_bfloat16* __restrict__ Av, const __nv_bfloat16* __restrict__ Wv_,
    const float* __restrict__ bv_, float* __restrict__ vf) {
    extern __shared__ uint32_t smu[];
    uint32_t* As = smu;
    uint32_t* Bs = smu + NSTAGE * GW;
    int b = blockIdx.z;
    int m0 = blockIdx.x * BM;
    int yb = blockIdx.y;
    const __nv_bfloat16 *A, *W;
    const float* bias;
    float* Yf = nullptr;
    __nv_bfloat16* Yh = nullptr;
    int N;
    if (yb < 3) {
        A = Aq; W = Wq_; bias = bq_; Yh = qh; N = NQ;
    } else if (yb < 6) {
        A = Ak; W = Wk_; bias = bk_; Yf = kf; N = NK; yb -= 3;
    } else {
        A = Av; W = Wv_; bias = bv_; Yf = vf; N = NK; yb -= 6;
    }
    if (m0 >= N) return;
    int c0 = yb * BN;
    int tid = threadIdx.x;
    int warp = tid >> 5, lane = tid & 31;
    int g = lane >> 2, lq = lane & 3;
    int wm = (warp >> 2) * 64;
    int wn = (warp & 3) * 32;
    float acc[4][4][4] = {};
    const __nv_bfloat16* Ab = A + (size_t)b * N * Cn;
    const __nv_bfloat16* Wp = W;
    const int K = Cn;

    GEMM_MAINLOOP(Ab, Wp, K)

#pragma unroll
    for (int mf = 0; mf < 4; mf++) {
#pragma unroll
        for (int nf = 0; nf < 4; nf++) {
            int co = c0 + wn + nf * 8 + lq * 2;
            float b0v = bias[co], b1v = bias[co + 1];
#pragma unroll
            for (int hr = 0; hr < 2; hr++) {
                int m = m0 + wm + mf * 16 + g + hr * 8;
                float v0 = acc[mf][nf][hr * 2 + 0] + b0v;
                float v1 = acc[mf][nf][hr * 2 + 1] + b1v;
                if (Yh) {
                    __nv_bfloat162 hv;
                    hv.x = __float2bfloat16_rn(v0);
                    hv.y = __float2bfloat16_rn(v1);
                    *(__nv_bfloat162*)(Yh + ((size_t)b * N + m) * Cn + co) = hv;
                } else {
                    *(float2*)(Yf + ((size_t)b * N + m) * Cn + co) = make_float2(v0, v1);
                }
            }
        }
    }
}

// ---------------- bf16 GEMM, row-major output (FFN1: silu + bf16) ----------------
__global__ __launch_bounds__(256) void gemm_bf16_row(
    const __nv_bfloat16* __restrict__ A, const __nv_bfloat16* __restrict__ W,
    const float* __restrict__ bias, __nv_bfloat16* __restrict__ Yh,
    int N, int K, int Cout) {
    extern __shared__ uint32_t smu[];
    uint32_t* As = smu;
    uint32_t* Bs = smu + NSTAGE * GW;
    int b = blockIdx.z;
    int m0 = blockIdx.x * BM;
    int c0 = blockIdx.y * BN;
    int tid = threadIdx.x;
    int warp = tid >> 5, lane = tid & 31;
    int g = lane >> 2, lq = lane & 3;
    int wm = (warp >> 2) * 64;
    int wn = (warp & 3) * 32;
    float acc[4][4][4] = {};
    const __nv_bfloat16* Ab = A + (size_t)b * N * K;
    const __nv_bfloat16* Wp = W;

    GEMM_MAINLOOP(Ab, Wp, K)

#pragma unroll
    for (int mf = 0; mf < 4; mf++) {
#pragma unroll
        for (int nf = 0; nf < 4; nf++) {
            int co = c0 + wn + nf * 8 + lq * 2;
            float b0v = bias[co], b1v = bias[co + 1];
#pragma unroll
            for (int hr = 0; hr < 2; hr++) {
                int m = m0 + wm + mf * 16 + g + hr * 8;
                float v0 = acc[mf][nf][hr * 2 + 0] + b0v;
                float v1 = acc[mf][nf][hr * 2 + 1] + b1v;
                v0 = v0 / (1.f + expf(-v0));
                v1 = v1 / (1.f + expf(-v1));
                __nv_bfloat162 hv;
                hv.x = __float2bfloat16_rn(v0);
                hv.y = __float2bfloat16_rn(v1);
                *(__nv_bfloat162*)(Yh + ((size_t)b * N + m) * Cout + co) = hv;
            }
        }
    }
}

// ---------------- bf16 GEMM, channel-major fused output (batch-strided W) ----------
// mode 0: out = resid1 + val*s1
// mode 1: out = resid1 + (resid2 + val*s1)*s2
__global__ __launch_bounds__(256) void gemm_bf16_cm(
    const __nv_bfloat16* __restrict__ A, const __nv_bfloat16* __restrict__ W,
    const float* __restrict__ bias,
    const float* __restrict__ resid1, const float* __restrict__ resid2,
    const float* __restrict__ scal1, const float* __restrict__ scal2,
    float* __restrict__ out, int N, int K, int Cout, int mode, int wstride) {
    extern __shared__ uint32_t smu[];
    uint32_t* As = smu;
    uint32_t* Bs = smu + NSTAGE * GW;
    int b = blockIdx.z;
    int m0 = blockIdx.x * BM;
    int c0 = blockIdx.y * BN;
    int tid = threadIdx.x;
    int warp = tid >> 5, lane = tid & 31;
    int g = lane >> 2, lq = lane & 3;
    int wm = (warp >> 2) * 64;
    int wn = (warp & 3) * 32;
    float acc[4][4][4] = {};
    const __nv_bfloat16* Ab = A + (size_t)b * N * K;
    const __nv_bfloat16* Wp = W + (size_t)b * wstride;

    GEMM_MAINLOOP(Ab, Wp, K)

#pragma unroll
    for (int nf = 0; nf < 4; nf++) {
#pragma unroll
        for (int cj = 0; cj < 2; cj++) {
            int co = c0 + wn + nf * 8 + lq * 2 + cj;
            float bv = bias[co];
            float s1 = scal1[co];
            float s2 = (mode == 1) ? scal2[co] : 0.f;
#pragma unroll
            for (int mf = 0; mf < 4; mf++) {
#pragma unroll
                for (int hr = 0; hr < 2; hr++) {
                    int m = m0 + wm + mf * 16 + g + hr * 8;
                    size_t idx = ((size_t)b * Cout + co) * (size_t)N + m;
                    float val = acc[mf][nf][hr * 2 + cj] + bv;
                    if (mode == 0)
                        out[idx] = resid1[idx] + val * s1;
                    else
                        out[idx] = resid1[idx] + (resid2[idx] + val * s1) * s2;
                }
            }
        }
    }
}

// ---------------- LayerNorm + elu+1 on k (in place) + zero kv/ksum ----------------
__global__ void ln_elu_kernel(float* __restrict__ x, const float* __restrict__ w,
                              const float* __restrict__ bvec, float* __restrict__ kv,
                              float* __restrict__ ksum) {
    int r = blockIdx.x;
    int t = threadIdx.x;  // 128
    // fused zeroing of kv (18432) + ksum (384) across the first blocks
    int gidx = r * 128 + t;
    if (gidx < Bn * Hn * Dn * Dn) kv[gidx] = 0.f;
    if (gidx < Bn * Hn * Dn) ksum[gidx] = 0.f;
    float* p = x + (size_t)r * Cn;
    float v0 = p[t], v1 = p[t + 128], v2 = p[t + 256];
    float s = v0 + v1 + v2;
    float s2 = v0 * v0 + v1 * v1 + v2 * v2;
#pragma unroll
    for (int o = 16; o; o >>= 1) {
        s += __shfl_down_sync(0xffffffffu, s, o);
        s2 += __shfl_down_sync(0xffffffffu, s2, o);
    }
    __shared__ float r1[4], r2[4];
    if ((t & 31) == 0) { r1[t >> 5] = s; r2[t >> 5] = s2; }
    __syncthreads();
    float S = r1[0] + r1[1] + r1[2] + r1[3];
    float S2 = r2[0] + r2[1] + r2[2] + r2[3];
    float mu = S * (1.f / (float)Cn);
    float var = S2 * (1.f / (float)Cn) - mu * mu;
    float inv = rsqrtf(var + LN_EPS);
    float y;
    y = (v0 - mu) * inv * w[t] + bvec[t];
    p[t] = (y > 0.f) ? y + 1.f : expf(y);
    y = (v1 - mu) * inv * w[t + 128] + bvec[t + 128];
    p[t + 128] = (y > 0.f) ? y + 1.f : expf(y);
    y = (v2 - mu) * inv * w[t + 256] + bvec[t + 256];
    p[t + 256] = (y > 0.f) ? y + 1.f : expf(y);
}

// ---------------- q: LN + elu+1 + den fold -> bf16 q' (warp-shuffle) ----------------
__global__ void ln_elu_q_den(const __nv_bfloat16* __restrict__ x,
                             const float* __restrict__ ksum,
                             const float* __restrict__ w, const float* __restrict__ bvec,
                             __nv_bfloat16* __restrict__ qp) {
    int r = blockIdx.x;
    int b = r / NQ;
    const __nv_bfloat16* p = x + (size_t)r * Cn;
    int t = threadIdx.x;  // 128
    float v0 = __bfloat162float(p[t]);
    float v1 = __bfloat162float(p[t + 128]);
    float v2 = __bfloat162float(p[t + 256]);
    float s = v0 + v1 + v2;
    float s2 = v0 * v0 + v1 * v1 + v2 * v2;
#pragma unroll
    for (int o = 16; o; o >>= 1) {
        s += __shfl_down_sync(0xffffffffu, s, o);
        s2 += __shfl_down_sync(0xffffffffu, s2, o);
    }
    __shared__ float r1[4], r2[4];
    __shared__ float prod[Cn];
    __shared__ float den[8];
    if ((t & 31) == 0) { r1[t >> 5] = s; r2[t >> 5] = s2; }
    __syncthreads();
    float S = r1[0] + r1[1] + r1[2] + r1[3];
    float S2 = r2[0] + r2[1] + r2[2] + r2[3];
    float mu = S * (1.f / (float)Cn);
    float var = S2 * (1.f / (float)Cn) - mu * mu;
    float inv = rsqrtf(var + LN_EPS);
    float y0 = (v0 - mu) * inv * w[t] + bvec[t];
    y0 = (y0 > 0.f) ? y0 + 1.f : expf(y0);
    float y1 = (v1 - mu) * inv * w[t + 128] + bvec[t + 128];
    y1 = (y1 > 0.f) ? y1 + 1.f : expf(y1);
    float y2 = (v2 - mu) * inv * w[t + 256] + bvec[t + 256];
    y2 = (y2 > 0.f) ? y2 + 1.f : expf(y2);
    const float* ks = ksum + (size_t)b * Cn;
    prod[t] = y0 * ks[t];
    prod[t + 128] = y1 * ks[t + 128];
    prod[t + 256] = y2 * ks[t + 256];
    __syncthreads();
    int h = t >> 4, i = t & 15;
    float pd = prod[h * Dn + i * 3] + prod[h * Dn + i * 3 + 1] + prod[h * Dn + i * 3 + 2];
#pragma unroll
    for (int o = 8; o; o >>= 1) pd += __shfl_down_sync(0xffffffffu, pd, o, 16);
    if (i == 0) den[h] = pd + 1e-8f;
    __syncthreads();
    __nv_bfloat16* o = qp + (size_t)r * Cn;
    o[t] = __float2bfloat16_rn(y0 / den[t / Dn]);
    o[t + 128] = __float2bfloat16_rn(y1 / den[(t + 128) / Dn]);
    o[t + 256] = __float2bfloat16_rn(y2 / den[(t + 256) / Dn]);
}

// ---------------- kv_sum + k_sum ----------------
__global__ void kv_v2(const float* __restrict__ k, const float* __restrict__ v,
                      float* __restrict__ kv, float* __restrict__ ksum) {
    int bh = blockIdx.x;
    int chunk = blockIdx.y;
    int b = bh >> 3, h = bh & 7;
    __shared__ float ks[32][49];
    __shared__ float vs[32][49];
    int tid = threadIdx.x;  // 256
    int di = tid >> 4, ei = tid & 15;
    int d0 = di * 3, e0 = ei * 3;
    float acc[3][3] = {};
    float ksa[3] = {};
    int nbeg = chunk * (NK / 4);
    for (int n0 = nbeg; n0 < nbeg + NK / 4; n0 += 32) {
        for (int i = tid; i < 32 * Dn; i += 256) {
            int nn = i / Dn, dd = i % Dn;
            size_t base = ((size_t)b * NK + n0 + nn) * Cn + h * Dn + dd;
            ks[nn][dd] = k[base];
            vs[nn][dd] = v[base];
        }
        __syncthreads();
#pragma unroll 4
        for (int nn = 0; nn < 32; nn++) {
            float kd0 = ks[nn][d0], kd1 = ks[nn][d0 + 1], kd2 = ks[nn][d0 + 2];
            float ve0 = vs[nn][e0], ve1 = vs[nn][e0 + 1], ve2 = vs[nn][e0 + 2];
            acc[0][0] += kd0 * ve0; acc[0][1] += kd0 * ve1; acc[0][2] += kd0 * ve2;
            acc[1][0] += kd1 * ve0; acc[1][1] += kd1 * ve1; acc[1][2] += kd1 * ve2;
            acc[2][0] += kd2 * ve0; acc[2][1] += kd2 * ve1; acc[2][2] += kd2 * ve2;
            if (ei == 0) { ksa[0] += kd0; ksa[1] += kd1; ksa[2] += kd2; }
        }
        __syncthreads();
    }
    float* kvb = kv + (size_t)bh * Dn * Dn;
#pragma unroll
    for (int i = 0; i < 3; i++)
#pragma unroll
        for (int j = 0; j < 3; j++)
            atomicAdd(&kvb[(d0 + i) * Dn + e0 + j], acc[i][j]);
    if (ei == 0)
#pragma unroll
        for (int i = 0; i < 3; i++) atomicAdd(&ksum[bh * Dn + d0 + i], ksa[i]);
}

// ---------------- make_M ----------------
__global__ void make_M(const float* __restrict__ kv, const float* __restrict__ Wo,
                       __nv_bfloat16* __restrict__ Wt) {
    int cb = blockIdx.x;
    int h = blockIdx.y;
    int b = blockIdx.z;
    __shared__ float kvs[Dn][49];
    __shared__ float wos[Dn][132];
    int tid = threadIdx.x;  // 256
    for (int i = tid; i < Dn * Dn; i += 256)
        kvs[i / Dn][i % Dn] = kv[((size_t)b * Hn + h) * Dn * Dn + i];
    for (int i = tid; i < 128 * Dn; i += 256) {
        int co = i / Dn, e = i % Dn;
        wos[e][co] = Wo[(size_t)(cb * 128 + co) * Cn + h * Dn + e];
    }
    __syncthreads();
    int cog = tid & 15, dg = tid >> 4;
    int co0 = cog * 8, d0 = dg * 3;
    float acc[8][3] = {};
#pragma unroll 4
    for (int e = 0; e < Dn; e++) {
        float kd0 = kvs[d0][e], kd1 = kvs[d0 + 1][e], kd2 = kvs[d0 + 2][e];
#pragma unroll
        for (int i = 0; i < 8; i++) {
            float wv = wos[e][co0 + i];
            acc[i][0] += wv * kd0;
            acc[i][1] += wv * kd1;
            acc[i][2] += wv * kd2;
        }
    }
#pragma unroll
    for (int i = 0; i < 8; i++)
#pragma unroll
        for (int j = 0; j < 3; j++)
            Wt[((size_t)b * Cn + cb * 128 + co0 + i) * Cn + h * Dn + d0 + j] =
                __float2bfloat16_rn(acc[i][j]);
}

// ---------------- host launch ----------------
extern "C" void kernel_launch(void* const* d_in, const int* in_sizes, int n_in,
                              void* d_out, int out_size) {
    const float* query = (const float*)d_in[0];
    const float* key = (const float*)d_in[1];
    const float* value = (const float*)d_in[2];
    const float* ada_gamma = (const float*)d_in[3];
    const float* ada_beta = (const float*)d_in[4];
    const float* Wq = (const float*)d_in[5];
    const float* bq = (const float*)d_in[6];
    const float* Wk = (const float*)d_in[7];
    const float* bk = (const float*)d_in[8];
    const float* Wv = (const float*)d_in[9];
    const float* bv = (const float*)d_in[10];
    const float* Wo = (const float*)d_in[11];
    const float* bo = (const float*)d_in[12];
    const float* lnq_w = (const float*)d_in[13];
    const float* lnq_b = (const float*)d_in[14];
    const float* lnk_w = (const float*)d_in[15];
    const float* lnk_b = (const float*)d_in[16];
    const float* attn_scalar = (const float*)d_in[17];
    const float* ffn_gamma = (const float*)d_in[18];
    const float* ffn_beta = (const float*)d_in[19];
    const float* W1 = (const float*)d_in[20];
    const float* b1 = (const float*)d_in[21];
    const float* W2 = (const float*)d_in[22];
    const float* b2 = (const float*)d_in[23];
    const float* ffn_scalar = (const float*)d_in[24];
    const float* final_scalar = (const float*)d_in[25];
    float* out = (float*)d_out;

    float *k, *v, *working, *kv, *ksum, *gx, *msum;
    __nv_bfloat16 *ada_b, *key_b, *val_b, *qh_b, *qp_b, *nrm_b, *h_b, *wts, *M_b;
    cudaGetSymbolAddress((void**)&k, g_k);
    cudaGetSymbolAddress((void**)&v, g_v);
    cudaGetSymbolAddress((void**)&working, g_working);
    cudaGetSymbolAddress((void**)&kv, g_kv);
    cudaGetSymbolAddress((void**)&ksum, g_ksum);
    cudaGetSymbolAddress((void**)&gx, g_gx);
    cudaGetSymbolAddress((void**)&msum, g_msum);
    cudaGetSymbolAddress((void**)&ada_b, b_ada);
    cudaGetSymbolAddress((void**)&key_b, b_key);
    cudaGetSymbolAddress((void**)&val_b, b_val);
    cudaGetSymbolAddress((void**)&qh_b, b_qh);
    cudaGetSymbolAddress((void**)&qp_b, b_qp);
    cudaGetSymbolAddress((void**)&nrm_b, b_nrm);
    cudaGetSymbolAddress((void**)&h_b, b_h);
    cudaGetSymbolAddress((void**)&wts, b_wts);
    cudaGetSymbolAddress((void**)&M_b, b_M);

    __nv_bfloat16* wq_b = wts;
    __nv_bfloat16* wk_b = wts + CC;
    __nv_bfloat16* wv_b = wts + 2 * CC;
    __nv_bfloat16* w1_b = wts + 4 * CC;
    __nv_bfloat16* w2_b = wts + 4 * CC + FC;

    cudaFuncSetAttribute(gemm_qkv, cudaFuncAttributeMaxDynamicSharedMemorySize, GEMM_SMEM);
    cudaFuncSetAttribute(gemm_bf16_row, cudaFuncAttributeMaxDynamicSharedMemorySize, GEMM_SMEM);
    cudaFuncSetAttribute(gemm_bf16_cm, cudaFuncAttributeMaxDynamicSharedMemorySize, GEMM_SMEM);

    // 0) weight conversions + zero msum (one launch)
    conv_f2bf_all<<<1728, 256>>>((const float4*)Wq, (const float4*)Wk, (const float4*)Wv,
                                 (const float4*)Wo, (const float4*)W1, (const float4*)W2,
                                 (__nv_bfloat162*)wts, msum);

    // 0b) key+value transpose-convert, one launch
    transconv_kv<<<dim3(Cn / 64, NK / 32, 2 * Bn), 256>>>(key, key_b, value, val_b);

    // 1) GRN on query -> ada (mean via atomics; no grn_mean launch)
    grn_reduce_kernel<<<Bn * Cn, 256>>>(query, gx, msum);
    transconv_kernel<<<dim3(Cn / 64, NQ / 32, Bn), 256>>>(query, ada_b, gx, msum,
                                                          ada_gamma, ada_beta, NQ, 1);

    // 2) Q + K + V projections in ONE launch
    gemm_qkv<<<dim3(NQ / BM, 9, Bn), 256, GEMM_SMEM>>>(ada_b, wq_b, bq, qh_b,
                                                       key_b, wk_b, bk, k,
                                                       val_b, wv_b, bv, v);

    // 3) LN + elu+1 on k (in place) + fused zero of kv/ksum
    ln_elu_kernel<<<Bn * NK, 128>>>(k, lnk_w, lnk_b, kv, ksum);

    // 4) kv_sum/k_sum
    kv_v2<<<dim3(Bn * Hn, 4), 256>>>(k, v, kv, ksum);

    // 5a) q: LN + elu+1 + fold den -> bf16 q'
    ln_elu_q_den<<<Bn * NQ, 128>>>(qh_b, ksum, lnq_w, lnq_b, qp_b);

    // 5b) fold kv into Wo: per-batch effective weight M
    make_M<<<dim3(Cn / 128, Hn, Bn), 256>>>(kv, Wo, M_b);

    // 6) (attention + Wo) as ONE GEMM
    gemm_bf16_cm<<<dim3(NQ / BM, Cn / BN, Bn), 256, GEMM_SMEM>>>(
        qp_b, M_b, bo, query, nullptr, attn_scalar, nullptr, working,
        NQ, Cn, Cn, 0, Cn * Cn);

    // 7) GRN on working -> normed (mean via atomics, slot 1)
    grn_reduce_kernel<<<Bn * Cn, 256>>>(working, gx, msum + Bn);
    transconv_kernel<<<dim3(Cn / 64, NQ / 32, Bn), 256>>>(working, nrm_b, gx, msum + Bn,
                                                          ffn_gamma, ffn_beta, NQ, 1);

    // 8) FFN1 (+silu) -> h (bf16 rows)
    gemm_bf16_row<<<dim3(NQ / BM, Fn / BN, Bn), 256, GEMM_SMEM>>>(nrm_b, w1_b, b1, h_b,
                                                                  NQ, Cn, Fn);

    // 9) FFN2 + ffn residual + final residual -> out (fp32, channel-major)
    gemm_bf16_cm<<<dim3(NQ / BM, Cn / BN, Bn), 256, GEMM_SMEM>>>(
        h_b, w2_b, b2, query, working, ffn_scalar, final_scalar, out,
        NQ, Fn, Cn, 1, 0);
}

// round 16
// speedup vs baseline: 1.4278x; 1.0129x over previous
#include <cuda_runtime.h>
#include <cuda_bf16.h>
#include <math.h>
#include <stdint.h>

// Problem constants
#define Bn 8
#define Cn 384
#define NQ 4096
#define NK 1024
#define Hn 8
#define Dn 48
#define Fn 1536
#define GRN_EPS 1e-6f
#define LN_EPS 1e-5f

// GEMM tiling (bf16): 128x128 CTA tile, 64x32 warp tiles (validated config)
#define BM 128
#define BN 128
#define KSB 32
#define KW 16
#define NSTAGE 3
#define GW (BM * KW)
#define GEMM_SMEM (NSTAGE * 2 * GW * 4)  // 49152 bytes

#define CC (Cn * Cn)
#define FC (Fn * Cn)

// ---------------- scratch (device globals; no allocations) ----------------
__device__ float g_k[(size_t)Bn * NK * Cn];
__device__ float g_v[(size_t)Bn * NK * Cn];
__device__ float g_kv[(size_t)Bn * Hn * Dn * Dn];
__device__ float g_ksum[(size_t)Bn * Hn * Dn];
__device__ float g_gx[(size_t)Bn * Cn];
__device__ float g_msum[2 * Bn];

__device__ __nv_bfloat16 b_ada[(size_t)Bn * NQ * Cn];
__device__ __nv_bfloat16 b_key[(size_t)Bn * NK * Cn];
__device__ __nv_bfloat16 b_val[(size_t)Bn * NK * Cn];
__device__ __nv_bfloat16 b_qh[(size_t)Bn * NQ * Cn];
__device__ __nv_bfloat16 b_qp[(size_t)Bn * NQ * Cn];
__device__ __nv_bfloat16 b_wk[(size_t)Bn * Cn * NQ];  // working residual (bf16, channel-major)
__device__ __nv_bfloat16 b_nrm[(size_t)Bn * NQ * Cn];
__device__ __nv_bfloat16 b_h[(size_t)Bn * NQ * Fn];
__device__ __nv_bfloat16 b_wts[4 * CC + 2 * FC];
__device__ __nv_bfloat16 b_M[(size_t)Bn * Cn * Cn];

// ---------------- helpers ----------------
__device__ __forceinline__ void cp_async16(void* smem_dst, const void* gsrc) {
    uint32_t s = (uint32_t)__cvta_generic_to_shared(smem_dst);
    asm volatile("cp.async.cg.shared.global [%0], [%1], 16;" ::"r"(s), "l"(gsrc));
}
__device__ __forceinline__ void cp_commit() { asm volatile("cp.async.commit_group;"); }
__device__ __forceinline__ void cp_wait1() { asm volatile("cp.async.wait_group 1;"); }
__device__ __forceinline__ void cp_wait0() { asm volatile("cp.async.wait_group 0;"); }

__device__ __forceinline__ void mma16(float* c, uint32_t a0, uint32_t a1, uint32_t a2,
                                      uint32_t a3, uint32_t b0, uint32_t b1) {
    asm volatile(
        "mma.sync.aligned.m16n8k16.row.col.f32.bf16.bf16.f32 "
        "{%0,%1,%2,%3},{%4,%5,%6,%7},{%8,%9},{%0,%1,%2,%3};"
        : "+f"(c[0]), "+f"(c[1]), "+f"(c[2]), "+f"(c[3])
        : "r"(a0), "r"(a1), "r"(a2), "r"(a3), "r"(b0), "r"(b1));
}

__device__ __forceinline__ void ldsm4(uint32_t& r0, uint32_t& r1, uint32_t& r2, uint32_t& r3,
                                      uint32_t saddr) {
    asm volatile("ldmatrix.sync.aligned.m8n8.x4.shared.b16 {%0,%1,%2,%3}, [%4];"
                 : "=r"(r0), "=r"(r1), "=r"(r2), "=r"(r3)
                 : "r"(saddr));
}

// ---------------- merged weight convert (+ zero msum) ----------------
__global__ void conv_f2bf_all(const float4* __restrict__ wq, const float4* __restrict__ wk,
                              const float4* __restrict__ wv, const float4* __restrict__ wo,
                              const float4* __restrict__ w1, const float4* __restrict__ w2,
                              __nv_bfloat162* __restrict__ dst, float* __restrict__ msum) {
    if (blockIdx.x == 0 && threadIdx.x < 2 * Bn) msum[threadIdx.x] = 0.f;
    const int C4 = CC / 4, F4 = FC / 4;
    int total = 4 * C4 + 2 * F4;
    for (int i = blockIdx.x * 256 + threadIdx.x; i < total; i += gridDim.x * 256) {
        const float4* src;
        int off;
        if (i < 4 * C4) {
            int seg = i / C4;
            off = i - seg * C4;
            src = (seg == 0) ? wq : (seg == 1) ? wk : (seg == 2) ? wv : wo;
        } else if (i < 4 * C4 + F4) {
            src = w1;
            off = i - 4 * C4;
        } else {
            src = w2;
            off = i - 4 * C4 - F4;
        }
        float4 v = src[off];
        __nv_bfloat162 a, b;
        a.x = __float2bfloat16_rn(v.x); a.y = __float2bfloat16_rn(v.y);
        b.x = __float2bfloat16_rn(v.z); b.y = __float2bfloat16_rn(v.w);
        dst[2 * i] = a;
        dst[2 * i + 1] = b;
    }
}

// ---------------- GRN reduce (fp32 input, query pass) ----------------
__global__ void grn_reduce_kernel(const float* __restrict__ x, float* __restrict__ gx,
                                  float* __restrict__ msum) {
    int bc = blockIdx.x;
    const float4* p = (const float4*)(x + (size_t)bc * NQ);
    int t = threadIdx.x;  // 256; 1024 float4 total
    float4 a = p[t], b = p[t + 256], c = p[t + 512], d = p[t + 768];
    float s = a.x * a.x + a.y * a.y + a.z * a.z + a.w * a.w;
    s += b.x * b.x + b.y * b.y + b.z * b.z + b.w * b.w;
    s += c.x * c.x + c.y * c.y + c.z * c.z + c.w * c.w;
    s += d.x * d.x + d.y * d.y + d.z * d.z + d.w * d.w;
#pragma unroll
    for (int o = 16; o; o >>= 1) s += __shfl_down_sync(0xffffffffu, s, o);
    __shared__ float r[8];
    if ((t & 31) == 0) r[t >> 5] = s;
    __syncthreads();
    if (t == 0) {
        float S = sqrtf(r[0] + r[1] + r[2] + r[3] + r[4] + r[5] + r[6] + r[7]);
        gx[bc] = S;
        atomicAdd(&msum[bc / Cn], S);
    }
}

// ---------------- GRN reduce (bf16 input, working pass) ----------------
__global__ void grn_reduce_h(const __nv_bfloat16* __restrict__ x, float* __restrict__ gx,
                             float* __restrict__ msum) {
    int bc = blockIdx.x;
    const uint4* p = (const uint4*)(x + (size_t)bc * NQ);  // 512 uint4 (8 bf16 each)
    int t = threadIdx.x;  // 256; 2 per thread
    float s = 0.f;
#pragma unroll
    for (int q = 0; q < 2; q++) {
        uint4 u = p[t + q * 256];
        uint32_t w[4] = {u.x, u.y, u.z, u.w};
#pragma unroll
        for (int i = 0; i < 4; i++) {
            __nv_bfloat162 hv = *(__nv_bfloat162*)&w[i];
            float f0 = __bfloat162float(hv.x), f1 = __bfloat162float(hv.y);
            s += f0 * f0 + f1 * f1;
        }
    }
#pragma unroll
    for (int o = 16; o; o >>= 1) s += __shfl_down_sync(0xffffffffu, s, o);
    __shared__ float r[8];
    if ((t & 31) == 0) r[t >> 5] = s;
    __syncthreads();
    if (t == 0) {
        float S = sqrtf(r[0] + r[1] + r[2] + r[3] + r[4] + r[5] + r[6] + r[7]);
        gx[bc] = S;
        atomicAdd(&msum[bc / Cn], S);
    }
}

// ---------------- transpose + GRN + convert to bf16 rows (fp32 input) --------------
__global__ void transconv_kernel(const float* __restrict__ x, __nv_bfloat16* __restrict__ out,
                                 const float* __restrict__ gx, const float* __restrict__ msum,
                                 const float* __restrict__ gamma, const float* __restrict__ beta,
                                 int N, int grn) {
    int b = blockIdx.z;
    int c0 = blockIdx.x * 64;
    int n0 = blockIdx.y * 32;
    __shared__ float t[64][33];
    int tid = threadIdx.x;
    int j = tid & 31, i0 = tid >> 5;
#pragma unroll
    for (int p = 0; p < 8; p++) {
        int i = i0 + p * 8;
        t[i][j] = x[((size_t)b * Cn + c0 + i) * N + n0 + j];
    }
    __syncthreads();
    int cp = tid & 31;
    int nn0 = tid >> 5;
    int c = c0 + 2 * cp;
    float sc0 = 1.f, bt0 = 0.f, sc1 = 1.f, bt1 = 0.f;
    if (grn) {
        float meanc = msum[b] * (1.f / (float)Cn) + GRN_EPS;
        sc0 = 1.f + (1.f + gamma[c]) * gx[b * Cn + c] / meanc;
        bt0 = beta[c];
        sc1 = 1.f + (1.f + gamma[c + 1]) * gx[b * Cn + c + 1] / meanc;
        bt1 = beta[c + 1];
    }
#pragma unroll
    for (int p = 0; p < 4; p++) {
        int nn = nn0 + p * 8;
        float v0 = t[2 * cp][nn] * sc0 + bt0;
        float v1 = t[2 * cp + 1][nn] * sc1 + bt1;
        __nv_bfloat162 hv;
        hv.x = __float2bfloat16_rn(v0);
        hv.y = __float2bfloat16_rn(v1);
        *(__nv_bfloat162*)(out + ((size_t)b * N + n0 + nn) * Cn + c) = hv;
    }
}

// ---------------- transpose + GRN + convert to bf16 rows (bf16 input) --------------
__global__ void transconv_h(const __nv_bfloat16* __restrict__ x,
                            __nv_bfloat16* __restrict__ out,
                            const float* __restrict__ gx, const float* __restrict__ msum,
                            const float* __restrict__ gamma, const float* __restrict__ beta) {
    int b = blockIdx.z;
    int c0 = blockIdx.x * 64;
    int n0 = blockIdx.y * 32;
    __shared__ float t[64][33];
    int tid = threadIdx.x;
    int j = tid & 31, i0 = tid >> 5;
#pragma unroll
    for (int p = 0; p < 8; p++) {
        int i = i0 + p * 8;
        t[i][j] = __bfloat162float(x[((size_t)b * Cn + c0 + i) * NQ + n0 + j]);
    }
    __syncthreads();
    int cp = tid & 31;
    int nn0 = tid >> 5;
    int c = c0 + 2 * cp;
    float meanc = msum[b] * (1.f / (float)Cn) + GRN_EPS;
    float sc0 = 1.f + (1.f + gamma[c]) * gx[b * Cn + c] / meanc;
    float bt0 = beta[c];
    float sc1 = 1.f + (1.f + gamma[c + 1]) * gx[b * Cn + c + 1] / meanc;
    float bt1 = beta[c + 1];
#pragma unroll
    for (int p = 0; p < 4; p++) {
        int nn = nn0 + p * 8;
        float v0 = t[2 * cp][nn] * sc0 + bt0;
        float v1 = t[2 * cp + 1][nn] * sc1 + bt1;
        __nv_bfloat162 hv;
        hv.x = __float2bfloat16_rn(v0);
        hv.y = __float2bfloat16_rn(v1);
        *(__nv_bfloat162*)(out + ((size_t)b * NQ + n0 + nn) * Cn + c) = hv;
    }
}

// merged key+value transpose-convert (no GRN), one launch
__global__ void transconv_kv(const float* __restrict__ xk, __nv_bfloat16* __restrict__ ok,
                             const float* __restrict__ xv, __nv_bfloat16* __restrict__ ov) {
    int z = blockIdx.z;
    const float* x = (z < Bn) ? xk : xv;
    __nv_bfloat16* out = (z < Bn) ? ok : ov;
    int b = (z < Bn) ? z : z - Bn;
    int c0 = blockIdx.x * 64;
    int n0 = blockIdx.y * 32;
    __shared__ float t[64][33];
    int tid = threadIdx.x;
    int j = tid & 31, i0 = tid >> 5;
#pragma unroll
    for (int p = 0; p < 8; p++) {
        int i = i0 + p * 8;
        t[i][j] = x[((size_t)b * Cn + c0 + i) * NK + n0 + j];
    }
    __syncthreads();
    int cp = tid & 31;
    int nn0 = tid >> 5;
    int c = c0 + 2 * cp;
#pragma unroll
    for (int p = 0; p < 4; p++) {
        int nn = nn0 + p * 8;
        __nv_bfloat162 hv;
        hv.x = __float2bfloat16_rn(t[2 * cp][nn]);
        hv.y = __float2bfloat16_rn(t[2 * cp + 1][nn]);
        *(__nv_bfloat162*)(out + ((size_t)b * NK + n0 + nn) * Cn + c) = hv;
    }
}

// ---------------- shared GEMM mainloop (128x128 tile, ldmatrix fragments) --------------
#define GEMM_MAINLOOP(Ab, Wp, K)                                                          \
    const uint32_t a_base = (uint32_t)__cvta_generic_to_shared(As);                       \
    const uint32_t b_base = (uint32_t)__cvta_generic_to_shared(Bs);                       \
    int lr = (lane & 7) + ((lane >> 3) & 1) * 8;                                          \
    int lca = lane >> 4;                                                                  \
    int lrb = (lane & 7) + (lane >> 4) * 8;                                               \
    int lcb = (lane >> 3) & 1;                                                            \
    int nslab = (K) / KSB;                                                                \
    LOAD_BF(0, 0, Ab, Wp, K);                                                             \
    LOAD_BF(1, 1, Ab, Wp, K);                                                             \
    for (int s = 0; s < nslab; s++) {                                                     \
        int stg = s % NSTAGE;                                                             \
        if (s + 1 < nslab) cp_wait1(); else cp_wait0();                                   \
        __syncthreads();                                                                  \
        if (s + 2 < nslab) LOAD_BF(s + 2, (s + 2) % NSTAGE, Ab, Wp, K);                   \
        uint32_t Ast = a_base + stg * GW * 4;                                             \
        uint32_t Bst = b_base + stg * GW * 4;                                             \
        _Pragma("unroll") for (int kb = 0; kb < 2; kb++) {                                \
            uint32_t af[4][4], bfr[4][2];                                                 \
            _Pragma("unroll") for (int mf = 0; mf < 4; mf++) {                            \
                int row = wm + mf * 16 + lr;                                              \
                int ch = 2 * kb + lca;                                                    \
                ldsm4(af[mf][0], af[mf][1], af[mf][2], af[mf][3],                         \
                      Ast + row * 64 + ((ch ^ ((row >> 1) & 3)) << 4));                   \
            }                                                                             \
            _Pragma("unroll") for (int p = 0; p < 2; p++) {                               \
                int row = wn + p * 16 + lrb;                                              \
                int ch = 2 * kb + lcb;                                                    \
                ldsm4(bfr[2 * p][0], bfr[2 * p][1], bfr[2 * p + 1][0], bfr[2 * p + 1][1], \
                      Bst + row * 64 + ((ch ^ ((row >> 1) & 3)) << 4));                   \
            }                                                                             \
            _Pragma("unroll") for (int mf = 0; mf < 4; mf++)                              \
                _Pragma("unroll") for (int nf = 0; nf < 4; nf++)                          \
                    mma16(acc[mf][nf], af[mf][0], af[mf][1], af[mf][2], af[mf][3],        \
                          bfr[nf][0], bfr[nf][1]);                                        \
        }                                                                                 \
    }

#define LOAD_BF(slab, stg, Abp, Wpp, Kk)                                                \
    {                                                                                   \
        int kk0 = (slab)*KSB;                                                           \
        uint32_t* Ad = As + (size_t)(stg)*GW;                                           \
        uint32_t* Bd = Bs + (size_t)(stg)*GW;                                           \
        _Pragma("unroll") for (int p = 0; p < 2; p++) {                                 \
            int c = tid + p * 256;                                                      \
            int r = c >> 2, ch = c & 3;                                                 \
            int sw = ((ch ^ ((r >> 1) & 3)) << 2);                                      \
            cp_async16(Ad + r * KW + sw, (Abp) + (size_t)(m0 + r) * (Kk) + kk0 + ch * 8); \
            cp_async16(Bd + r * KW + sw, (Wpp) + (size_t)(c0 + r) * (Kk) + kk0 + ch * 8); \
        }                                                                               \
        cp_commit();                                                                    \
    }

// ---------------- Q/K/V projections in ONE launch ----------------
__global__ __launch_bounds__(256) void gemm_qkv(
    const __nv_bfloat16* __restrict__ Aq, const __nv_bfloat16* __restrict__ Wq_,
    const float* __restrict__ bq_, __nv_bfloat16* __restrict__ qh,
    const __nv_bfloat16* __restrict__ Ak, const __nv_bfloat16* __restrict__ Wk_,
    const float* __restrict__ bk_, float* __restrict__ kf,
    const __nv_bfloat16* __restrict__ Av, const __nv_bfloat16* __restrict__ Wv_,
    const float* __restrict__ bv_, float* __restrict__ vf) {
    extern __shared__ uint32_t smu[];
    uint32_t* As = smu;
    uint32_t* Bs = smu + NSTAGE * GW;
    int b = blockIdx.z;
    int m0 = blockIdx.x * BM;
    int yb = blockIdx.y;
    const __nv_bfloat16 *A, *W;
    const float* bias;
    float* Yf = nullptr;
    __nv_bfloat16* Yh = nullptr;
    int N;
    if (yb < 3) {
        A = Aq; W = Wq_; bias = bq_; Yh = qh; N = NQ;
    } else if (yb < 6) {
        A = Ak; W = Wk_; bias = bk_; Yf = kf; N = NK; yb -= 3;
    } else {
        A = Av; W = Wv_; bias = bv_; Yf = vf; N = NK; yb -= 6;
    }
    if (m0 >= N) return;
    int c0 = yb * BN;
    int tid = threadIdx.x;
    int warp = tid >> 5, lane = tid & 31;
    int g = lane >> 2, lq = lane & 3;
    int wm = (warp >> 2) * 64;
    int wn = (warp & 3) * 32;
    float acc[4][4][4] = {};
    const __nv_bfloat16* Ab = A + (size_t)b * N * Cn;
    const __nv_bfloat16* Wp = W;
    const int K = Cn;

    GEMM_MAINLOOP(Ab, Wp, K)

#pragma unroll
    for (int mf = 0; mf < 4; mf++) {
#pragma unroll
        for (int nf = 0; nf < 4; nf++) {
            int co = c0 + wn + nf * 8 + lq * 2;
            float b0v = bias[co], b1v = bias[co + 1];
#pragma unroll
            for (int hr = 0; hr < 2; hr++) {
                int m = m0 + wm + mf * 16 + g + hr * 8;
                float v0 = acc[mf][nf][hr * 2 + 0] + b0v;
                float v1 = acc[mf][nf][hr * 2 + 1] + b1v;
                if (Yh) {
                    __nv_bfloat162 hv;
                    hv.x = __float2bfloat16_rn(v0);
                    hv.y = __float2bfloat16_rn(v1);
                    *(__nv_bfloat162*)(Yh + ((size_t)b * N + m) * Cn + co) = hv;
                } else {
                    *(float2*)(Yf + ((size_t)b * N + m) * Cn + co) = make_float2(v0, v1);
                }
            }
        }
    }
}

// ---------------- bf16 GEMM, row-major output (FFN1: silu + bf16) ----------------
__global__ __launch_bounds__(256) void gemm_bf16_row(
    const __nv_bfloat16* __restrict__ A, const __nv_bfloat16* __restrict__ W,
    const float* __restrict__ bias, __nv_bfloat16* __restrict__ Yh,
    int N, int K, int Cout) {
    extern __shared__ uint32_t smu[];
    uint32_t* As = smu;
    uint32_t* Bs = smu + NSTAGE * GW;
    int b = blockIdx.z;
    int m0 = blockIdx.x * BM;
    int c0 = blockIdx.y * BN;
    int tid = threadIdx.x;
    int warp = tid >> 5, lane = tid & 31;
    int g = lane >> 2, lq = lane & 3;
    int wm = (warp >> 2) * 64;
    int wn = (warp & 3) * 32;
    float acc[4][4][4] = {};
    const __nv_bfloat16* Ab = A + (size_t)b * N * K;
    const __nv_bfloat16* Wp = W;

    GEMM_MAINLOOP(Ab, Wp, K)

#pragma unroll
    for (int mf = 0; mf < 4; mf++) {
#pragma unroll
        for (int nf = 0; nf < 4; nf++) {
            int co = c0 + wn + nf * 8 + lq * 2;
            float b0v = bias[co], b1v = bias[co + 1];
#pragma unroll
            for (int hr = 0; hr < 2; hr++) {
                int m = m0 + wm + mf * 16 + g + hr * 8;
                float v0 = acc[mf][nf][hr * 2 + 0] + b0v;
                float v1 = acc[mf][nf][hr * 2 + 1] + b1v;
                v0 = v0 / (1.f + expf(-v0));
                v1 = v1 / (1.f + expf(-v1));
                __nv_bfloat162 hv;
                hv.x = __float2bfloat16_rn(v0);
                hv.y = __float2bfloat16_rn(v1);
                *(__nv_bfloat162*)(Yh + ((size_t)b * N + m) * Cout + co) = hv;
            }
        }
    }
}

// ---------------- bf16 GEMM, channel-major fused output (batch-strided W) ----------
// mode 0: outh[b,co,m] = bf16(resid1 + val*s1)                (attn -> working bf16)
// mode 1: outf[b,co,m] = resid1 + (float(resid2h) + val*s1)*s2 (FFN2 -> final fp32)
__global__ __launch_bounds__(256) void gemm_bf16_cm(
    const __nv_bfloat16* __restrict__ A, const __nv_bfloat16* __restrict__ W,
    const float* __restrict__ bias,
    const float* __restrict__ resid1, const __nv_bfloat16* __restrict__ resid2h,
    const float* __restrict__ scal1, const float* __restrict__ scal2,
    float* __restrict__ outf, __nv_bfloat16* __restrict__ outh,
    int N, int K, int Cout, int mode, int wstride) {
    extern __shared__ uint32_t smu[];
    uint32_t* As = smu;
    uint32_t* Bs = smu + NSTAGE * GW;
    int b = blockIdx.z;
    int m0 = blockIdx.x * BM;
    int c0 = blockIdx.y * BN;
    int tid = threadIdx.x;
    int warp = tid >> 5, lane = tid & 31;
    int g = lane >> 2, lq = lane & 3;
    int wm = (warp >> 2) * 64;
    int wn = (warp & 3) * 32;
    float acc[4][4][4] = {};
    const __nv_bfloat16* Ab = A + (size_t)b * N * K;
    const __nv_bfloat16* Wp = W + (size_t)b * wstride;

    GEMM_MAINLOOP(Ab, Wp, K)

#pragma unroll
    for (int nf = 0; nf < 4; nf++) {
#pragma unroll
        for (int cj = 0; cj < 2; cj++) {
            int co = c0 + wn + nf * 8 + lq * 2 + cj;
            float bv = bias[co];
            float s1 = scal1[co];
            float s2 = (mode == 1) ? scal2[co] : 0.f;
#pragma unroll
            for (int mf = 0; mf < 4; mf++) {
#pragma unroll
                for (int hr = 0; hr < 2; hr++) {
                    int m = m0 + wm + mf * 16 + g + hr * 8;
                    size_t idx = ((size_t)b * Cout + co) * (size_t)N + m;
                    float val = acc[mf][nf][hr * 2 + cj] + bv;
                    if (mode == 0) {
                        outh[idx] = __float2bfloat16_rn(resid1[idx] + val * s1);
                    } else {
                        outf[idx] = resid1[idx] +
                                    (__bfloat162float(resid2h[idx]) + val * s1) * s2;
                    }
                }
            }
        }
    }
}

// ---------------- LayerNorm + elu+1 on k (in place) + zero kv/ksum ----------------
__global__ void ln_elu_kernel(float* __restrict__ x, const float* __restrict__ w,
                              const float* __restrict__ bvec, float* __restrict__ kv,
                              float* __restrict__ ksum) {
    int r = blockIdx.x;
    int t = threadIdx.x;  // 128
    int gidx = r * 128 + t;
    if (gidx < Bn * Hn * Dn * Dn) kv[gidx] = 0.f;
    if (gidx < Bn * Hn * Dn) ksum[gidx] = 0.f;
    float* p = x + (size_t)r * Cn;
    float v0 = p[t], v1 = p[t + 128], v2 = p[t + 256];
    float s = v0 + v1 + v2;
    float s2 = v0 * v0 + v1 * v1 + v2 * v2;
#pragma unroll
    for (int o = 16; o; o >>= 1) {
        s += __shfl_down_sync(0xffffffffu, s, o);
        s2 += __shfl_down_sync(0xffffffffu, s2, o);
    }
    __shared__ float r1[4], r2[4];
    if ((t & 31) == 0) { r1[t >> 5] = s; r2[t >> 5] = s2; }
    __syncthreads();
    float S = r1[0] + r1[1] + r1[2] + r1[3];
    float S2 = r2[0] + r2[1] + r2[2] + r2[3];
    float mu = S * (1.f / (float)Cn);
    float var = S2 * (1.f / (float)Cn) - mu * mu;
    float inv = rsqrtf(var + LN_EPS);
    float y;
    y = (v0 - mu) * inv * w[t] + bvec[t];
    p[t] = (y > 0.f) ? y + 1.f : expf(y);
    y = (v1 - mu) * inv * w[t + 128] + bvec[t + 128];
    p[t + 128] = (y > 0.f) ? y + 1.f : expf(y);
    y = (v2 - mu) * inv * w[t + 256] + bvec[t + 256];
    p[t + 256] = (y > 0.f) ? y + 1.f : expf(y);
}

// ---------------- q: LN + elu+1 + den fold -> bf16 q' (warp-shuffle) ----------------
__global__ void ln_elu_q_den(const __nv_bfloat16* __restrict__ x,
                             const float* __restrict__ ksum,
                             const float* __restrict__ w, const float* __restrict__ bvec,
                             __nv_bfloat16* __restrict__ qp) {
    int r = blockIdx.x;
    int b = r / NQ;
    const __nv_bfloat16* p = x + (size_t)r * Cn;
    int t = threadIdx.x;  // 128
    float v0 = __bfloat162float(p[t]);
    float v1 = __bfloat162float(p[t + 128]);
    float v2 = __bfloat162float(p[t + 256]);
    float s = v0 + v1 + v2;
    float s2 = v0 * v0 + v1 * v1 + v2 * v2;
#pragma unroll
    for (int o = 16; o; o >>= 1) {
        s += __shfl_down_sync(0xffffffffu, s, o);
        s2 += __shfl_down_sync(0xffffffffu, s2, o);
    }
    __shared__ float r1[4], r2[4];
    __shared__ float prod[Cn];
    __shared__ float den[8];
    if ((t & 31) == 0) { r1[t >> 5] = s; r2[t >> 5] = s2; }
    __syncthreads();
    float S = r1[0] + r1[1] + r1[2] + r1[3];
    float S2 = r2[0] + r2[1] + r2[2] + r2[3];
    float mu = S * (1.f / (float)Cn);
    float var = S2 * (1.f / (float)Cn) - mu * mu;
    float inv = rsqrtf(var + LN_EPS);
    float y0 = (v0 - mu) * inv * w[t] + bvec[t];
    y0 = (y0 > 0.f) ? y0 + 1.f : expf(y0);
    float y1 = (v1 - mu) * inv * w[t + 128] + bvec[t + 128];
    y1 = (y1 > 0.f) ? y1 + 1.f : expf(y1);
    float y2 = (v2 - mu) * inv * w[t + 256] + bvec[t + 256];
    y2 = (y2 > 0.f) ? y2 + 1.f : expf(y2);
    const float* ks = ksum + (size_t)b * Cn;
    prod[t] = y0 * ks[t];
    prod[t + 128] = y1 * ks[t + 128];
    prod[t + 256] = y2 * ks[t + 256];
    __syncthreads();
    int h = t >> 4, i = t & 15;
    float pd = prod[h * Dn + i * 3] + prod[h * Dn + i * 3 + 1] + prod[h * Dn + i * 3 + 2];
#pragma unroll
    for (int o = 8; o; o >>= 1) pd += __shfl_down_sync(0xffffffffu, pd, o, 16);
    if (i == 0) den[h] = pd + 1e-8f;
    __syncthreads();
    __nv_bfloat16* o = qp + (size_t)r * Cn;
    o[t] = __float2bfloat16_rn(y0 / den[t / Dn]);
    o[t + 128] = __float2bfloat16_rn(y1 / den[(t + 128) / Dn]);
    o[t + 256] = __float2bfloat16_rn(y2 / den[(t + 256) / Dn]);
}

// ---------------- kv_sum + k_sum ----------------
__global__ void kv_v2(const float* __restrict__ k, const float* __restrict__ v,
                      float* __restrict__ kv, float* __restrict__ ksum) {
    int bh = blockIdx.x;
    int chunk = blockIdx.y;
    int b = bh >> 3, h = bh & 7;
    __shared__ float ks[32][49];
    __shared__ float vs[32][49];
    int tid = threadIdx.x;  // 256
    int di = tid >> 4, ei = tid & 15;
    int d0 = di * 3, e0 = ei * 3;
    float acc[3][3] = {};
    float ksa[3] = {};
    int nbeg = chunk * (NK / 4);
    for (int n0 = nbeg; n0 < nbeg + NK / 4; n0 += 32) {
        for (int i = tid; i < 32 * Dn; i += 256) {
            int nn = i / Dn, dd = i % Dn;
            size_t base = ((size_t)b * NK + n0 + nn) * Cn + h * Dn + dd;
            ks[nn][dd] = k[base];
            vs[nn][dd] = v[base];
        }
        __syncthreads();
#pragma unroll 4
        for (int nn = 0; nn < 32; nn++) {
            float kd0 = ks[nn][d0], kd1 = ks[nn][d0 + 1], kd2 = ks[nn][d0 + 2];
            float ve0 = vs[nn][e0], ve1 = vs[nn][e0 + 1], ve2 = vs[nn][e0 + 2];
            acc[0][0] += kd0 * ve0; acc[0][1] += kd0 * ve1; acc[0][2] += kd0 * ve2;
            acc[1][0] += kd1 * ve0; acc[1][1] += kd1 * ve1; acc[1][2] += kd1 * ve2;
            acc[2][0] += kd2 * ve0; acc[2][1] += kd2 * ve1; acc[2][2] += kd2 * ve2;
            if (ei == 0) { ksa[0] += kd0; ksa[1] += kd1; ksa[2] += kd2; }
        }
        __syncthreads();
    }
    float* kvb = kv + (size_t)bh * Dn * Dn;
#pragma unroll
    for (int i = 0; i < 3; i++)
#pragma unroll
        for (int j = 0; j < 3; j++)
            atomicAdd(&kvb[(d0 + i) * Dn + e0 + j], acc[i][j]);
    if (ei == 0)
#pragma unroll
        for (int i = 0; i < 3; i++) atomicAdd(&ksum[bh * Dn + d0 + i], ksa[i]);
}

// ---------------- make_M ----------------
__global__ void make_M(const float* __restrict__ kv, const float* __restrict__ Wo,
                       __nv_bfloat16* __restrict__ Wt) {
    int cb = blockIdx.x;
    int h = blockIdx.y;
    int b = blockIdx.z;
    __shared__ float kvs[Dn][49];
    __shared__ float wos[Dn][132];
    int tid = threadIdx.x;  // 256
    for (int i = tid; i < Dn * Dn; i += 256)
        kvs[i / Dn][i % Dn] = kv[((size_t)b * Hn + h) * Dn * Dn + i];
    for (int i = tid; i < 128 * Dn; i += 256) {
        int co = i / Dn, e = i % Dn;
        wos[e][co] = Wo[(size_t)(cb * 128 + co) * Cn + h * Dn + e];
    }
    __syncthreads();
    int cog = tid & 15, dg = tid >> 4;
    int co0 = cog * 8, d0 = dg * 3;
    float acc[8][3] = {};
#pragma unroll 4
    for (int e = 0; e < Dn; e++) {
        float kd0 = kvs[d0][e], kd1 = kvs[d0 + 1][e], kd2 = kvs[d0 + 2][e];
#pragma unroll
        for (int i = 0; i < 8; i++) {
            float wv = wos[e][co0 + i];
            acc[i][0] += wv * kd0;
            acc[i][1] += wv * kd1;
            acc[i][2] += wv * kd2;
        }
    }
#pragma unroll
    for (int i = 0; i < 8; i++)
#pragma unroll
        for (int j = 0; j < 3; j++)
            Wt[((size_t)b * Cn + cb * 128 + co0 + i) * Cn + h * Dn + d0 + j] =
                __float2bfloat16_rn(acc[i][j]);
}

// ---------------- host launch ----------------
extern "C" void kernel_launch(void* const* d_in, const int* in_sizes, int n_in,
                              void* d_out, int out_size) {
    const float* query = (const float*)d_in[0];
    const float* key = (const float*)d_in[1];
    const float* value = (const float*)d_in[2];
    const float* ada_gamma = (const float*)d_in[3];
    const float* ada_beta = (const float*)d_in[4];
    const float* Wq = (const float*)d_in[5];
    const float* bq = (const float*)d_in[6];
    const float* Wk = (const float*)d_in[7];
    const float* bk = (const float*)d_in[8];
    const float* Wv = (const float*)d_in[9];
    const float* bv = (const float*)d_in[10];
    const float* Wo = (const float*)d_in[11];
    const float* bo = (const float*)d_in[12];
    const float* lnq_w = (const float*)d_in[13];
    const float* lnq_b = (const float*)d_in[14];
    const float* lnk_w = (const float*)d_in[15];
    const float* lnk_b = (const float*)d_in[16];
    const float* attn_scalar = (const float*)d_in[17];
    const float* ffn_gamma = (const float*)d_in[18];
    const float* ffn_beta = (const float*)d_in[19];
    const float* W1 = (const float*)d_in[20];
    const float* b1 = (const float*)d_in[21];
    const float* W2 = (const float*)d_in[22];
    const float* b2 = (const float*)d_in[23];
    const float* ffn_scalar = (const float*)d_in[24];
    const float* final_scalar = (const float*)d_in[25];
    float* out = (float*)d_out;

    float *k, *v, *kv, *ksum, *gx, *msum;
    __nv_bfloat16 *ada_b, *key_b, *val_b, *qh_b, *qp_b, *wk_b, *nrm_b, *h_b, *wts, *M_b;
    cudaGetSymbolAddress((void**)&k, g_k);
    cudaGetSymbolAddress((void**)&v, g_v);
    cudaGetSymbolAddress((void**)&kv, g_kv);
    cudaGetSymbolAddress((void**)&ksum, g_ksum);
    cudaGetSymbolAddress((void**)&gx, g_gx);
    cudaGetSymbolAddress((void**)&msum, g_msum);
    cudaGetSymbolAddress((void**)&ada_b, b_ada);
    cudaGetSymbolAddress((void**)&key_b, b_key);
    cudaGetSymbolAddress((void**)&val_b, b_val);
    cudaGetSymbolAddress((void**)&qh_b, b_qh);
    cudaGetSymbolAddress((void**)&qp_b, b_qp);
    cudaGetSymbolAddress((void**)&wk_b, b_wk);
    cudaGetSymbolAddress((void**)&nrm_b, b_nrm);
    cudaGetSymbolAddress((void**)&h_b, b_h);
    cudaGetSymbolAddress((void**)&wts, b_wts);
    cudaGetSymbolAddress((void**)&M_b, b_M);

    __nv_bfloat16* wq_b = wts;
    __nv_bfloat16* wk2_b = wts + CC;
    __nv_bfloat16* wv_b = wts + 2 * CC;
    __nv_bfloat16* w1_b = wts + 4 * CC;
    __nv_bfloat16* w2_b = wts + 4 * CC + FC;

    cudaFuncSetAttribute(gemm_qkv, cudaFuncAttributeMaxDynamicSharedMemorySize, GEMM_SMEM);
    cudaFuncSetAttribute(gemm_bf16_row, cudaFuncAttributeMaxDynamicSharedMemorySize, GEMM_SMEM);
    cudaFuncSetAttribute(gemm_bf16_cm, cudaFuncAttributeMaxDynamicSharedMemorySize, GEMM_SMEM);

    // 0) weight conversions + zero msum (one launch)
    conv_f2bf_all<<<1728, 256>>>((const float4*)Wq, (const float4*)Wk, (const float4*)Wv,
                                 (const float4*)Wo, (const float4*)W1, (const float4*)W2,
                                 (__nv_bfloat162*)wts, msum);

    // 0b) key+value transpose-convert, one launch
    transconv_kv<<<dim3(Cn / 64, NK / 32, 2 * Bn), 256>>>(key, key_b, value, val_b);

    // 1) GRN on query -> ada
    grn_reduce_kernel<<<Bn * Cn, 256>>>(query, gx, msum);
    transconv_kernel<<<dim3(Cn / 64, NQ / 32, Bn), 256>>>(query, ada_b, gx, msum,
                                                          ada_gamma, ada_beta, NQ, 1);

    // 2) Q + K + V projections in ONE launch
    gemm_qkv<<<dim3(NQ / BM, 9, Bn), 256, GEMM_SMEM>>>(ada_b, wq_b, bq, qh_b,
                                                       key_b, wk2_b, bk, k,
                                                       val_b, wv_b, bv, v);

    // 3) LN + elu+1 on k (in place) + fused zero of kv/ksum
    ln_elu_kernel<<<Bn * NK, 128>>>(k, lnk_w, lnk_b, kv, ksum);

    // 4) kv_sum/k_sum
    kv_v2<<<dim3(Bn * Hn, 4), 256>>>(k, v, kv, ksum);

    // 5a) q: LN + elu+1 + fold den -> bf16 q'
    ln_elu_q_den<<<Bn * NQ, 128>>>(qh_b, ksum, lnq_w, lnq_b, qp_b);

    // 5b) fold kv into Wo: per-batch effective weight M
    make_M<<<dim3(Cn / 128, Hn, Bn), 256>>>(kv, Wo, M_b);

    // 6) (attention + Wo) as ONE GEMM -> working (bf16, channel-major)
    gemm_bf16_cm<<<dim3(NQ / BM, Cn / BN, Bn), 256, GEMM_SMEM>>>(
        qp_b, M_b, bo, query, nullptr, attn_scalar, nullptr, nullptr, wk_b,
        NQ, Cn, Cn, 0, Cn * Cn);

    // 7) GRN on working (bf16) -> normed
    grn_reduce_h<<<Bn * Cn, 256>>>(wk_b, gx, msum + Bn);
    transconv_h<<<dim3(Cn / 64, NQ / 32, Bn), 256>>>(wk_b, nrm_b, gx, msum + Bn,
                                                     ffn_gamma, ffn_beta);

    // 8) FFN1 (+silu) -> h (bf16 rows)
    gemm_bf16_row<<<dim3(NQ / BM, Fn / BN, Bn), 256, GEMM_SMEM>>>(nrm_b, w1_b, b1, h_b,
                                                                  NQ, Cn, Fn);

    // 9) FFN2 + bf16 working residual + final residual -> out (fp32, channel-major)
    gemm_bf16_cm<<<dim3(NQ / BM, Cn / BN, Bn), 256, GEMM_SMEM>>>(
        h_b, w2_b, b2, query, wk_b, ffn_scalar, final_scalar, out, nullptr,
        NQ, Fn, Cn, 1, 0);
}

// round 17
// speedup vs baseline: 1.4313x; 1.0025x over previous
#include <cuda_runtime.h>
#include <cuda_bf16.h>
#include <math.h>
#include <stdint.h>

// Problem constants
#define Bn 8
#define Cn 384
#define NQ 4096
#define NK 1024
#define Hn 8
#define Dn 48
#define Fn 1536
#define GRN_EPS 1e-6f
#define LN_EPS 1e-5f

// GEMM tiling (bf16): 128x128 CTA tile, 64x32 warp tiles (validated config)
#define BM 128
#define BN 128
#define KSB 32
#define KW 16
#define NSTAGE 3
#define GW (BM * KW)
#define GEMM_SMEM (NSTAGE * 2 * GW * 4)  // 49152 bytes

#define CC (Cn * Cn)
#define FC (Fn * Cn)

// ---------------- scratch (device globals; no allocations) ----------------
__device__ float g_kv[(size_t)Bn * Hn * Dn * Dn];
__device__ float g_ksum[(size_t)Bn * Hn * Dn];
__device__ float g_gx[(size_t)Bn * Cn];
__device__ float g_msum[2 * Bn];

__device__ __nv_bfloat16 b_ada[(size_t)Bn * NQ * Cn];
__device__ __nv_bfloat16 b_key[(size_t)Bn * NK * Cn];
__device__ __nv_bfloat16 b_val[(size_t)Bn * NK * Cn];
__device__ __nv_bfloat16 b_k[(size_t)Bn * NK * Cn];   // k projection (bf16)
__device__ __nv_bfloat16 b_v[(size_t)Bn * NK * Cn];   // v projection (bf16)
__device__ __nv_bfloat16 b_qh[(size_t)Bn * NQ * Cn];
__device__ __nv_bfloat16 b_qp[(size_t)Bn * NQ * Cn];
__device__ __nv_bfloat16 b_wk[(size_t)Bn * Cn * NQ];  // working residual (bf16, channel-major)
__device__ __nv_bfloat16 b_nrm[(size_t)Bn * NQ * Cn];
__device__ __nv_bfloat16 b_h[(size_t)Bn * NQ * Fn];
__device__ __nv_bfloat16 b_wts[4 * CC + 2 * FC];
__device__ __nv_bfloat16 b_M[(size_t)Bn * Cn * Cn];

// ---------------- helpers ----------------
__device__ __forceinline__ void cp_async16(void* smem_dst, const void* gsrc) {
    uint32_t s = (uint32_t)__cvta_generic_to_shared(smem_dst);
    asm volatile("cp.async.cg.shared.global [%0], [%1], 16;" ::"r"(s), "l"(gsrc));
}
__device__ __forceinline__ void cp_commit() { asm volatile("cp.async.commit_group;"); }
__device__ __forceinline__ void cp_wait1() { asm volatile("cp.async.wait_group 1;"); }
__device__ __forceinline__ void cp_wait0() { asm volatile("cp.async.wait_group 0;"); }

__device__ __forceinline__ void mma16(float* c, uint32_t a0, uint32_t a1, uint32_t a2,
                                      uint32_t a3, uint32_t b0, uint32_t b1) {
    asm volatile(
        "mma.sync.aligned.m16n8k16.row.col.f32.bf16.bf16.f32 "
        "{%0,%1,%2,%3},{%4,%5,%6,%7},{%8,%9},{%0,%1,%2,%3};"
        : "+f"(c[0]), "+f"(c[1]), "+f"(c[2]), "+f"(c[3])
        : "r"(a0), "r"(a1), "r"(a2), "r"(a3), "r"(b0), "r"(b1));
}

__device__ __forceinline__ void ldsm4(uint32_t& r0, uint32_t& r1, uint32_t& r2, uint32_t& r3,
                                      uint32_t saddr) {
    asm volatile("ldmatrix.sync.aligned.m8n8.x4.shared.b16 {%0,%1,%2,%3}, [%4];"
                 : "=r"(r0), "=r"(r1), "=r"(r2), "=r"(r3)
                 : "r"(saddr));
}

// ---------------- merged weight convert (+ zero msum) ----------------
__global__ void conv_f2bf_all(const float4* __restrict__ wq, const float4* __restrict__ wk,
                              const float4* __restrict__ wv, const float4* __restrict__ wo,
                              const float4* __restrict__ w1, const float4* __restrict__ w2,
                              __nv_bfloat162* __restrict__ dst, float* __restrict__ msum) {
    if (blockIdx.x == 0 && threadIdx.x < 2 * Bn) msum[threadIdx.x] = 0.f;
    const int C4 = CC / 4, F4 = FC / 4;
    int total = 4 * C4 + 2 * F4;
    for (int i = blockIdx.x * 256 + threadIdx.x; i < total; i += gridDim.x * 256) {
        const float4* src;
        int off;
        if (i < 4 * C4) {
            int seg = i / C4;
            off = i - seg * C4;
            src = (seg == 0) ? wq : (seg == 1) ? wk : (seg == 2) ? wv : wo;
        } else if (i < 4 * C4 + F4) {
            src = w1;
            off = i - 4 * C4;
        } else {
            src = w2;
            off = i - 4 * C4 - F4;
        }
        float4 v = src[off];
        __nv_bfloat162 a, b;
        a.x = __float2bfloat16_rn(v.x); a.y = __float2bfloat16_rn(v.y);
        b.x = __float2bfloat16_rn(v.z); b.y = __float2bfloat16_rn(v.w);
        dst[2 * i] = a;
        dst[2 * i + 1] = b;
    }
}

// ---------------- GRN reduce (fp32 input, query pass) ----------------
__global__ void grn_reduce_kernel(const float* __restrict__ x, float* __restrict__ gx,
                                  float* __restrict__ msum) {
    int bc = blockIdx.x;
    const float4* p = (const float4*)(x + (size_t)bc * NQ);
    int t = threadIdx.x;  // 256; 1024 float4 total
    float4 a = p[t], b = p[t + 256], c = p[t + 512], d = p[t + 768];
    float s = a.x * a.x + a.y * a.y + a.z * a.z + a.w * a.w;
    s += b.x * b.x + b.y * b.y + b.z * b.z + b.w * b.w;
    s += c.x * c.x + c.y * c.y + c.z * c.z + c.w * c.w;
    s += d.x * d.x + d.y * d.y + d.z * d.z + d.w * d.w;
#pragma unroll
    for (int o = 16; o; o >>= 1) s += __shfl_down_sync(0xffffffffu, s, o);
    __shared__ float r[8];
    if ((t & 31) == 0) r[t >> 5] = s;
    __syncthreads();
    if (t == 0) {
        float S = sqrtf(r[0] + r[1] + r[2] + r[3] + r[4] + r[5] + r[6] + r[7]);
        gx[bc] = S;
        atomicAdd(&msum[bc / Cn], S);
    }
}

// ---------------- GRN reduce (bf16 input, working pass) ----------------
__global__ void grn_reduce_h(const __nv_bfloat16* __restrict__ x, float* __restrict__ gx,
                             float* __restrict__ msum) {
    int bc = blockIdx.x;
    const uint4* p = (const uint4*)(x + (size_t)bc * NQ);
    int t = threadIdx.x;  // 256; 2 per thread
    float s = 0.f;
#pragma unroll
    for (int q = 0; q < 2; q++) {
        uint4 u = p[t + q * 256];
        uint32_t w[4] = {u.x, u.y, u.z, u.w};
#pragma unroll
        for (int i = 0; i < 4; i++) {
            __nv_bfloat162 hv = *(__nv_bfloat162*)&w[i];
            float f0 = __bfloat162float(hv.x), f1 = __bfloat162float(hv.y);
            s += f0 * f0 + f1 * f1;
        }
    }
#pragma unroll
    for (int o = 16; o; o >>= 1) s += __shfl_down_sync(0xffffffffu, s, o);
    __shared__ float r[8];
    if ((t & 31) == 0) r[t >> 5] = s;
    __syncthreads();
    if (t == 0) {
        float S = sqrtf(r[0] + r[1] + r[2] + r[3] + r[4] + r[5] + r[6] + r[7]);
        gx[bc] = S;
        atomicAdd(&msum[bc / Cn], S);
    }
}

// ---------------- transpose + GRN + convert to bf16 rows (fp32 input) --------------
__global__ void transconv_kernel(const float* __restrict__ x, __nv_bfloat16* __restrict__ out,
                                 const float* __restrict__ gx, const float* __restrict__ msum,
                                 const float* __restrict__ gamma, const float* __restrict__ beta,
                                 int N, int grn) {
    int b = blockIdx.z;
    int c0 = blockIdx.x * 64;
    int n0 = blockIdx.y * 32;
    __shared__ float t[64][33];
    int tid = threadIdx.x;
    int j = tid & 31, i0 = tid >> 5;
#pragma unroll
    for (int p = 0; p < 8; p++) {
        int i = i0 + p * 8;
        t[i][j] = x[((size_t)b * Cn + c0 + i) * N + n0 + j];
    }
    __syncthreads();
    int cp = tid & 31;
    int nn0 = tid >> 5;
    int c = c0 + 2 * cp;
    float sc0 = 1.f, bt0 = 0.f, sc1 = 1.f, bt1 = 0.f;
    if (grn) {
        float meanc = msum[b] * (1.f / (float)Cn) + GRN_EPS;
        sc0 = 1.f + (1.f + gamma[c]) * gx[b * Cn + c] / meanc;
        bt0 = beta[c];
        sc1 = 1.f + (1.f + gamma[c + 1]) * gx[b * Cn + c + 1] / meanc;
        bt1 = beta[c + 1];
    }
#pragma unroll
    for (int p = 0; p < 4; p++) {
        int nn = nn0 + p * 8;
        float v0 = t[2 * cp][nn] * sc0 + bt0;
        float v1 = t[2 * cp + 1][nn] * sc1 + bt1;
        __nv_bfloat162 hv;
        hv.x = __float2bfloat16_rn(v0);
        hv.y = __float2bfloat16_rn(v1);
        *(__nv_bfloat162*)(out + ((size_t)b * N + n0 + nn) * Cn + c) = hv;
    }
}

// ---------------- transpose + GRN + convert to bf16 rows (bf16 input) --------------
__global__ void transconv_h(const __nv_bfloat16* __restrict__ x,
                            __nv_bfloat16* __restrict__ out,
                            const float* __restrict__ gx, const float* __restrict__ msum,
                            const float* __restrict__ gamma, const float* __restrict__ beta) {
    int b = blockIdx.z;
    int c0 = blockIdx.x * 64;
    int n0 = blockIdx.y * 32;
    __shared__ float t[64][33];
    int tid = threadIdx.x;
    int j = tid & 31, i0 = tid >> 5;
#pragma unroll
    for (int p = 0; p < 8; p++) {
        int i = i0 + p * 8;
        t[i][j] = __bfloat162float(x[((size_t)b * Cn + c0 + i) * NQ + n0 + j]);
    }
    __syncthreads();
    int cp = tid & 31;
    int nn0 = tid >> 5;
    int c = c0 + 2 * cp;
    float meanc = msum[b] * (1.f / (float)Cn) + GRN_EPS;
    float sc0 = 1.f + (1.f + gamma[c]) * gx[b * Cn + c] / meanc;
    float bt0 = beta[c];
    float sc1 = 1.f + (1.f + gamma[c + 1]) * gx[b * Cn + c + 1] / meanc;
    float bt1 = beta[c + 1];
#pragma unroll
    for (int p = 0; p < 4; p++) {
        int nn = nn0 + p * 8;
        float v0 = t[2 * cp][nn] * sc0 + bt0;
        float v1 = t[2 * cp + 1][nn] * sc1 + bt1;
        __nv_bfloat162 hv;
        hv.x = __float2bfloat16_rn(v0);
        hv.y = __float2bfloat16_rn(v1);
        *(__nv_bfloat162*)(out + ((size_t)b * NQ + n0 + nn) * Cn + c) = hv;
    }
}

// merged key+value transpose-convert (no GRN), one launch
__global__ void transconv_kv(const float* __restrict__ xk, __nv_bfloat16* __restrict__ ok,
                             const float* __restrict__ xv, __nv_bfloat16* __restrict__ ov) {
    int z = blockIdx.z;
    const float* x = (z < Bn) ? xk : xv;
    __nv_bfloat16* out = (z < Bn) ? ok : ov;
    int b = (z < Bn) ? z : z - Bn;
    int c0 = blockIdx.x * 64;
    int n0 = blockIdx.y * 32;
    __shared__ float t[64][33];
    int tid = threadIdx.x;
    int j = tid & 31, i0 = tid >> 5;
#pragma unroll
    for (int p = 0; p < 8; p++) {
        int i = i0 + p * 8;
        t[i][j] = x[((size_t)b * Cn + c0 + i) * NK + n0 + j];
    }
    __syncthreads();
    int cp = tid & 31;
    int nn0 = tid >> 5;
    int c = c0 + 2 * cp;
#pragma unroll
    for (int p = 0; p < 4; p++) {
        int nn = nn0 + p * 8;
        __nv_bfloat162 hv;
        hv.x = __float2bfloat16_rn(t[2 * cp][nn]);
        hv.y = __float2bfloat16_rn(t[2 * cp + 1][nn]);
        *(__nv_bfloat162*)(out + ((size_t)b * NK + n0 + nn) * Cn + c) = hv;
    }
}

// ---------------- shared GEMM mainloop (128x128 tile, ldmatrix fragments) --------------
#define GEMM_MAINLOOP(Ab, Wp, K)                                                          \
    const uint32_t a_base = (uint32_t)__cvta_generic_to_shared(As);                       \
    const uint32_t b_base = (uint32_t)__cvta_generic_to_shared(Bs);                       \
    int lr = (lane & 7) + ((lane >> 3) & 1) * 8;                                          \
    int lca = lane >> 4;                                                                  \
    int lrb = (lane & 7) + (lane >> 4) * 8;                                               \
    int lcb = (lane >> 3) & 1;                                                            \
    int nslab = (K) / KSB;                                                                \
    LOAD_BF(0, 0, Ab, Wp, K);                                                             \
    LOAD_BF(1, 1, Ab, Wp, K);                                                             \
    for (int s = 0; s < nslab; s++) {                                                     \
        int stg = s % NSTAGE;                                                             \
        if (s + 1 < nslab) cp_wait1(); else cp_wait0();                                   \
        __syncthreads();                                                                  \
        if (s + 2 < nslab) LOAD_BF(s + 2, (s + 2) % NSTAGE, Ab, Wp, K);                   \
        uint32_t Ast = a_base + stg * GW * 4;                                             \
        uint32_t Bst = b_base + stg * GW * 4;                                             \
        _Pragma("unroll") for (int kb = 0; kb < 2; kb++) {                                \
            uint32_t af[4][4], bfr[4][2];                                                 \
            _Pragma("unroll") for (int mf = 0; mf < 4; mf++) {                            \
                int row = wm + mf * 16 + lr;                                              \
                int ch = 2 * kb + lca;                                                    \
                ldsm4(af[mf][0], af[mf][1], af[mf][2], af[mf][3],                         \
                      Ast + row * 64 + ((ch ^ ((row >> 1) & 3)) << 4));                   \
            }                                                                             \
            _Pragma("unroll") for (int p = 0; p < 2; p++) {                               \
                int row = wn + p * 16 + lrb;                                              \
                int ch = 2 * kb + lcb;                                                    \
                ldsm4(bfr[2 * p][0], bfr[2 * p][1], bfr[2 * p + 1][0], bfr[2 * p + 1][1], \
                      Bst + row * 64 + ((ch ^ ((row >> 1) & 3)) << 4));                   \
            }                                                                             \
            _Pragma("unroll") for (int mf = 0; mf < 4; mf++)                              \
                _Pragma("unroll") for (int nf = 0; nf < 4; nf++)                          \
                    mma16(acc[mf][nf], af[mf][0], af[mf][1], af[mf][2], af[mf][3],        \
                          bfr[nf][0], bfr[nf][1]);                                        \
        }                                                                                 \
    }

#define LOAD_BF(slab, stg, Abp, Wpp, Kk)                                                \
    {                                                                                   \
        int kk0 = (slab)*KSB;                                                           \
        uint32_t* Ad = As + (size_t)(stg)*GW;                                           \
        uint32_t* Bd = Bs + (size_t)(stg)*GW;                                           \
        _Pragma("unroll") for (int p = 0; p < 2; p++) {                                 \
            int c = tid + p * 256;                                                      \
            int r = c >> 2, ch = c & 3;                                                 \
            int sw = ((ch ^ ((r >> 1) & 3)) << 2);                                      \
            cp_async16(Ad + r * KW + sw, (Abp) + (size_t)(m0 + r) * (Kk) + kk0 + ch * 8); \
            cp_async16(Bd + r * KW + sw, (Wpp) + (size_t)(c0 + r) * (Kk) + kk0 + ch * 8); \
        }                                                                               \
        cp_commit();                                                                    \
    }

// ---------------- Q/K/V projections in ONE launch (all bf16 outputs) ----------------
__global__ __launch_bounds__(256) void gemm_qkv(
    const __nv_bfloat16* __restrict__ Aq, const __nv_bfloat16* __restrict__ Wq_,
    const float* __restrict__ bq_, __nv_bfloat16* __restrict__ qh,
    const __nv_bfloat16* __restrict__ Ak, const __nv_bfloat16* __restrict__ Wk_,
    const float* __restrict__ bk_, __nv_bfloat16* __restrict__ kh,
    const __nv_bfloat16* __restrict__ Av, const __nv_bfloat16* __restrict__ Wv_,
    const float* __restrict__ bv_, __nv_bfloat16* __restrict__ vh) {
    extern __shared__ uint32_t smu[];
    uint32_t* As = smu;
    uint32_t* Bs = smu + NSTAGE * GW;
    int b = blockIdx.z;
    int m0 = blockIdx.x * BM;
    int yb = blockIdx.y;
    const __nv_bfloat16 *A, *W;
    const float* bias;
    __nv_bfloat16* Yh;
    int N;
    if (yb < 3) {
        A = Aq; W = Wq_; bias = bq_; Yh = qh; N = NQ;
    } else if (yb < 6) {
        A = Ak; W = Wk_; bias = bk_; Yh = kh; N = NK; yb -= 3;
    } else {
        A = Av; W = Wv_; bias = bv_; Yh = vh; N = NK; yb -= 6;
    }
    if (m0 >= N) return;
    int c0 = yb * BN;
    int tid = threadIdx.x;
    int warp = tid >> 5, lane = tid & 31;
    int g = lane >> 2, lq = lane & 3;
    int wm = (warp >> 2) * 64;
    int wn = (warp & 3) * 32;
    float acc[4][4][4] = {};
    const __nv_bfloat16* Ab = A + (size_t)b * N * Cn;
    const __nv_bfloat16* Wp = W;
    const int K = Cn;

    GEMM_MAINLOOP(Ab, Wp, K)

#pragma unroll
    for (int mf = 0; mf < 4; mf++) {
#pragma unroll
        for (int nf = 0; nf < 4; nf++) {
            int co = c0 + wn + nf * 8 + lq * 2;
            float b0v = bias[co], b1v = bias[co + 1];
#pragma unroll
            for (int hr = 0; hr < 2; hr++) {
                int m = m0 + wm + mf * 16 + g + hr * 8;
                float v0 = acc[mf][nf][hr * 2 + 0] + b0v;
                float v1 = acc[mf][nf][hr * 2 + 1] + b1v;
                __nv_bfloat162 hv;
                hv.x = __float2bfloat16_rn(v0);
                hv.y = __float2bfloat16_rn(v1);
                *(__nv_bfloat162*)(Yh + ((size_t)b * N + m) * Cn + co) = hv;
            }
        }
    }
}

// ---------------- bf16 GEMM, row-major output (FFN1: silu + bf16) ----------------
__global__ __launch_bounds__(256) void gemm_bf16_row(
    const __nv_bfloat16* __restrict__ A, const __nv_bfloat16* __restrict__ W,
    const float* __restrict__ bias, __nv_bfloat16* __restrict__ Yh,
    int N, int K, int Cout) {
    extern __shared__ uint32_t smu[];
    uint32_t* As = smu;
    uint32_t* Bs = smu + NSTAGE * GW;
    int b = blockIdx.z;
    int m0 = blockIdx.x * BM;
    int c0 = blockIdx.y * BN;
    int tid = threadIdx.x;
    int warp = tid >> 5, lane = tid & 31;
    int g = lane >> 2, lq = lane & 3;
    int wm = (warp >> 2) * 64;
    int wn = (warp & 3) * 32;
    float acc[4][4][4] = {};
    const __nv_bfloat16* Ab = A + (size_t)b * N * K;
    const __nv_bfloat16* Wp = W;

    GEMM_MAINLOOP(Ab, Wp, K)

#pragma unroll
    for (int mf = 0; mf < 4; mf++) {
#pragma unroll
        for (int nf = 0; nf < 4; nf++) {
            int co = c0 + wn + nf * 8 + lq * 2;
            float b0v = bias[co], b1v = bias[co + 1];
#pragma unroll
            for (int hr = 0; hr < 2; hr++) {
                int m = m0 + wm + mf * 16 + g + hr * 8;
                float v0 = acc[mf][nf][hr * 2 + 0] + b0v;
                float v1 = acc[mf][nf][hr * 2 + 1] + b1v;
                v0 = v0 / (1.f + expf(-v0));
                v1 = v1 / (1.f + expf(-v1));
                __nv_bfloat162 hv;
                hv.x = __float2bfloat16_rn(v0);
                hv.y = __float2bfloat16_rn(v1);
                *(__nv_bfloat162*)(Yh + ((size_t)b * N + m) * Cout + co) = hv;
            }
        }
    }
}

// ---------------- bf16 GEMM, channel-major fused output (batch-strided W) ----------
// mode 0: outh[b,co,m] = bf16(resid1 + val*s1)                 (attn -> working bf16)
// mode 1: outf[b,co,m] = resid1 + (float(resid2h) + val*s1)*s2 (FFN2 -> final fp32)
__global__ __launch_bounds__(256) void gemm_bf16_cm(
    const __nv_bfloat16* __restrict__ A, const __nv_bfloat16* __restrict__ W,
    const float* __restrict__ bias,
    const float* __restrict__ resid1, const __nv_bfloat16* __restrict__ resid2h,
    const float* __restrict__ scal1, const float* __restrict__ scal2,
    float* __restrict__ outf, __nv_bfloat16* __restrict__ outh,
    int N, int K, int Cout, int mode, int wstride) {
    extern __shared__ uint32_t smu[];
    uint32_t* As = smu;
    uint32_t* Bs = smu + NSTAGE * GW;
    int b = blockIdx.z;
    int m0 = blockIdx.x * BM;
    int c0 = blockIdx.y * BN;
    int tid = threadIdx.x;
    int warp = tid >> 5, lane = tid & 31;
    int g = lane >> 2, lq = lane & 3;
    int wm = (warp >> 2) * 64;
    int wn = (warp & 3) * 32;
    float acc[4][4][4] = {};
    const __nv_bfloat16* Ab = A + (size_t)b * N * K;
    const __nv_bfloat16* Wp = W + (size_t)b * wstride;

    GEMM_MAINLOOP(Ab, Wp, K)

#pragma unroll
    for (int nf = 0; nf < 4; nf++) {
#pragma unroll
        for (int cj = 0; cj < 2; cj++) {
            int co = c0 + wn + nf * 8 + lq * 2 + cj;
            float bv = bias[co];
            float s1 = scal1[co];
            float s2 = (mode == 1) ? scal2[co] : 0.f;
#pragma unroll
            for (int mf = 0; mf < 4; mf++) {
#pragma unroll
                for (int hr = 0; hr < 2; hr++) {
                    int m = m0 + wm + mf * 16 + g + hr * 8;
                    size_t idx = ((size_t)b * Cout + co) * (size_t)N + m;
                    float val = acc[mf][nf][hr * 2 + cj] + bv;
                    if (mode == 0) {
                        outh[idx] = __float2bfloat16_rn(resid1[idx] + val * s1);
                    } else {
                        outf[idx] = resid1[idx] +
                                    (__bfloat162float(resid2h[idx]) + val * s1) * s2;
                    }
                }
            }
        }
    }
}

// ---------------- LayerNorm + elu+1 on k (bf16 in place) + zero kv/ksum ----------------
__global__ void ln_elu_kernel(__nv_bfloat16* __restrict__ x, const float* __restrict__ w,
                              const float* __restrict__ bvec, float* __restrict__ kv,
                              float* __restrict__ ksum) {
    int r = blockIdx.x;
    int t = threadIdx.x;  // 128
    int gidx = r * 128 + t;
    if (gidx < Bn * Hn * Dn * Dn) kv[gidx] = 0.f;
    if (gidx < Bn * Hn * Dn) ksum[gidx] = 0.f;
    __nv_bfloat16* p = x + (size_t)r * Cn;
    float v0 = __bfloat162float(p[t]);
    float v1 = __bfloat162float(p[t + 128]);
    float v2 = __bfloat162float(p[t + 256]);
    float s = v0 + v1 + v2;
    float s2 = v0 * v0 + v1 * v1 + v2 * v2;
#pragma unroll
    for (int o = 16; o; o >>= 1) {
        s += __shfl_down_sync(0xffffffffu, s, o);
        s2 += __shfl_down_sync(0xffffffffu, s2, o);
    }
    __shared__ float r1[4], r2[4];
    if ((t & 31) == 0) { r1[t >> 5] = s; r2[t >> 5] = s2; }
    __syncthreads();
    float S = r1[0] + r1[1] + r1[2] + r1[3];
    float S2 = r2[0] + r2[1] + r2[2] + r2[3];
    float mu = S * (1.f / (float)Cn);
    float var = S2 * (1.f / (float)Cn) - mu * mu;
    float inv = rsqrtf(var + LN_EPS);
    float y;
    y = (v0 - mu) * inv * w[t] + bvec[t];
    p[t] = __float2bfloat16_rn((y > 0.f) ? y + 1.f : expf(y));
    y = (v1 - mu) * inv * w[t + 128] + bvec[t + 128];
    p[t + 128] = __float2bfloat16_rn((y > 0.f) ? y + 1.f : expf(y));
    y = (v2 - mu) * inv * w[t + 256] + bvec[t + 256];
    p[t + 256] = __float2bfloat16_rn((y > 0.f) ? y + 1.f : expf(y));
}

// ---------------- q: LN + elu+1 + den fold -> bf16 q' (warp-shuffle) ----------------
__global__ void ln_elu_q_den(const __nv_bfloat16* __restrict__ x,
                             const float* __restrict__ ksum,
                             const float* __restrict__ w, const float* __restrict__ bvec,
                             __nv_bfloat16* __restrict__ qp) {
    int r = blockIdx.x;
    int b = r / NQ;
    const __nv_bfloat16* p = x + (size_t)r * Cn;
    int t = threadIdx.x;  // 128
    float v0 = __bfloat162float(p[t]);
    float v1 = __bfloat162float(p[t + 128]);
    float v2 = __bfloat162float(p[t + 256]);
    float s = v0 + v1 + v2;
    float s2 = v0 * v0 + v1 * v1 + v2 * v2;
#pragma unroll
    for (int o = 16; o; o >>= 1) {
        s += __shfl_down_sync(0xffffffffu, s, o);
        s2 += __shfl_down_sync(0xffffffffu, s2, o);
    }
    __shared__ float r1[4], r2[4];
    __shared__ float prod[Cn];
    __shared__ float den[8];
    if ((t & 31) == 0) { r1[t >> 5] = s; r2[t >> 5] = s2; }
    __syncthreads();
    float S = r1[0] + r1[1] + r1[2] + r1[3];
    float S2 = r2[0] + r2[1] + r2[2] + r2[3];
    float mu = S * (1.f / (float)Cn);
    float var = S2 * (1.f / (float)Cn) - mu * mu;
    float inv = rsqrtf(var + LN_EPS);
    float y0 = (v0 - mu) * inv * w[t] + bvec[t];
    y0 = (y0 > 0.f) ? y0 + 1.f : expf(y0);
    float y1 = (v1 - mu) * inv * w[t + 128] + bvec[t + 128];
    y1 = (y1 > 0.f) ? y1 + 1.f : expf(y1);
    float y2 = (v2 - mu) * inv * w[t + 256] + bvec[t + 256];
    y2 = (y2 > 0.f) ? y2 + 1.f : expf(y2);
    const float* ks = ksum + (size_t)b * Cn;
    prod[t] = y0 * ks[t];
    prod[t + 128] = y1 * ks[t + 128];
    prod[t + 256] = y2 * ks[t + 256];
    __syncthreads();
    int h = t >> 4, i = t & 15;
    float pd = prod[h * Dn + i * 3] + prod[h * Dn + i * 3 + 1] + prod[h * Dn + i * 3 + 2];
#pragma unroll
    for (int o = 8; o; o >>= 1) pd += __shfl_down_sync(0xffffffffu, pd, o, 16);
    if (i == 0) den[h] = pd + 1e-8f;
    __syncthreads();
    __nv_bfloat16* o = qp + (size_t)r * Cn;
    o[t] = __float2bfloat16_rn(y0 / den[t / Dn]);
    o[t + 128] = __float2bfloat16_rn(y1 / den[(t + 128) / Dn]);
    o[t + 256] = __float2bfloat16_rn(y2 / den[(t + 256) / Dn]);
}

// ---------------- kv_sum + k_sum (bf16 inputs, fp32 accumulate) ----------------
__global__ void kv_v2(const __nv_bfloat16* __restrict__ k, const __nv_bfloat16* __restrict__ v,
                      float* __restrict__ kv, float* __restrict__ ksum) {
    int bh = blockIdx.x;
    int chunk = blockIdx.y;
    int b = bh >> 3, h = bh & 7;
    __shared__ float ks[32][49];
    __shared__ float vs[32][49];
    int tid = threadIdx.x;  // 256
    int di = tid >> 4, ei = tid & 15;
    int d0 = di * 3, e0 = ei * 3;
    float acc[3][3] = {};
    float ksa[3] = {};
    int nbeg = chunk * (NK / 4);
    for (int n0 = nbeg; n0 < nbeg + NK / 4; n0 += 32) {
        for (int i = tid; i < 32 * Dn; i += 256) {
            int nn = i / Dn, dd = i % Dn;
            size_t base = ((size_t)b * NK + n0 + nn) * Cn + h * Dn + dd;
            ks[nn][dd] = __bfloat162float(k[base]);
            vs[nn][dd] = __bfloat162float(v[base]);
        }
        __syncthreads();
#pragma unroll 4
        for (int nn = 0; nn < 32; nn++) {
            float kd0 = ks[nn][d0], kd1 = ks[nn][d0 + 1], kd2 = ks[nn][d0 + 2];
            float ve0 = vs[nn][e0], ve1 = vs[nn][e0 + 1], ve2 = vs[nn][e0 + 2];
            acc[0][0] += kd0 * ve0; acc[0][1] += kd0 * ve1; acc[0][2] += kd0 * ve2;
            acc[1][0] += kd1 * ve0; acc[1][1] += kd1 * ve1; acc[1][2] += kd1 * ve2;
            acc[2][0] += kd2 * ve0; acc[2][1] += kd2 * ve1; acc[2][2] += kd2 * ve2;
            if (ei == 0) { ksa[0] += kd0; ksa[1] += kd1; ksa[2] += kd2; }
        }
        __syncthreads();
    }
    float* kvb = kv + (size_t)bh * Dn * Dn;
#pragma unroll
    for (int i = 0; i < 3; i++)
#pragma unroll
        for (int j = 0; j < 3; j++)
            atomicAdd(&kvb[(d0 + i) * Dn + e0 + j], acc[i][j]);
    if (ei == 0)
#pragma unroll
        for (int i = 0; i < 3; i++) atomicAdd(&ksum[bh * Dn + d0 + i], ksa[i]);
}

// ---------------- make_M ----------------
__global__ void make_M(const float* __restrict__ kv, const float* __restrict__ Wo,
                       __nv_bfloat16* __restrict__ Wt) {
    int cb = blockIdx.x;
    int h = blockIdx.y;
    int b = blockIdx.z;
    __shared__ float kvs[Dn][49];
    __shared__ float wos[Dn][132];
    int tid = threadIdx.x;  // 256
    for (int i = tid; i < Dn * Dn; i += 256)
        kvs[i / Dn][i % Dn] = kv[((size_t)b * Hn + h) * Dn * Dn + i];
    for (int i = tid; i < 128 * Dn; i += 256) {
        int co = i / Dn, e = i % Dn;
        wos[e][co] = Wo[(size_t)(cb * 128 + co) * Cn + h * Dn + e];
    }
    __syncthreads();
    int cog = tid & 15, dg = tid >> 4;
    int co0 = cog * 8, d0 = dg * 3;
    float acc[8][3] = {};
#pragma unroll 4
    for (int e = 0; e < Dn; e++) {
        float kd0 = kvs[d0][e], kd1 = kvs[d0 + 1][e], kd2 = kvs[d0 + 2][e];
#pragma unroll
        for (int i = 0; i < 8; i++) {
            float wv = wos[e][co0 + i];
            acc[i][0] += wv * kd0;
            acc[i][1] += wv * kd1;
            acc[i][2] += wv * kd2;
        }
    }
#pragma unroll
    for (int i = 0; i < 8; i++)
#pragma unroll
        for (int j = 0; j < 3; j++)
            Wt[((size_t)b * Cn + cb * 128 + co0 + i) * Cn + h * Dn + d0 + j] =
                __float2bfloat16_rn(acc[i][j]);
}

// ---------------- host launch ----------------
extern "C" void kernel_launch(void* const* d_in, const int* in_sizes, int n_in,
                              void* d_out, int out_size) {
    const float* query = (const float*)d_in[0];
    const float* key = (const float*)d_in[1];
    const float* value = (const float*)d_in[2];
    const float* ada_gamma = (const float*)d_in[3];
    const float* ada_beta = (const float*)d_in[4];
    const float* Wq = (const float*)d_in[5];
    const float* bq = (const float*)d_in[6];
    const float* Wk = (const float*)d_in[7];
    const float* bk = (const float*)d_in[8];
    const float* Wv = (const float*)d_in[9];
    const float* bv = (const float*)d_in[10];
    const float* Wo = (const float*)d_in[11];
    const float* bo = (const float*)d_in[12];
    const float* lnq_w = (const float*)d_in[13];
    const float* lnq_b = (const float*)d_in[14];
    const float* lnk_w = (const float*)d_in[15];
    const float* lnk_b = (const float*)d_in[16];
    const float* attn_scalar = (const float*)d_in[17];
    const float* ffn_gamma = (const float*)d_in[18];
    const float* ffn_beta = (const float*)d_in[19];
    const float* W1 = (const float*)d_in[20];
    const float* b1 = (const float*)d_in[21];
    const float* W2 = (const float*)d_in[22];
    const float* b2 = (const float*)d_in[23];
    const float* ffn_scalar = (const float*)d_in[24];
    const float* final_scalar = (const float*)d_in[25];
    float* out = (float*)d_out;

    float *kv, *ksum, *gx, *msum;
    __nv_bfloat16 *ada_b, *key_b, *val_b, *k_b, *v_b, *qh_b, *qp_b, *wk_b, *nrm_b, *h_b,
        *wts, *M_b;
    cudaGetSymbolAddress((void**)&kv, g_kv);
    cudaGetSymbolAddress((void**)&ksum, g_ksum);
    cudaGetSymbolAddress((void**)&gx, g_gx);
    cudaGetSymbolAddress((void**)&msum, g_msum);
    cudaGetSymbolAddress((void**)&ada_b, b_ada);
    cudaGetSymbolAddress((void**)&key_b, b_key);
    cudaGetSymbolAddress((void**)&val_b, b_val);
    cudaGetSymbolAddress((void**)&k_b, b_k);
    cudaGetSymbolAddress((void**)&v_b, b_v);
    cudaGetSymbolAddress((void**)&qh_b, b_qh);
    cudaGetSymbolAddress((void**)&qp_b, b_qp);
    cudaGetSymbolAddress((void**)&wk_b, b_wk);
    cudaGetSymbolAddress((void**)&nrm_b, b_nrm);
    cudaGetSymbolAddress((void**)&h_b, b_h);
    cudaGetSymbolAddress((void**)&wts, b_wts);
    cudaGetSymbolAddress((void**)&M_b, b_M);

    __nv_bfloat16* wq_b = wts;
    __nv_bfloat16* wk2_b = wts + CC;
    __nv_bfloat16* wv_b = wts + 2 * CC;
    __nv_bfloat16* w1_b = wts + 4 * CC;
    __nv_bfloat16* w2_b = wts + 4 * CC + FC;

    cudaFuncSetAttribute(gemm_qkv, cudaFuncAttributeMaxDynamicSharedMemorySize, GEMM_SMEM);
    cudaFuncSetAttribute(gemm_bf16_row, cudaFuncAttributeMaxDynamicSharedMemorySize, GEMM_SMEM);
    cudaFuncSetAttribute(gemm_bf16_cm, cudaFuncAttributeMaxDynamicSharedMemorySize, GEMM_SMEM);

    // 0) weight conversions + zero msum (one launch)
    conv_f2bf_all<<<1728, 256>>>((const float4*)Wq, (const float4*)Wk, (const float4*)Wv,
                                 (const float4*)Wo, (const float4*)W1, (const float4*)W2,
                                 (__nv_bfloat162*)wts, msum);

    // 0b) key+value transpose-convert, one launch
    transconv_kv<<<dim3(Cn / 64, NK / 32, 2 * Bn), 256>>>(key, key_b, value, val_b);

    // 1) GRN on query -> ada
    grn_reduce_kernel<<<Bn * Cn, 256>>>(query, gx, msum);
    transconv_kernel<<<dim3(Cn / 64, NQ / 32, Bn), 256>>>(query, ada_b, gx, msum,
                                                          ada_gamma, ada_beta, NQ, 1);

    // 2) Q + K + V projections in ONE launch (all bf16 out)
    gemm_qkv<<<dim3(NQ / BM, 9, Bn), 256, GEMM_SMEM>>>(ada_b, wq_b, bq, qh_b,
                                                       key_b, wk2_b, bk, k_b,
                                                       val_b, wv_b, bv, v_b);

    // 3) LN + elu+1 on k (bf16 in place) + fused zero of kv/ksum
    ln_elu_kernel<<<Bn * NK, 128>>>(k_b, lnk_w, lnk_b, kv, ksum);

    // 4) kv_sum/k_sum (bf16 inputs)
    kv_v2<<<dim3(Bn * Hn, 4), 256>>>(k_b, v_b, kv, ksum);

    // 5a) q: LN + elu+1 + fold den -> bf16 q'
    ln_elu_q_den<<<Bn * NQ, 128>>>(qh_b, ksum, lnq_w, lnq_b, qp_b);

    // 5b) fold kv into Wo: per-batch effective weight M
    make_M<<<dim3(Cn / 128, Hn, Bn), 256>>>(kv, Wo, M_b);

    // 6) (attention + Wo) as ONE GEMM -> working (bf16, channel-major)
    gemm_bf16_cm<<<dim3(NQ / BM, Cn / BN, Bn), 256, GEMM_SMEM>>>(
        qp_b, M_b, bo, query, nullptr, attn_scalar, nullptr, nullptr, wk_b,
        NQ, Cn, Cn, 0, Cn * Cn);

    // 7) GRN on working (bf16) -> normed
    grn_reduce_h<<<Bn * Cn, 256>>>(wk_b, gx, msum + Bn);
    transconv_h<<<dim3(Cn / 64, NQ / 32, Bn), 256>>>(wk_b, nrm_b, gx, msum + Bn,
                                                     ffn_gamma, ffn_beta);

    // 8) FFN1 (+silu) -> h (bf16 rows)
    gemm_bf16_row<<<dim3(NQ / BM, Fn / BN, Bn), 256, GEMM_SMEM>>>(nrm_b, w1_b, b1, h_b,
                                                                  NQ, Cn, Fn);

    // 9) FFN2 + bf16 working residual + final residual -> out (fp32, channel-major)
    gemm_bf16_cm<<<dim3(NQ / BM, Cn / BN, Bn), 256, GEMM_SMEM>>>(
        h_b, w2_b, b2, query, wk_b, ffn_scalar, final_scalar, out, nullptr,
        NQ, Fn, Cn, 1, 0);
}